// round 1
// baseline (speedup 1.0000x reference)
#include <cuda_runtime.h>
#include <math.h>

#define Tc 4096
#define Dc 512
#define Sc 1024
#define Bc 4
#define Hc 8
#define HEADc 64
#define Ec 8
#define DHc 2048
#define Lc 2

// ---------------- scratch (device globals; no runtime allocation) ----------
__device__ float g_h[Tc * Dc];
__device__ float g_q[Tc * Dc];
__device__ float g_k[Tc * Dc];
__device__ float g_v[Tc * Dc];
__device__ float g_s[(size_t)Bc * Hc * Sc * Sc];   // 134 MB attention scores
__device__ float g_ao[Tc * Dc];
__device__ float g_hmid[(size_t)2 * Tc * DHc];     // grouped expert mid activations
__device__ float g_ybuf[(size_t)Tc * 2 * Dc];      // per (token,slot) expert outputs
__device__ float g_gate[Tc * 2];
__device__ int   g_topi[Tc * 2];
__device__ int   g_cnt[Ec];
__device__ int   g_cur[Ec];
__device__ int   g_off[Ec];
__device__ int   g_tok[2 * Tc];                    // entry id = token*2 + slot

// ---------------- simple copy ----------------------------------------------
__global__ void copy_k(const float* __restrict__ a, float* __restrict__ o) {
    long i = (long)blockIdx.x * 256 + threadIdx.x;
    o[i] = a[i];
}

// ---------------- layernorm (one row per block, 128 threads) ---------------
__global__ void ln_k(const float* __restrict__ x, const float* __restrict__ w,
                     const float* __restrict__ b, float* __restrict__ out) {
    int row = blockIdx.x;
    const float* xr = x + (long)row * Dc;
    int tid = threadIdx.x;
    float v[4];
    float s = 0.f, s2 = 0.f;
#pragma unroll
    for (int i = 0; i < 4; i++) {
        v[i] = xr[tid + i * 128];
        s += v[i]; s2 += v[i] * v[i];
    }
    __shared__ float sh[4], sh2[4];
#pragma unroll
    for (int o = 16; o > 0; o >>= 1) {
        s  += __shfl_xor_sync(0xffffffffu, s, o);
        s2 += __shfl_xor_sync(0xffffffffu, s2, o);
    }
    if ((tid & 31) == 0) { sh[tid >> 5] = s; sh2[tid >> 5] = s2; }
    __syncthreads();
    if (tid == 0) {
        float a = 0.f, a2 = 0.f;
#pragma unroll
        for (int i = 0; i < 4; i++) { a += sh[i]; a2 += sh2[i]; }
        sh[0] = a; sh2[0] = a2;
    }
    __syncthreads();
    float mu  = sh[0] * (1.f / Dc);
    float var = sh2[0] * (1.f / Dc) - mu * mu;
    float inv = rsqrtf(var + 1e-6f);
#pragma unroll
    for (int i = 0; i < 4; i++) {
        int d = tid + i * 128;
        out[(long)row * Dc + d] = (v[i] - mu) * inv * w[d] + b[d];
    }
}

// ---------------- generic batched GEMM, 64x64x16 tile, 4x4/thread ----------
// C[z] = alpha * A[z] @ op(B[z]) (+bias) (+C)   with z = zb*zh + zhh
// op(B) = B            (TB=false, B is [K x N], ldb)
// op(B) = B^T          (TB=true,  B is [N x K], ldb)
template <bool TB>
__global__ void __launch_bounds__(256) gemm_k(
    int M, int N, int Kd,
    const float* __restrict__ A, int lda, long sa1, long sa2,
    const float* __restrict__ B, int ldb, long sb1, long sb2,
    float* __restrict__ C, int ldc, long sc1, long sc2, int zh,
    const float* __restrict__ bias, float alpha, int addC)
{
    __shared__ float As[16][68];
    __shared__ float Bs[16][68];
    int z = blockIdx.z;
    int zb = z / zh, zhh = z - zb * zh;
    A += zb * sa1 + zhh * sa2;
    B += zb * sb1 + zhh * sb2;
    C += zb * sc1 + zhh * sc2;

    int tid = threadIdx.x;
    int tx = tid & 15, ty = tid >> 4;
    int m0 = blockIdx.y * 64, n0 = blockIdx.x * 64;

    int ra = tid >> 2,  ca = (tid & 3) * 4;   // A: row 0..63, k 0..15
    int rb = tid >> 4,  cb = (tid & 15) * 4;  // B(nn): k 0..15, col 0..63

    float acc[4][4] = {};
    for (int k0 = 0; k0 < Kd; k0 += 16) {
        float4 av = *(const float4*)&A[(long)(m0 + ra) * lda + k0 + ca];
        As[ca + 0][ra] = av.x; As[ca + 1][ra] = av.y;
        As[ca + 2][ra] = av.z; As[ca + 3][ra] = av.w;
        if (TB) {
            float4 bv = *(const float4*)&B[(long)(n0 + ra) * ldb + k0 + ca];
            Bs[ca + 0][ra] = bv.x; Bs[ca + 1][ra] = bv.y;
            Bs[ca + 2][ra] = bv.z; Bs[ca + 3][ra] = bv.w;
        } else {
            float4 bv = *(const float4*)&B[(long)(k0 + rb) * ldb + n0 + cb];
            Bs[rb][cb + 0] = bv.x; Bs[rb][cb + 1] = bv.y;
            Bs[rb][cb + 2] = bv.z; Bs[rb][cb + 3] = bv.w;
        }
        __syncthreads();
#pragma unroll
        for (int k = 0; k < 16; k++) {
            float4 a = *(const float4*)&As[k][ty * 4];
            float4 b = *(const float4*)&Bs[k][tx * 4];
            acc[0][0] += a.x * b.x; acc[0][1] += a.x * b.y; acc[0][2] += a.x * b.z; acc[0][3] += a.x * b.w;
            acc[1][0] += a.y * b.x; acc[1][1] += a.y * b.y; acc[1][2] += a.y * b.z; acc[1][3] += a.y * b.w;
            acc[2][0] += a.z * b.x; acc[2][1] += a.z * b.y; acc[2][2] += a.z * b.z; acc[2][3] += a.z * b.w;
            acc[3][0] += a.w * b.x; acc[3][1] += a.w * b.y; acc[3][2] += a.w * b.z; acc[3][3] += a.w * b.w;
        }
        __syncthreads();
    }
#pragma unroll
    for (int i = 0; i < 4; i++) {
        int row = m0 + ty * 4 + i;
#pragma unroll
        for (int j = 0; j < 4; j++) {
            int col = n0 + tx * 4 + j;
            float c = acc[i][j] * alpha;
            if (bias) c += bias[col];
            long idx = (long)row * ldc + col;
            if (addC) c += C[idx];
            C[idx] = c;
        }
    }
}

// ---------------- row softmax over Sc=1024, 256 threads --------------------
__global__ void softmax_k(float* __restrict__ s) {
    long row = blockIdx.x;
    float* r = s + row * Sc;
    int tid = threadIdx.x;
    float v[4];
    float m = -3.4e38f;
#pragma unroll
    for (int i = 0; i < 4; i++) { v[i] = r[tid + i * 256]; m = fmaxf(m, v[i]); }
    __shared__ float sh[8], sh2[8];
#pragma unroll
    for (int o = 16; o > 0; o >>= 1) m = fmaxf(m, __shfl_xor_sync(0xffffffffu, m, o));
    if ((tid & 31) == 0) sh[tid >> 5] = m;
    __syncthreads();
    if (tid == 0) {
        float t = sh[0];
#pragma unroll
        for (int i = 1; i < 8; i++) t = fmaxf(t, sh[i]);
        sh[0] = t;
    }
    __syncthreads();
    m = sh[0];
    float sum = 0.f;
#pragma unroll
    for (int i = 0; i < 4; i++) { v[i] = expf(v[i] - m); sum += v[i]; }
#pragma unroll
    for (int o = 16; o > 0; o >>= 1) sum += __shfl_xor_sync(0xffffffffu, sum, o);
    if ((tid & 31) == 0) sh2[tid >> 5] = sum;
    __syncthreads();
    if (tid == 0) {
        float t = 0.f;
#pragma unroll
        for (int i = 0; i < 8; i++) t += sh2[i];
        sh2[0] = t;
    }
    __syncthreads();
    float inv = 1.f / sh2[0];
#pragma unroll
    for (int i = 0; i < 4; i++) r[tid + i * 256] = v[i] * inv;
}

// ---------------- gate: logits, top-2, softmax, count ----------------------
__global__ void zero_k() { if (threadIdx.x < Ec) g_cnt[threadIdx.x] = 0; }

__global__ void gate_k(const float* __restrict__ h, const float* __restrict__ gw) {
    int t = blockIdx.x * 4 + (threadIdx.x >> 5);
    int lid = threadIdx.x & 31;
    const float* hr = h + (long)t * Dc;
    float acc[Ec] = {};
    for (int d = lid; d < Dc; d += 32) {
        float hv = hr[d];
#pragma unroll
        for (int e = 0; e < Ec; e++) acc[e] += hv * gw[d * Ec + e];
    }
#pragma unroll
    for (int e = 0; e < Ec; e++)
#pragma unroll
        for (int o = 16; o > 0; o >>= 1)
            acc[e] += __shfl_xor_sync(0xffffffffu, acc[e], o);
    if (lid == 0) {
        int i0 = 0; float v0 = acc[0];
#pragma unroll
        for (int e = 1; e < Ec; e++) if (acc[e] > v0) { v0 = acc[e]; i0 = e; }
        int i1 = -1; float v1 = -3.4e38f;
#pragma unroll
        for (int e = 0; e < Ec; e++) if (e != i0 && acc[e] > v1) { v1 = acc[e]; i1 = e; }
        float g1 = 1.f / (1.f + expf(v0 - v1));
        float g0 = 1.f - g1;
        g_topi[t * 2] = i0; g_topi[t * 2 + 1] = i1;
        g_gate[t * 2] = g0; g_gate[t * 2 + 1] = g1;
        atomicAdd(&g_cnt[i0], 1);
        atomicAdd(&g_cnt[i1], 1);
    }
}

__global__ void offsets_k() {
    if (threadIdx.x == 0) {
        int o = 0;
        for (int e = 0; e < Ec; e++) { g_off[e] = o; g_cur[e] = o; o += g_cnt[e]; }
    }
}

__global__ void scatter_k() {
    int i = blockIdx.x * 256 + threadIdx.x;
    if (i >= 2 * Tc) return;
    int e = g_topi[i];
    int pos = atomicAdd(&g_cur[e], 1);
    g_tok[pos] = i;
}

// ---------------- grouped MoE GEMM 1: hmid = gelu(h[tok] @ W1[e] + b1[e]) --
__global__ void __launch_bounds__(256) moe_g1(
    const float* __restrict__ Hm, const float* __restrict__ W1,
    const float* __restrict__ B1)
{
    int e = blockIdx.z;
    int cnt = g_cnt[e];
    int m0 = blockIdx.y * 64;
    if (m0 >= cnt) return;
    int off = g_off[e];
    __shared__ float As[16][68];
    __shared__ float Bs[16][68];
    __shared__ int stok[64];
    int tid = threadIdx.x;
    if (tid < 64) {
        int i = m0 + tid;
        stok[tid] = (i < cnt) ? (g_tok[off + i] >> 1) : -1;
    }
    __syncthreads();
    const float* W = W1 + (long)e * Dc * DHc;
    int tx = tid & 15, ty = tid >> 4;
    int n0 = blockIdx.x * 64;
    int ra = tid >> 2, ca = (tid & 3) * 4;
    int rb = tid >> 4, cb = (tid & 15) * 4;
    float acc[4][4] = {};
    for (int k0 = 0; k0 < Dc; k0 += 16) {
        int tok = stok[ra];
        float4 av = (tok >= 0) ? *(const float4*)&Hm[(long)tok * Dc + k0 + ca]
                               : make_float4(0, 0, 0, 0);
        As[ca + 0][ra] = av.x; As[ca + 1][ra] = av.y;
        As[ca + 2][ra] = av.z; As[ca + 3][ra] = av.w;
        float4 bv = *(const float4*)&W[(long)(k0 + rb) * DHc + n0 + cb];
        Bs[rb][cb + 0] = bv.x; Bs[rb][cb + 1] = bv.y;
        Bs[rb][cb + 2] = bv.z; Bs[rb][cb + 3] = bv.w;
        __syncthreads();
#pragma unroll
        for (int k = 0; k < 16; k++) {
            float4 a = *(const float4*)&As[k][ty * 4];
            float4 b = *(const float4*)&Bs[k][tx * 4];
            acc[0][0] += a.x * b.x; acc[0][1] += a.x * b.y; acc[0][2] += a.x * b.z; acc[0][3] += a.x * b.w;
            acc[1][0] += a.y * b.x; acc[1][1] += a.y * b.y; acc[1][2] += a.y * b.z; acc[1][3] += a.y * b.w;
            acc[2][0] += a.z * b.x; acc[2][1] += a.z * b.y; acc[2][2] += a.z * b.z; acc[2][3] += a.z * b.w;
            acc[3][0] += a.w * b.x; acc[3][1] += a.w * b.y; acc[3][2] += a.w * b.z; acc[3][3] += a.w * b.w;
        }
        __syncthreads();
    }
    const float* be = B1 + e * DHc;
#pragma unroll
    for (int i = 0; i < 4; i++) {
        int rloc = m0 + ty * 4 + i;
        if (rloc >= cnt) break;
        float* dst = &g_hmid[(long)(off + rloc) * DHc + n0 + tx * 4];
#pragma unroll
        for (int j = 0; j < 4; j++) {
            float c = acc[i][j] + be[n0 + tx * 4 + j];
            dst[j] = 0.5f * c * (1.f + erff(c * 0.70710678118654752f));
        }
    }
}

// ---------------- grouped MoE GEMM 2: ybuf[entry] = hmid @ W2[e] + b2[e] ---
__global__ void __launch_bounds__(256) moe_g2(
    const float* __restrict__ W2, const float* __restrict__ B2)
{
    int e = blockIdx.z;
    int cnt = g_cnt[e];
    int m0 = blockIdx.y * 64;
    if (m0 >= cnt) return;
    int off = g_off[e];
    __shared__ float As[16][68];
    __shared__ float Bs[16][68];
    __shared__ int sent[64];
    int tid = threadIdx.x;
    if (tid < 64) {
        int i = m0 + tid;
        sent[tid] = (i < cnt) ? g_tok[off + i] : -1;
    }
    __syncthreads();
    const float* W = W2 + (long)e * DHc * Dc;
    int tx = tid & 15, ty = tid >> 4;
    int n0 = blockIdx.x * 64;
    int ra = tid >> 2, ca = (tid & 3) * 4;
    int rb = tid >> 4, cb = (tid & 15) * 4;
    float acc[4][4] = {};
    for (int k0 = 0; k0 < DHc; k0 += 16) {
        bool valid = (m0 + ra) < cnt;
        float4 av = valid ? *(const float4*)&g_hmid[(long)(off + m0 + ra) * DHc + k0 + ca]
                          : make_float4(0, 0, 0, 0);
        As[ca + 0][ra] = av.x; As[ca + 1][ra] = av.y;
        As[ca + 2][ra] = av.z; As[ca + 3][ra] = av.w;
        float4 bv = *(const float4*)&W[(long)(k0 + rb) * Dc + n0 + cb];
        Bs[rb][cb + 0] = bv.x; Bs[rb][cb + 1] = bv.y;
        Bs[rb][cb + 2] = bv.z; Bs[rb][cb + 3] = bv.w;
        __syncthreads();
#pragma unroll
        for (int k = 0; k < 16; k++) {
            float4 a = *(const float4*)&As[k][ty * 4];
            float4 b = *(const float4*)&Bs[k][tx * 4];
            acc[0][0] += a.x * b.x; acc[0][1] += a.x * b.y; acc[0][2] += a.x * b.z; acc[0][3] += a.x * b.w;
            acc[1][0] += a.y * b.x; acc[1][1] += a.y * b.y; acc[1][2] += a.y * b.z; acc[1][3] += a.y * b.w;
            acc[2][0] += a.z * b.x; acc[2][1] += a.z * b.y; acc[2][2] += a.z * b.z; acc[2][3] += a.z * b.w;
            acc[3][0] += a.w * b.x; acc[3][1] += a.w * b.y; acc[3][2] += a.w * b.z; acc[3][3] += a.w * b.w;
        }
        __syncthreads();
    }
    const float* be = B2 + e * Dc;
#pragma unroll
    for (int i = 0; i < 4; i++) {
        int rloc = m0 + ty * 4 + i;
        if (rloc >= cnt) break;
        int entry = sent[rloc - m0];
        float* dst = &g_ybuf[(long)entry * Dc + n0 + tx * 4];
#pragma unroll
        for (int j = 0; j < 4; j++) dst[j] = acc[i][j] + be[n0 + tx * 4 + j];
    }
}

// ---------------- combine: x += g0*y0 + g1*y1 ------------------------------
__global__ void combine_k(float* __restrict__ x) {
    int i = blockIdx.x * 256 + threadIdx.x;
    int t = i >> 9;
    int d = i & 511;
    x[i] += g_gate[t * 2] * g_ybuf[(long)(t * 2) * Dc + d]
          + g_gate[t * 2 + 1] * g_ybuf[(long)(t * 2 + 1) * Dc + d];
}

// ---------------- host ------------------------------------------------------
extern "C" void kernel_launch(void* const* d_in, const int* in_sizes, int n_in,
                              void* d_out, int out_size)
{
    const float* x      = (const float*)d_in[0];
    const float* ln1_w  = (const float*)d_in[1];
    const float* ln1_b  = (const float*)d_in[2];
    const float* wq     = (const float*)d_in[3];
    const float* wk     = (const float*)d_in[4];
    const float* wv     = (const float*)d_in[5];
    const float* wo     = (const float*)d_in[6];
    const float* bo     = (const float*)d_in[7];
    const float* ln2_w  = (const float*)d_in[8];
    const float* ln2_b  = (const float*)d_in[9];
    const float* gate_w = (const float*)d_in[10];
    const float* w1     = (const float*)d_in[11];
    const float* b1     = (const float*)d_in[12];
    const float* w2     = (const float*)d_in[13];
    const float* b2     = (const float*)d_in[14];
    float* out = (float*)d_out;

    float *ph, *pq, *pk, *pv, *ps, *pao;
    cudaGetSymbolAddress((void**)&ph,  g_h);
    cudaGetSymbolAddress((void**)&pq,  g_q);
    cudaGetSymbolAddress((void**)&pk,  g_k);
    cudaGetSymbolAddress((void**)&pv,  g_v);
    cudaGetSymbolAddress((void**)&ps,  g_s);
    cudaGetSymbolAddress((void**)&pao, g_ao);

    copy_k<<<Tc * Dc / 256, 256>>>(x, out);

    for (int l = 0; l < Lc; l++) {
        const float* wq_l = wq + (long)l * Dc * Dc;
        const float* wk_l = wk + (long)l * Dc * Dc;
        const float* wv_l = wv + (long)l * Dc * Dc;
        const float* wo_l = wo + (long)l * Dc * Dc;

        // LN1
        ln_k<<<Tc, 128>>>(out, ln1_w + l * Dc, ln1_b + l * Dc, ph);

        // QKV projections
        gemm_k<false><<<dim3(Dc / 64, Tc / 64, 1), 256>>>(
            Tc, Dc, Dc, ph, Dc, 0, 0, wq_l, Dc, 0, 0, pq, Dc, 0, 0, 1,
            nullptr, 1.f, 0);
        gemm_k<false><<<dim3(Dc / 64, Tc / 64, 1), 256>>>(
            Tc, Dc, Dc, ph, Dc, 0, 0, wk_l, Dc, 0, 0, pk, Dc, 0, 0, 1,
            nullptr, 1.f, 0);
        gemm_k<false><<<dim3(Dc / 64, Tc / 64, 1), 256>>>(
            Tc, Dc, Dc, ph, Dc, 0, 0, wv_l, Dc, 0, 0, pv, Dc, 0, 0, 1,
            nullptr, 1.f, 0);

        // scores = q @ k^T / 8, batched over (b,h)
        gemm_k<true><<<dim3(Sc / 64, Sc / 64, Bc * Hc), 256>>>(
            Sc, Sc, HEADc,
            pq, Dc, (long)Sc * Dc, HEADc,
            pk, Dc, (long)Sc * Dc, HEADc,
            ps, Sc, (long)Hc * Sc * Sc, (long)Sc * Sc, Hc,
            nullptr, 0.125f, 0);

        softmax_k<<<Bc * Hc * Sc, 256>>>(ps);

        // attn_out = scores @ v
        gemm_k<false><<<dim3(1, Sc / 64, Bc * Hc), 256>>>(
            Sc, HEADc, Sc,
            ps, Sc, (long)Hc * Sc * Sc, (long)Sc * Sc,
            pv, Dc, (long)Sc * Dc, HEADc,
            pao, Dc, (long)Sc * Dc, HEADc, Hc,
            nullptr, 1.f, 0);

        // x = attn_out @ wo + bo + x (fused bias + residual)
        gemm_k<false><<<dim3(Dc / 64, Tc / 64, 1), 256>>>(
            Tc, Dc, Dc, pao, Dc, 0, 0, wo_l, Dc, 0, 0, out, Dc, 0, 0, 1,
            bo + l * Dc, 1.f, 1);

        // LN2
        ln_k<<<Tc, 128>>>(out, ln2_w + l * Dc, ln2_b + l * Dc, ph);

        // gate + routing
        zero_k<<<1, 32>>>();
        gate_k<<<Tc / 4, 128>>>(ph, gate_w + (long)l * Dc * Ec);
        offsets_k<<<1, 1>>>();
        scatter_k<<<2 * Tc / 256, 256>>>();

        // grouped expert GEMMs
        moe_g1<<<dim3(DHc / 64, 2 * Tc / 64, Ec), 256>>>(
            ph, w1 + (long)l * Ec * Dc * DHc, b1 + (long)l * Ec * DHc);
        moe_g2<<<dim3(Dc / 64, 2 * Tc / 64, Ec), 256>>>(
            w2 + (long)l * Ec * DHc * Dc, b2 + (long)l * Ec * Dc);

        // x += gate-weighted expert outputs
        combine_k<<<Tc * Dc / 256, 256>>>(out);
    }
}

// round 3
// speedup vs baseline: 1.0417x; 1.0417x over previous
#include <cuda_runtime.h>
#include <cuda_bf16.h>
#include <math.h>
#include <stdint.h>

#define Tc 4096
#define Dc 512
#define Sc 1024
#define Bc 4
#define Hc 8
#define HEADc 64
#define Ec 8
#define DHc 2048
#define Lc 2

// ---------------- scratch (device globals; no runtime allocation) ----------
__device__ float g_h[Tc * Dc];
__device__ float g_q[Tc * Dc];
__device__ float g_k[Tc * Dc];
__device__ float g_v[Tc * Dc];
__device__ float g_s[(size_t)Bc * Hc * Sc * Sc];   // attention scores
__device__ float g_ao[Tc * Dc];
__device__ float g_hmid[(size_t)2 * Tc * DHc];
__device__ float g_ybuf[(size_t)Tc * 2 * Dc];
__device__ float g_gate[Tc * 2];
__device__ int   g_topi[Tc * 2];
__device__ int   g_cnt[Ec];
__device__ int   g_cur[Ec];
__device__ int   g_off[Ec];
__device__ int   g_tok[2 * Tc];

// ================= warp-MMA helpers ========================================
__device__ __forceinline__ uint32_t smem_u32(const void* p) {
    uint32_t a;
    asm("{ .reg .u64 t; cvta.to.shared.u64 t, %1; cvt.u32.u64 %0, t; }"
        : "=r"(a) : "l"(p));
    return a;
}
#define SWZ(o) ((o) ^ (((o) >> 3) & 0x70))

__device__ __forceinline__ void ldsm4(uint32_t* r, uint32_t addr) {
    asm volatile("ldmatrix.sync.aligned.m8n8.x4.shared.b16 {%0,%1,%2,%3}, [%4];"
                 : "=r"(r[0]), "=r"(r[1]), "=r"(r[2]), "=r"(r[3]) : "r"(addr));
}
__device__ __forceinline__ void mma_bf16(float* d, const uint32_t* a,
                                         uint32_t b0, uint32_t b1) {
    asm volatile(
        "mma.sync.aligned.m16n8k16.row.col.f32.bf16.bf16.f32 "
        "{%0,%1,%2,%3}, {%4,%5,%6,%7}, {%8,%9}, {%0,%1,%2,%3};"
        : "+f"(d[0]), "+f"(d[1]), "+f"(d[2]), "+f"(d[3])
        : "r"(a[0]), "r"(a[1]), "r"(a[2]), "r"(a[3]), "r"(b0), "r"(b1));
}

// bf16 hi/lo split + pack of 2 consecutive values
__device__ __forceinline__ void split2(float x0, float x1, uint32_t& hi, uint32_t& lo) {
    __nv_bfloat16 h0 = __float2bfloat16(x0);
    __nv_bfloat16 h1 = __float2bfloat16(x1);
    __nv_bfloat16 l0 = __float2bfloat16(x0 - __bfloat162float(h0));
    __nv_bfloat16 l1 = __float2bfloat16(x1 - __bfloat162float(h1));
    hi = (uint32_t)__bfloat16_as_ushort(h0) | ((uint32_t)__bfloat16_as_ushort(h1) << 16);
    lo = (uint32_t)__bfloat16_as_ushort(l0) | ((uint32_t)__bfloat16_as_ushort(l1) << 16);
}

// ================= unified tensor GEMM (HMMA, 3-MMA bf16 split) ============
// C[128x128 tile] = alpha * A @ op(B) (+bias)(+C), fp32 accum.
// BT: B stored [N,K] (K contiguous). else B stored [K,N] (N contiguous).
// EPI: 0 plain*alpha; 1 +bias +C(resid); 2 gelu(+bias)->grouped C; 3 +bias->scatter C
// AMODE: 0 direct A; 1 gather rows via g_tok>>1; 2 grouped rows off+m of A
#define TG_SMEM (65536 + 1024)
template <bool BT, int EPI, int AMODE>
__global__ void __launch_bounds__(256) tgemm(
    int Nvalid, int K,
    const float* __restrict__ A, int lda, long sa1, long sa2,
    const float* __restrict__ B, int ldb, long sb1, long sb2,
    float* __restrict__ C, int ldc, long sc1, long sc2,
    int zh, const float* __restrict__ bias, float alpha,
    long wstride, long bstride)
{
    extern __shared__ char dsm[];
    __shared__ int stok_s[128];
    uint32_t sbb = smem_u32(dsm);
    uint32_t tb = (sbb + 1023) & ~1023u;
    char* tilep = dsm + (tb - sbb);
    const uint32_t OAH = 0, OAL = 16384, OBH = 32768, OBL = 49152;

    int tid = threadIdx.x, wid = tid >> 5, lid = tid & 31;

    int cnt = 0, off = 0;
    if (AMODE != 0) {
        int e = blockIdx.z;
        cnt = g_cnt[e]; off = g_off[e];
        if ((int)blockIdx.y * 128 >= cnt) return;
        B += (long)e * wstride;
        bias += (long)e * bstride;
    } else {
        int z = blockIdx.z, zb = z / zh, zhh = z - zb * zh;
        A += zb * sa1 + zhh * sa2;
        B += zb * sb1 + zhh * sb2;
        C += zb * sc1 + zhh * sc2;
    }
    int m0 = blockIdx.y * 128, n0 = blockIdx.x * 128;

    if (AMODE == 1 && tid < 128) {
        int i = m0 + tid;
        stok_s[tid] = (i < cnt) ? (g_tok[off + i] >> 1) : -1;
    }
    if (AMODE == 2 && tid < 128) {
        int i = m0 + tid;
        stok_s[tid] = (i < cnt) ? g_tok[off + i] : -1;
    }
    if (AMODE != 0) __syncthreads();

    // warp tile: 64(M) x 32(N)
    int wm = (wid >> 2) * 64, wn = (wid & 3) * 32;

    // per-lane ldmatrix source offsets (byte offsets before swizzle)
    int a_row = wm + (lid & 15);
    int a_cb  = (lid >> 4) << 4;                       // 0 or 16 bytes
    int b_row = wn + ((lid >> 4) << 3) + (lid & 7);    // two 8-row n groups
    int b_cb  = ((lid >> 3) & 1) << 4;

    float acc[4][4][4] = {};

    int nchunks = K >> 6;
    for (int c = 0; c < nchunks; c++) {
        int k0 = c << 6;
        // ---- stage A tile: 128 rows x 64 k (hi/lo bf16) ----
#pragma unroll
        for (int i = 0; i < 16; i++) {
            int p = tid + (i << 8);
            int row = p >> 5, cp = p & 31;
            int kg = k0 + cp * 2;
            float2 x;
            if (AMODE == 0) {
                x = *(const float2*)&A[(long)(m0 + row) * lda + kg];
            } else if (AMODE == 1) {
                int tk = stok_s[row];
                x = (tk >= 0) ? *(const float2*)&A[(long)tk * lda + kg]
                              : make_float2(0.f, 0.f);
            } else {
                x = (stok_s[row] >= 0)
                        ? *(const float2*)&A[(long)(off + m0 + row) * lda + kg]
                        : make_float2(0.f, 0.f);
            }
            uint32_t hi, lo; split2(x.x, x.y, hi, lo);
            uint32_t o = SWZ((uint32_t)(row * 128 + cp * 4));
            *(uint32_t*)(tilep + OAH + o) = hi;
            *(uint32_t*)(tilep + OAL + o) = lo;
        }
        // ---- stage B tile: 128 n-rows x 64 k ----
#pragma unroll
        for (int i = 0; i < 16; i++) {
            int p = tid + (i << 8);
            float x0, x1; int row, cp;
            if (BT) {
                row = p >> 5; cp = p & 31;
                int kg = k0 + cp * 2;
                if (n0 + row < Nvalid) {
                    float2 xx = *(const float2*)&B[(long)(n0 + row) * ldb + kg];
                    x0 = xx.x; x1 = xx.y;
                } else { x0 = x1 = 0.f; }
            } else {
                row = p & 127; cp = p >> 7;
                int kg = k0 + cp * 2;
                bool valid = (n0 + row) < Nvalid;
                x0 = valid ? B[(long)kg * ldb + n0 + row] : 0.f;
                x1 = valid ? B[(long)(kg + 1) * ldb + n0 + row] : 0.f;
            }
            uint32_t hi, lo; split2(x0, x1, hi, lo);
            uint32_t o = SWZ((uint32_t)(row * 128 + cp * 4));
            *(uint32_t*)(tilep + OBH + o) = hi;
            *(uint32_t*)(tilep + OBL + o) = lo;
        }
        __syncthreads();

        // ---- consume: 4 k-steps of m16n8k16, 3-way split ----
#pragma unroll
        for (int ks = 0; ks < 4; ks++) {
            int kb = ks * 32;
            uint32_t aH[4][4], aL[4][4], bH[2][4], bL[2][4];
#pragma unroll
            for (int mt = 0; mt < 4; mt++) {
                uint32_t o = SWZ((uint32_t)((a_row + mt * 16) * 128 + kb + a_cb));
                ldsm4(aH[mt], tb + OAH + o);
                ldsm4(aL[mt], tb + OAL + o);
            }
#pragma unroll
            for (int g = 0; g < 2; g++) {
                uint32_t o = SWZ((uint32_t)((b_row + g * 16) * 128 + kb + b_cb));
                ldsm4(bH[g], tb + OBH + o);
                ldsm4(bL[g], tb + OBL + o);
            }
#pragma unroll
            for (int mt = 0; mt < 4; mt++)
#pragma unroll
                for (int nt = 0; nt < 4; nt++) {
                    int g = nt >> 1, pr = (nt & 1) * 2;
                    mma_bf16(acc[mt][nt], aH[mt], bH[g][pr], bH[g][pr + 1]);
                    mma_bf16(acc[mt][nt], aH[mt], bL[g][pr], bL[g][pr + 1]);
                    mma_bf16(acc[mt][nt], aL[mt], bH[g][pr], bH[g][pr + 1]);
                }
        }
        __syncthreads();
    }

    // ---- epilogue straight from registers ----
    int lr = (lid >> 2);               // 0..7
    int lc = (lid & 3) * 2;            // 0,2,4,6
#pragma unroll
    for (int mt = 0; mt < 4; mt++) {
#pragma unroll
        for (int half = 0; half < 2; half++) {
            int lrow = wm + mt * 16 + lr + half * 8;   // local row 0..127
            int grow = m0 + lrow;
#pragma unroll
            for (int nt = 0; nt < 4; nt++) {
                float v0 = acc[mt][nt][half * 2 + 0];
                float v1 = acc[mt][nt][half * 2 + 1];
                int gc = n0 + wn + nt * 8 + lc;
                if (EPI == 0) {
                    if (gc < Nvalid) {
                        float2 o = make_float2(v0 * alpha, v1 * alpha);
                        *(float2*)&C[(long)grow * ldc + gc] = o;
                    }
                } else if (EPI == 1) {
                    long idx = (long)grow * ldc + gc;
                    float2 old = *(const float2*)&C[idx];
                    *(float2*)&C[idx] = make_float2(v0 + bias[gc] + old.x,
                                                    v1 + bias[gc + 1] + old.y);
                } else if (EPI == 2) {
                    if (stok_s[lrow] >= 0) {
                        float t0 = v0 + bias[gc];
                        float t1 = v1 + bias[gc + 1];
                        float o0 = 0.5f * t0 * (1.f + erff(t0 * 0.70710678118654752f));
                        float o1 = 0.5f * t1 * (1.f + erff(t1 * 0.70710678118654752f));
                        *(float2*)&C[(long)(off + grow) * ldc + gc] = make_float2(o0, o1);
                    }
                } else {  // EPI == 3
                    int ent = stok_s[lrow];
                    if (ent >= 0) {
                        *(float2*)&C[(long)ent * ldc + gc] =
                            make_float2(v0 + bias[gc], v1 + bias[gc + 1]);
                    }
                }
            }
        }
    }
}

// ================= SIMT helpers =============================================
__global__ void copy_k(const float* __restrict__ a, float* __restrict__ o) {
    long i = (long)blockIdx.x * 256 + threadIdx.x;
    o[i] = a[i];
}

__global__ void ln_k(const float* __restrict__ x, const float* __restrict__ w,
                     const float* __restrict__ b, float* __restrict__ out) {
    int row = blockIdx.x;
    const float* xr = x + (long)row * Dc;
    int tid = threadIdx.x;
    float v[4];
    float s = 0.f, s2 = 0.f;
#pragma unroll
    for (int i = 0; i < 4; i++) {
        v[i] = xr[tid + i * 128];
        s += v[i]; s2 += v[i] * v[i];
    }
    __shared__ float sh[4], sh2[4];
#pragma unroll
    for (int o = 16; o > 0; o >>= 1) {
        s  += __shfl_xor_sync(0xffffffffu, s, o);
        s2 += __shfl_xor_sync(0xffffffffu, s2, o);
    }
    if ((tid & 31) == 0) { sh[tid >> 5] = s; sh2[tid >> 5] = s2; }
    __syncthreads();
    if (tid == 0) {
        float a = 0.f, a2 = 0.f;
#pragma unroll
        for (int i = 0; i < 4; i++) { a += sh[i]; a2 += sh2[i]; }
        sh[0] = a; sh2[0] = a2;
    }
    __syncthreads();
    float mu  = sh[0] * (1.f / Dc);
    float var = sh2[0] * (1.f / Dc) - mu * mu;
    float inv = rsqrtf(var + 1e-6f);
#pragma unroll
    for (int i = 0; i < 4; i++) {
        int d = tid + i * 128;
        out[(long)row * Dc + d] = (v[i] - mu) * inv * w[d] + b[d];
    }
}

__global__ void softmax_k(float* __restrict__ s) {
    long row = blockIdx.x;
    float* r = s + row * Sc;
    int tid = threadIdx.x;
    float v[4];
    float m = -3.4e38f;
#pragma unroll
    for (int i = 0; i < 4; i++) { v[i] = r[tid + i * 256]; m = fmaxf(m, v[i]); }
    __shared__ float sh[8], sh2[8];
#pragma unroll
    for (int o = 16; o > 0; o >>= 1) m = fmaxf(m, __shfl_xor_sync(0xffffffffu, m, o));
    if ((tid & 31) == 0) sh[tid >> 5] = m;
    __syncthreads();
    if (tid == 0) {
        float t = sh[0];
#pragma unroll
        for (int i = 1; i < 8; i++) t = fmaxf(t, sh[i]);
        sh[0] = t;
    }
    __syncthreads();
    m = sh[0];
    float sum = 0.f;
#pragma unroll
    for (int i = 0; i < 4; i++) { v[i] = expf(v[i] - m); sum += v[i]; }
#pragma unroll
    for (int o = 16; o > 0; o >>= 1) sum += __shfl_xor_sync(0xffffffffu, sum, o);
    if ((tid & 31) == 0) sh2[tid >> 5] = sum;
    __syncthreads();
    if (tid == 0) {
        float t = 0.f;
#pragma unroll
        for (int i = 0; i < 8; i++) t += sh2[i];
        sh2[0] = t;
    }
    __syncthreads();
    float inv = 1.f / sh2[0];
#pragma unroll
    for (int i = 0; i < 4; i++) r[tid + i * 256] = v[i] * inv;
}

__global__ void zero_k() { if (threadIdx.x < Ec) g_cnt[threadIdx.x] = 0; }

__global__ void gate_k(const float* __restrict__ h, const float* __restrict__ gw) {
    int t = blockIdx.x * 4 + (threadIdx.x >> 5);
    int lid = threadIdx.x & 31;
    const float* hr = h + (long)t * Dc;
    float acc[Ec] = {};
    for (int d = lid; d < Dc; d += 32) {
        float hv = hr[d];
#pragma unroll
        for (int e = 0; e < Ec; e++) acc[e] += hv * gw[d * Ec + e];
    }
#pragma unroll
    for (int e = 0; e < Ec; e++)
#pragma unroll
        for (int o = 16; o > 0; o >>= 1)
            acc[e] += __shfl_xor_sync(0xffffffffu, acc[e], o);
    if (lid == 0) {
        int i0 = 0; float v0 = acc[0];
#pragma unroll
        for (int e = 1; e < Ec; e++) if (acc[e] > v0) { v0 = acc[e]; i0 = e; }
        int i1 = -1; float v1 = -3.4e38f;
#pragma unroll
        for (int e = 0; e < Ec; e++) if (e != i0 && acc[e] > v1) { v1 = acc[e]; i1 = e; }
        float g1 = 1.f / (1.f + expf(v0 - v1));
        float g0 = 1.f - g1;
        g_topi[t * 2] = i0; g_topi[t * 2 + 1] = i1;
        g_gate[t * 2] = g0; g_gate[t * 2 + 1] = g1;
        atomicAdd(&g_cnt[i0], 1);
        atomicAdd(&g_cnt[i1], 1);
    }
}

__global__ void offsets_k() {
    if (threadIdx.x == 0) {
        int o = 0;
        for (int e = 0; e < Ec; e++) { g_off[e] = o; g_cur[e] = o; o += g_cnt[e]; }
    }
}

__global__ void scatter_k() {
    int i = blockIdx.x * 256 + threadIdx.x;
    if (i >= 2 * Tc) return;
    int e = g_topi[i];
    int pos = atomicAdd(&g_cur[e], 1);
    g_tok[pos] = i;
}

__global__ void combine_k(float* __restrict__ x) {
    int i = blockIdx.x * 256 + threadIdx.x;
    int t = i >> 9;
    int d = i & 511;
    x[i] += g_gate[t * 2] * g_ybuf[(long)(t * 2) * Dc + d]
          + g_gate[t * 2 + 1] * g_ybuf[(long)(t * 2 + 1) * Dc + d];
}

// ================= host =====================================================
extern "C" void kernel_launch(void* const* d_in, const int* in_sizes, int n_in,
                              void* d_out, int out_size)
{
    const float* x      = (const float*)d_in[0];
    const float* ln1_w  = (const float*)d_in[1];
    const float* ln1_b  = (const float*)d_in[2];
    const float* wq     = (const float*)d_in[3];
    const float* wk     = (const float*)d_in[4];
    const float* wv     = (const float*)d_in[5];
    const float* wo     = (const float*)d_in[6];
    const float* bo     = (const float*)d_in[7];
    const float* ln2_w  = (const float*)d_in[8];
    const float* ln2_b  = (const float*)d_in[9];
    const float* gate_w = (const float*)d_in[10];
    const float* w1     = (const float*)d_in[11];
    const float* b1     = (const float*)d_in[12];
    const float* w2     = (const float*)d_in[13];
    const float* b2     = (const float*)d_in[14];
    float* out = (float*)d_out;

    float *ph, *pq, *pk, *pv, *ps, *pao, *phm, *pyb;
    cudaGetSymbolAddress((void**)&ph,  g_h);
    cudaGetSymbolAddress((void**)&pq,  g_q);
    cudaGetSymbolAddress((void**)&pk,  g_k);
    cudaGetSymbolAddress((void**)&pv,  g_v);
    cudaGetSymbolAddress((void**)&ps,  g_s);
    cudaGetSymbolAddress((void**)&pao, g_ao);
    cudaGetSymbolAddress((void**)&phm, g_hmid);
    cudaGetSymbolAddress((void**)&pyb, g_ybuf);

    cudaFuncSetAttribute(tgemm<false, 0, 0>, cudaFuncAttributeMaxDynamicSharedMemorySize, TG_SMEM);
    cudaFuncSetAttribute(tgemm<true,  0, 0>, cudaFuncAttributeMaxDynamicSharedMemorySize, TG_SMEM);
    cudaFuncSetAttribute(tgemm<false, 1, 0>, cudaFuncAttributeMaxDynamicSharedMemorySize, TG_SMEM);
    cudaFuncSetAttribute(tgemm<false, 2, 1>, cudaFuncAttributeMaxDynamicSharedMemorySize, TG_SMEM);
    cudaFuncSetAttribute(tgemm<false, 3, 2>, cudaFuncAttributeMaxDynamicSharedMemorySize, TG_SMEM);

    copy_k<<<Tc * Dc / 256, 256>>>(x, out);

    for (int l = 0; l < Lc; l++) {
        const float* wq_l = wq + (long)l * Dc * Dc;
        const float* wk_l = wk + (long)l * Dc * Dc;
        const float* wv_l = wv + (long)l * Dc * Dc;
        const float* wo_l = wo + (long)l * Dc * Dc;

        ln_k<<<Tc, 128>>>(out, ln1_w + l * Dc, ln1_b + l * Dc, ph);

        // QKV projections
        tgemm<false, 0, 0><<<dim3(4, 32, 1), 256, TG_SMEM>>>(
            Dc, Dc, ph, Dc, 0, 0, wq_l, Dc, 0, 0, pq, Dc, 0, 0, 1, nullptr, 1.f, 0, 0);
        tgemm<false, 0, 0><<<dim3(4, 32, 1), 256, TG_SMEM>>>(
            Dc, Dc, ph, Dc, 0, 0, wk_l, Dc, 0, 0, pk, Dc, 0, 0, 1, nullptr, 1.f, 0, 0);
        tgemm<false, 0, 0><<<dim3(4, 32, 1), 256, TG_SMEM>>>(
            Dc, Dc, ph, Dc, 0, 0, wv_l, Dc, 0, 0, pv, Dc, 0, 0, 1, nullptr, 1.f, 0, 0);

        // scores = q @ k^T / 8
        tgemm<true, 0, 0><<<dim3(8, 8, Bc * Hc), 256, TG_SMEM>>>(
            Sc, HEADc,
            pq, Dc, (long)Sc * Dc, HEADc,
            pk, Dc, (long)Sc * Dc, HEADc,
            ps, Sc, (long)Hc * Sc * Sc, (long)Sc * Sc,
            Hc, nullptr, 0.125f, 0, 0);

        softmax_k<<<Bc * Hc * Sc, 256>>>(ps);

        // attn_out = scores @ v
        tgemm<false, 0, 0><<<dim3(1, 8, Bc * Hc), 256, TG_SMEM>>>(
            HEADc, Sc,
            ps, Sc, (long)Hc * Sc * Sc, (long)Sc * Sc,
            pv, Dc, (long)Sc * Dc, HEADc,
            pao, Dc, (long)Sc * Dc, HEADc,
            Hc, nullptr, 1.f, 0, 0);

        // x = attn_out @ wo + bo + x
        tgemm<false, 1, 0><<<dim3(4, 32, 1), 256, TG_SMEM>>>(
            Dc, Dc, pao, Dc, 0, 0, wo_l, Dc, 0, 0, out, Dc, 0, 0, 1,
            bo + l * Dc, 1.f, 0, 0);

        ln_k<<<Tc, 128>>>(out, ln2_w + l * Dc, ln2_b + l * Dc, ph);

        zero_k<<<1, 32>>>();
        gate_k<<<Tc / 4, 128>>>(ph, gate_w + (long)l * Dc * Ec);
        offsets_k<<<1, 1>>>();
        scatter_k<<<2 * Tc / 256, 256>>>();

        // grouped expert GEMMs (tensor)
        tgemm<false, 2, 1><<<dim3(16, 64, Ec), 256, TG_SMEM>>>(
            DHc, Dc, ph, Dc, 0, 0,
            w1 + (long)l * Ec * Dc * DHc, DHc, 0, 0,
            phm, DHc, 0, 0, 1,
            b1 + (long)l * Ec * DHc, 1.f, (long)Dc * DHc, DHc);
        tgemm<false, 3, 2><<<dim3(4, 64, Ec), 256, TG_SMEM>>>(
            Dc, DHc, phm, DHc, 0, 0,
            w2 + (long)l * Ec * DHc * Dc, Dc, 0, 0,
            pyb, Dc, 0, 0, 1,
            b2 + (long)l * Ec * Dc, 1.f, (long)DHc * Dc, Dc);

        combine_k<<<Tc * Dc / 256, 256>>>(out);
    }
}

// round 4
// speedup vs baseline: 2.5384x; 2.4369x over previous
#include <cuda_runtime.h>
#include <cuda_bf16.h>
#include <math.h>
#include <stdint.h>

#define Tc 4096
#define Dc 512
#define Sc 1024
#define Bc 4
#define Hc 8
#define HEADc 64
#define Ec 8
#define DHc 2048
#define Lc 2

typedef __nv_bfloat16 bf16;

// ---------------- scratch (device globals) ---------------------------------
__device__ float g_h[Tc * Dc];
__device__ bf16  g_h_hi[Tc * Dc], g_h_lo[Tc * Dc];
__device__ bf16  g_q_hi[Tc * Dc], g_q_lo[Tc * Dc];
__device__ bf16  g_k_hi[Tc * Dc], g_k_lo[Tc * Dc];
__device__ float g_v[Tc * Dc];
__device__ bf16  g_vt_hi[Tc * Dc], g_vt_lo[Tc * Dc];     // [B][D][S]
__device__ float g_s[(size_t)Bc * Hc * Sc * Sc];
__device__ bf16  g_s_hi[(size_t)Bc * Hc * Sc * Sc], g_s_lo[(size_t)Bc * Hc * Sc * Sc];
__device__ bf16  g_ao_hi[Tc * Dc], g_ao_lo[Tc * Dc];
__device__ bf16  g_hm_hi[(size_t)2 * Tc * DHc], g_hm_lo[(size_t)2 * Tc * DHc];
__device__ float g_ybuf[(size_t)2 * Tc * Dc];
__device__ bf16  g_wqt_hi[Dc * Dc], g_wqt_lo[Dc * Dc];
__device__ bf16  g_wkt_hi[Dc * Dc], g_wkt_lo[Dc * Dc];
__device__ bf16  g_wvt_hi[Dc * Dc], g_wvt_lo[Dc * Dc];
__device__ bf16  g_wot_hi[Dc * Dc], g_wot_lo[Dc * Dc];
__device__ bf16  g_w1t_hi[(size_t)Ec * Dc * DHc], g_w1t_lo[(size_t)Ec * Dc * DHc];
__device__ bf16  g_w2t_hi[(size_t)Ec * Dc * DHc], g_w2t_lo[(size_t)Ec * Dc * DHc];
__device__ float g_gate[Tc * 2];
__device__ int   g_topi[Tc * 2];
__device__ int   g_cnt[Ec], g_cur[Ec], g_off[Ec];
__device__ int   g_tok[2 * Tc];

// ================= low-level helpers ========================================
__device__ __forceinline__ uint32_t smem_u32(const void* p) {
    uint32_t a;
    asm("{ .reg .u64 t; cvta.to.shared.u64 t, %1; cvt.u32.u64 %0, t; }"
        : "=r"(a) : "l"(p));
    return a;
}
#define SWZ(o) ((o) ^ (((o) >> 3) & 0x70))
#define CP16(dst, src, sz) \
    asm volatile("cp.async.cg.shared.global [%0], [%1], 16, %2;" \
                 :: "r"(dst), "l"(src), "r"(sz) : "memory")
#define CP_COMMIT() asm volatile("cp.async.commit_group;" ::: "memory")

__device__ __forceinline__ void ldsm4(uint32_t* r, uint32_t addr) {
    asm volatile("ldmatrix.sync.aligned.m8n8.x4.shared.b16 {%0,%1,%2,%3}, [%4];"
                 : "=r"(r[0]), "=r"(r[1]), "=r"(r[2]), "=r"(r[3]) : "r"(addr));
}
__device__ __forceinline__ void mma_bf16(float* d, const uint32_t* a,
                                         uint32_t b0, uint32_t b1) {
    asm volatile(
        "mma.sync.aligned.m16n8k16.row.col.f32.bf16.bf16.f32 "
        "{%0,%1,%2,%3}, {%4,%5,%6,%7}, {%8,%9}, {%0,%1,%2,%3};"
        : "+f"(d[0]), "+f"(d[1]), "+f"(d[2]), "+f"(d[3])
        : "r"(a[0]), "r"(a[1]), "r"(a[2]), "r"(a[3]), "r"(b0), "r"(b1));
}
__device__ __forceinline__ void split2(float x0, float x1, uint32_t& hi, uint32_t& lo) {
    bf16 h0 = __float2bfloat16(x0);
    bf16 h1 = __float2bfloat16(x1);
    bf16 l0 = __float2bfloat16(x0 - __bfloat162float(h0));
    bf16 l1 = __float2bfloat16(x1 - __bfloat162float(h1));
    hi = (uint32_t)__bfloat16_as_ushort(h0) | ((uint32_t)__bfloat16_as_ushort(h1) << 16);
    lo = (uint32_t)__bfloat16_as_ushort(l0) | ((uint32_t)__bfloat16_as_ushort(l1) << 16);
}

// ================= pipelined tensor GEMM ====================================
// A: [*,K] K-major bf16 hi/lo.  B: [N,K] K-major bf16 hi/lo.  128xBN tile.
// EPI: 0 fp32*alpha; 1 fp32+bias+C; 2 gelu(+bias)->bf16pair grouped;
//      3 +bias->scatter fp32; 4 bf16 pair plain
// AMODE: 0 direct; 1 gather rows via g_tok>>1; 2 grouped rows off+m
template <int BN, int EPI, int AMODE>
__global__ void __launch_bounds__(256, 1) tgemm(
    int K,
    const bf16* __restrict__ Ahi, const bf16* __restrict__ Alo,
    int lda, long sa1, long sa2,
    const bf16* __restrict__ Bhi, const bf16* __restrict__ Blo,
    int ldb, long sb1, long sb2,
    float* __restrict__ C, bf16* __restrict__ Chi, bf16* __restrict__ Clo,
    int ldc, long sc1, long sc2, int zh,
    const float* __restrict__ bias, float alpha, long wstride, long bstride)
{
    constexpr int NWN = BN / 32, NWM = 8 / NWN, MT = 8 / NWM;
    constexpr uint32_t ASZ = 16384u, BSZ = (uint32_t)BN * 128u;
    constexpr uint32_t STG = 2 * ASZ + 2 * BSZ;
    extern __shared__ char dsm[];
    __shared__ int stok_s[128];
    uint32_t sbb = smem_u32(dsm);
    uint32_t tb = (sbb + 1023) & ~1023u;
    int tid = threadIdx.x, wid = tid >> 5, lid = tid & 31;

    int cnt = 0, off = 0;
    if (AMODE != 0) {
        int e = blockIdx.z;
        cnt = g_cnt[e]; off = g_off[e];
        if ((int)blockIdx.y * 128 >= cnt) return;
        Bhi += (long)e * wstride; Blo += (long)e * wstride;
        bias += (long)e * bstride;
    } else {
        int z = blockIdx.z, zb = z / zh, zhh = z - zb * zh;
        Ahi += zb * sa1 + zhh * sa2; Alo += zb * sa1 + zhh * sa2;
        Bhi += zb * sb1 + zhh * sb2; Blo += zb * sb1 + zhh * sb2;
        if (EPI == 2 || EPI == 4) { Chi += zb * sc1 + zhh * sc2; Clo += zb * sc1 + zhh * sc2; }
        else                       { C   += zb * sc1 + zhh * sc2; }
    }
    int m0 = blockIdx.y * 128, n0 = blockIdx.x * BN;

    if (AMODE == 1 && tid < 128) {
        int i = m0 + tid;
        stok_s[tid] = (i < cnt) ? (g_tok[off + i] >> 1) : -1;
    }
    if (AMODE == 2 && tid < 128) {
        int i = m0 + tid;
        stok_s[tid] = (i < cnt) ? g_tok[off + i] : -1;
    }
    if (AMODE != 0) __syncthreads();

    auto load_stage = [&](int c, int st) {
        uint32_t base = tb + (uint32_t)st * STG;
        int k0 = c << 6;
#pragma unroll
        for (int i = 0; i < 4; i++) {
            int idx = tid + (i << 8);
            int row = idx >> 3, c16 = idx & 7;
            uint32_t d = SWZ((uint32_t)(row * 128 + c16 * 16));
            long so; uint32_t sz = 16;
            if (AMODE == 0) so = (long)(m0 + row) * lda + k0 + c16 * 8;
            else if (AMODE == 1) {
                int tk = stok_s[row];
                if (tk < 0) { sz = 0; tk = 0; }
                so = (long)tk * lda + k0 + c16 * 8;
            } else {
                if (stok_s[row] < 0) { sz = 0; so = 0; }
                else so = (long)(off + m0 + row) * lda + k0 + c16 * 8;
            }
            CP16(base + d, Ahi + so, sz);
            CP16(base + ASZ + d, Alo + so, sz);
        }
#pragma unroll
        for (int i = 0; i < BN / 32; i++) {
            int idx = tid + (i << 8);
            int row = idx >> 3, c16 = idx & 7;
            uint32_t d = SWZ((uint32_t)(row * 128 + c16 * 16));
            long so = (long)(n0 + row) * ldb + k0 + c16 * 8;
            CP16(base + 2 * ASZ + d, Bhi + so, 16);
            CP16(base + 2 * ASZ + BSZ + d, Blo + so, 16);
        }
        CP_COMMIT();
    };

    int wm = (wid / NWN) * (MT * 16), wn = (wid % NWN) * 32;
    int a_row = wm + (lid & 15), a_cb = (lid >> 4) << 4;
    int b_row = wn + ((lid >> 4) << 3) + (lid & 7), b_cb = ((lid >> 3) & 1) << 4;
    float acc[MT][4][4] = {};

    int nch = K >> 6;
    load_stage(0, 0);
    for (int c = 0; c < nch; c++) {
        if (c + 1 < nch) {
            load_stage(c + 1, (c + 1) & 1);
            asm volatile("cp.async.wait_group 1;" ::: "memory");
        } else {
            asm volatile("cp.async.wait_group 0;" ::: "memory");
        }
        __syncthreads();
        uint32_t base = tb + (uint32_t)(c & 1) * STG;
#pragma unroll
        for (int ks = 0; ks < 4; ks++) {
            int kb = ks * 32;
            uint32_t aH[MT][4], aL[MT][4], bH[2][4], bL[2][4];
#pragma unroll
            for (int mt = 0; mt < MT; mt++) {
                uint32_t o = SWZ((uint32_t)((a_row + mt * 16) * 128 + kb + a_cb));
                ldsm4(aH[mt], base + o);
                ldsm4(aL[mt], base + ASZ + o);
            }
#pragma unroll
            for (int g = 0; g < 2; g++) {
                uint32_t o = SWZ((uint32_t)((b_row + g * 16) * 128 + kb + b_cb));
                ldsm4(bH[g], base + 2 * ASZ + o);
                ldsm4(bL[g], base + 2 * ASZ + BSZ + o);
            }
#pragma unroll
            for (int mt = 0; mt < MT; mt++)
#pragma unroll
                for (int nt = 0; nt < 4; nt++) {
                    int g = nt >> 1, pr = (nt & 1) * 2;
                    mma_bf16(acc[mt][nt], aH[mt], bH[g][pr], bH[g][pr + 1]);
                    mma_bf16(acc[mt][nt], aH[mt], bL[g][pr], bL[g][pr + 1]);
                    mma_bf16(acc[mt][nt], aL[mt], bH[g][pr], bH[g][pr + 1]);
                }
        }
        __syncthreads();
    }

    // ---- register epilogue ----
    int lr = lid >> 2, lc = (lid & 3) * 2;
#pragma unroll
    for (int mt = 0; mt < MT; mt++) {
#pragma unroll
        for (int half = 0; half < 2; half++) {
            int lrow = wm + mt * 16 + lr + half * 8;
            int grow = m0 + lrow;
#pragma unroll
            for (int nt = 0; nt < 4; nt++) {
                float v0 = acc[mt][nt][half * 2 + 0];
                float v1 = acc[mt][nt][half * 2 + 1];
                int gc = n0 + wn + nt * 8 + lc;
                if (EPI == 0) {
                    *(float2*)&C[(long)grow * ldc + gc] = make_float2(v0 * alpha, v1 * alpha);
                } else if (EPI == 1) {
                    long idx = (long)grow * ldc + gc;
                    float2 old = *(const float2*)&C[idx];
                    *(float2*)&C[idx] = make_float2(v0 + bias[gc] + old.x,
                                                    v1 + bias[gc + 1] + old.y);
                } else if (EPI == 2) {
                    if (stok_s[lrow] >= 0) {
                        float t0 = v0 + bias[gc], t1 = v1 + bias[gc + 1];
                        float o0 = 0.5f * t0 * (1.f + erff(t0 * 0.70710678118654752f));
                        float o1 = 0.5f * t1 * (1.f + erff(t1 * 0.70710678118654752f));
                        uint32_t hi, lo; split2(o0, o1, hi, lo);
                        long idx = (long)(off + grow) * ldc + gc;
                        *(uint32_t*)&Chi[idx] = hi;
                        *(uint32_t*)&Clo[idx] = lo;
                    }
                } else if (EPI == 3) {
                    int ent = stok_s[lrow];
                    if (ent >= 0) {
                        *(float2*)&C[(long)ent * ldc + gc] =
                            make_float2(v0 + bias[gc], v1 + bias[gc + 1]);
                    }
                } else {  // EPI == 4
                    uint32_t hi, lo; split2(v0, v1, hi, lo);
                    long idx = (long)grow * ldc + gc;
                    *(uint32_t*)&Chi[idx] = hi;
                    *(uint32_t*)&Clo[idx] = lo;
                }
            }
        }
    }
}

// ================= transpose + split convert ================================
// in fp32 [R, Ccol] -> out bf16 hi/lo [Ccol, R]; batched via sin/sout strides
__global__ void tconv(const float* __restrict__ in, bf16* __restrict__ ohi,
                      bf16* __restrict__ olo, int R, int Ccol, long sin, long sout)
{
    __shared__ float t[32][33];
    long ib = (long)blockIdx.z * sin, ob = (long)blockIdx.z * sout;
    int c0 = blockIdx.x * 32, r0 = blockIdx.y * 32;
    int tx = threadIdx.x, ty = threadIdx.y;
#pragma unroll
    for (int j = 0; j < 4; j++)
        t[ty + j * 8][tx] = in[ib + (long)(r0 + ty + j * 8) * Ccol + c0 + tx];
    __syncthreads();
#pragma unroll
    for (int j = 0; j < 4; j++) {
        float v = t[tx][ty + j * 8];
        bf16 h = __float2bfloat16(v);
        long o = ob + (long)(c0 + ty + j * 8) * R + r0 + tx;
        ohi[o] = h;
        olo[o] = __float2bfloat16(v - __bfloat162float(h));
    }
}

// ================= elementwise kernels ======================================
__global__ void copy_k(const float* __restrict__ a, float* __restrict__ o) {
    long i = (long)blockIdx.x * 256 + threadIdx.x;
    o[i] = a[i];
}

// LN: 128 threads, each handles 4 contiguous elements; writes fp32 + bf16 pair
__global__ void ln_k(const float* __restrict__ x, const float* __restrict__ w,
                     const float* __restrict__ b, float* __restrict__ out,
                     bf16* __restrict__ ohi, bf16* __restrict__ olo) {
    int row = blockIdx.x;
    const float* xr = x + (long)row * Dc;
    int tid = threadIdx.x;
    float4 v = *(const float4*)&xr[tid * 4];
    float s = v.x + v.y + v.z + v.w;
    float s2 = v.x * v.x + v.y * v.y + v.z * v.z + v.w * v.w;
    __shared__ float sh[4], sh2[4];
#pragma unroll
    for (int o = 16; o > 0; o >>= 1) {
        s  += __shfl_xor_sync(0xffffffffu, s, o);
        s2 += __shfl_xor_sync(0xffffffffu, s2, o);
    }
    if ((tid & 31) == 0) { sh[tid >> 5] = s; sh2[tid >> 5] = s2; }
    __syncthreads();
    float a = 0.f, a2 = 0.f;
#pragma unroll
    for (int i = 0; i < 4; i++) { a += sh[i]; a2 += sh2[i]; }
    float mu  = a * (1.f / Dc);
    float var = a2 * (1.f / Dc) - mu * mu;
    float inv = rsqrtf(var + 1e-6f);
    int d = tid * 4;
    const float4 wv = *(const float4*)&w[d];
    const float4 bv = *(const float4*)&b[d];
    float y0 = (v.x - mu) * inv * wv.x + bv.x;
    float y1 = (v.y - mu) * inv * wv.y + bv.y;
    float y2 = (v.z - mu) * inv * wv.z + bv.z;
    float y3 = (v.w - mu) * inv * wv.w + bv.w;
    long idx = (long)row * Dc + d;
    *(float4*)&out[idx] = make_float4(y0, y1, y2, y3);
    uint32_t h0, l0, h1, l1;
    split2(y0, y1, h0, l0); split2(y2, y3, h1, l1);
    *(uint32_t*)&ohi[idx] = h0; *(uint32_t*)&ohi[idx + 2] = h1;
    *(uint32_t*)&olo[idx] = l0; *(uint32_t*)&olo[idx + 2] = l1;
}

// softmax over 1024, 256 threads x 4 contiguous; writes bf16 hi/lo
__global__ void softmax_k(const float* __restrict__ s,
                          bf16* __restrict__ shi, bf16* __restrict__ slo) {
    long row = blockIdx.x;
    const float* r = s + row * Sc;
    int tid = threadIdx.x;
    float4 v = *(const float4*)&r[tid * 4];
    float m = fmaxf(fmaxf(v.x, v.y), fmaxf(v.z, v.w));
    __shared__ float sh[8], sh2[8];
#pragma unroll
    for (int o = 16; o > 0; o >>= 1) m = fmaxf(m, __shfl_xor_sync(0xffffffffu, m, o));
    if ((tid & 31) == 0) sh[tid >> 5] = m;
    __syncthreads();
    m = sh[0];
#pragma unroll
    for (int i = 1; i < 8; i++) m = fmaxf(m, sh[i]);
    v.x = expf(v.x - m); v.y = expf(v.y - m);
    v.z = expf(v.z - m); v.w = expf(v.w - m);
    float sum = v.x + v.y + v.z + v.w;
#pragma unroll
    for (int o = 16; o > 0; o >>= 1) sum += __shfl_xor_sync(0xffffffffu, sum, o);
    if ((tid & 31) == 0) sh2[tid >> 5] = sum;
    __syncthreads();
    float tot = 0.f;
#pragma unroll
    for (int i = 0; i < 8; i++) tot += sh2[i];
    float inv = 1.f / tot;
    uint32_t h0, l0, h1, l1;
    split2(v.x * inv, v.y * inv, h0, l0);
    split2(v.z * inv, v.w * inv, h1, l1);
    long idx = row * Sc + tid * 4;
    *(uint32_t*)&shi[idx] = h0; *(uint32_t*)&shi[idx + 2] = h1;
    *(uint32_t*)&slo[idx] = l0; *(uint32_t*)&slo[idx + 2] = l1;
}

__global__ void zero_k() { if (threadIdx.x < Ec) g_cnt[threadIdx.x] = 0; }

__global__ void gate_k(const float* __restrict__ h, const float* __restrict__ gw) {
    int t = blockIdx.x * 4 + (threadIdx.x >> 5);
    int lid = threadIdx.x & 31;
    const float* hr = h + (long)t * Dc;
    float acc[Ec] = {};
    for (int d = lid; d < Dc; d += 32) {
        float hv = hr[d];
#pragma unroll
        for (int e = 0; e < Ec; e++) acc[e] += hv * gw[d * Ec + e];
    }
#pragma unroll
    for (int e = 0; e < Ec; e++)
#pragma unroll
        for (int o = 16; o > 0; o >>= 1)
            acc[e] += __shfl_xor_sync(0xffffffffu, acc[e], o);
    if (lid == 0) {
        int i0 = 0; float v0 = acc[0];
#pragma unroll
        for (int e = 1; e < Ec; e++) if (acc[e] > v0) { v0 = acc[e]; i0 = e; }
        int i1 = -1; float v1 = -3.4e38f;
#pragma unroll
        for (int e = 0; e < Ec; e++) if (e != i0 && acc[e] > v1) { v1 = acc[e]; i1 = e; }
        float g1 = 1.f / (1.f + expf(v0 - v1));
        g_topi[t * 2] = i0; g_topi[t * 2 + 1] = i1;
        g_gate[t * 2] = 1.f - g1; g_gate[t * 2 + 1] = g1;
        atomicAdd(&g_cnt[i0], 1);
        atomicAdd(&g_cnt[i1], 1);
    }
}

__global__ void offsets_k() {
    if (threadIdx.x == 0) {
        int o = 0;
        for (int e = 0; e < Ec; e++) { g_off[e] = o; g_cur[e] = o; o += g_cnt[e]; }
    }
}

__global__ void scatter_k() {
    int i = blockIdx.x * 256 + threadIdx.x;
    if (i >= 2 * Tc) return;
    int e = g_topi[i];
    int pos = atomicAdd(&g_cur[e], 1);
    g_tok[pos] = i;
}

__global__ void combine_k(float* __restrict__ x) {
    int i = blockIdx.x * 256 + threadIdx.x;
    int t = i >> 9;
    int d = i & 511;
    x[i] += g_gate[t * 2] * g_ybuf[(long)(t * 2) * Dc + d]
          + g_gate[t * 2 + 1] * g_ybuf[(long)(t * 2 + 1) * Dc + d];
}

// ================= host =====================================================
#define S128 (2 * (2 * 16384 + 2 * 128 * 128) + 1024)
#define S64  (2 * (2 * 16384 + 2 * 64 * 128) + 1024)

extern "C" void kernel_launch(void* const* d_in, const int* in_sizes, int n_in,
                              void* d_out, int out_size)
{
    const float* x      = (const float*)d_in[0];
    const float* ln1_w  = (const float*)d_in[1];
    const float* ln1_b  = (const float*)d_in[2];
    const float* wq     = (const float*)d_in[3];
    const float* wk     = (const float*)d_in[4];
    const float* wv     = (const float*)d_in[5];
    const float* wo     = (const float*)d_in[6];
    const float* bo     = (const float*)d_in[7];
    const float* ln2_w  = (const float*)d_in[8];
    const float* ln2_b  = (const float*)d_in[9];
    const float* gate_w = (const float*)d_in[10];
    const float* w1     = (const float*)d_in[11];
    const float* b1     = (const float*)d_in[12];
    const float* w2     = (const float*)d_in[13];
    const float* b2     = (const float*)d_in[14];
    float* out = (float*)d_out;

    float *ph, *pv, *ps, *pyb;
    bf16 *ph_hi, *ph_lo, *pq_hi, *pq_lo, *pk_hi, *pk_lo, *pvt_hi, *pvt_lo;
    bf16 *ps_hi, *ps_lo, *pao_hi, *pao_lo, *phm_hi, *phm_lo;
    bf16 *wqt_hi, *wqt_lo, *wkt_hi, *wkt_lo, *wvt_hi, *wvt_lo, *wot_hi, *wot_lo;
    bf16 *w1t_hi, *w1t_lo, *w2t_hi, *w2t_lo;
    cudaGetSymbolAddress((void**)&ph, g_h);
    cudaGetSymbolAddress((void**)&pv, g_v);
    cudaGetSymbolAddress((void**)&ps, g_s);
    cudaGetSymbolAddress((void**)&pyb, g_ybuf);
    cudaGetSymbolAddress((void**)&ph_hi, g_h_hi);  cudaGetSymbolAddress((void**)&ph_lo, g_h_lo);
    cudaGetSymbolAddress((void**)&pq_hi, g_q_hi);  cudaGetSymbolAddress((void**)&pq_lo, g_q_lo);
    cudaGetSymbolAddress((void**)&pk_hi, g_k_hi);  cudaGetSymbolAddress((void**)&pk_lo, g_k_lo);
    cudaGetSymbolAddress((void**)&pvt_hi, g_vt_hi); cudaGetSymbolAddress((void**)&pvt_lo, g_vt_lo);
    cudaGetSymbolAddress((void**)&ps_hi, g_s_hi);  cudaGetSymbolAddress((void**)&ps_lo, g_s_lo);
    cudaGetSymbolAddress((void**)&pao_hi, g_ao_hi); cudaGetSymbolAddress((void**)&pao_lo, g_ao_lo);
    cudaGetSymbolAddress((void**)&phm_hi, g_hm_hi); cudaGetSymbolAddress((void**)&phm_lo, g_hm_lo);
    cudaGetSymbolAddress((void**)&wqt_hi, g_wqt_hi); cudaGetSymbolAddress((void**)&wqt_lo, g_wqt_lo);
    cudaGetSymbolAddress((void**)&wkt_hi, g_wkt_hi); cudaGetSymbolAddress((void**)&wkt_lo, g_wkt_lo);
    cudaGetSymbolAddress((void**)&wvt_hi, g_wvt_hi); cudaGetSymbolAddress((void**)&wvt_lo, g_wvt_lo);
    cudaGetSymbolAddress((void**)&wot_hi, g_wot_hi); cudaGetSymbolAddress((void**)&wot_lo, g_wot_lo);
    cudaGetSymbolAddress((void**)&w1t_hi, g_w1t_hi); cudaGetSymbolAddress((void**)&w1t_lo, g_w1t_lo);
    cudaGetSymbolAddress((void**)&w2t_hi, g_w2t_hi); cudaGetSymbolAddress((void**)&w2t_lo, g_w2t_lo);

    cudaFuncSetAttribute(tgemm<128, 0, 0>, cudaFuncAttributeMaxDynamicSharedMemorySize, S128);
    cudaFuncSetAttribute(tgemm<128, 1, 0>, cudaFuncAttributeMaxDynamicSharedMemorySize, S128);
    cudaFuncSetAttribute(tgemm<128, 4, 0>, cudaFuncAttributeMaxDynamicSharedMemorySize, S128);
    cudaFuncSetAttribute(tgemm<64,  4, 0>, cudaFuncAttributeMaxDynamicSharedMemorySize, S64);
    cudaFuncSetAttribute(tgemm<128, 2, 1>, cudaFuncAttributeMaxDynamicSharedMemorySize, S128);
    cudaFuncSetAttribute(tgemm<128, 3, 2>, cudaFuncAttributeMaxDynamicSharedMemorySize, S128);

    copy_k<<<Tc * Dc / 256, 256>>>(x, out);

    dim3 tcb(32, 8);
    for (int l = 0; l < Lc; l++) {
        // weight transpose+split
        tconv<<<dim3(16, 16, 1), tcb>>>(wq + (long)l * Dc * Dc, wqt_hi, wqt_lo, Dc, Dc, 0, 0);
        tconv<<<dim3(16, 16, 1), tcb>>>(wk + (long)l * Dc * Dc, wkt_hi, wkt_lo, Dc, Dc, 0, 0);
        tconv<<<dim3(16, 16, 1), tcb>>>(wv + (long)l * Dc * Dc, wvt_hi, wvt_lo, Dc, Dc, 0, 0);
        tconv<<<dim3(16, 16, 1), tcb>>>(wo + (long)l * Dc * Dc, wot_hi, wot_lo, Dc, Dc, 0, 0);
        tconv<<<dim3(DHc / 32, Dc / 32, Ec), tcb>>>(
            w1 + (long)l * Ec * Dc * DHc, w1t_hi, w1t_lo, Dc, DHc,
            (long)Dc * DHc, (long)Dc * DHc);
        tconv<<<dim3(Dc / 32, DHc / 32, Ec), tcb>>>(
            w2 + (long)l * Ec * DHc * Dc, w2t_hi, w2t_lo, DHc, Dc,
            (long)DHc * Dc, (long)DHc * Dc);

        ln_k<<<Tc, 128>>>(out, ln1_w + l * Dc, ln1_b + l * Dc, ph, ph_hi, ph_lo);

        // QKV
        tgemm<128, 4, 0><<<dim3(4, 32, 1), 256, S128>>>(
            Dc, ph_hi, ph_lo, Dc, 0, 0, wqt_hi, wqt_lo, Dc, 0, 0,
            nullptr, pq_hi, pq_lo, Dc, 0, 0, 1, nullptr, 1.f, 0, 0);
        tgemm<128, 4, 0><<<dim3(4, 32, 1), 256, S128>>>(
            Dc, ph_hi, ph_lo, Dc, 0, 0, wkt_hi, wkt_lo, Dc, 0, 0,
            nullptr, pk_hi, pk_lo, Dc, 0, 0, 1, nullptr, 1.f, 0, 0);
        tgemm<128, 0, 0><<<dim3(4, 32, 1), 256, S128>>>(
            Dc, ph_hi, ph_lo, Dc, 0, 0, wvt_hi, wvt_lo, Dc, 0, 0,
            pv, nullptr, nullptr, Dc, 0, 0, 1, nullptr, 1.f, 0, 0);

        // v -> vt (bf16 split, [B][D][S])
        tconv<<<dim3(Dc / 32, Sc / 32, Bc), tcb>>>(
            pv, pvt_hi, pvt_lo, Sc, Dc, (long)Sc * Dc, (long)Dc * Sc);

        // scores = q @ k^T / 8
        tgemm<128, 0, 0><<<dim3(8, 8, Bc * Hc), 256, S128>>>(
            HEADc, pq_hi, pq_lo, Dc, (long)Sc * Dc, HEADc,
            pk_hi, pk_lo, Dc, (long)Sc * Dc, HEADc,
            ps, nullptr, nullptr, Sc, (long)Hc * Sc * Sc, (long)Sc * Sc,
            Hc, nullptr, 0.125f, 0, 0);

        softmax_k<<<Bc * Hc * Sc, 256>>>(ps, ps_hi, ps_lo);

        // attn_out = probs @ v   (BN=64)
        tgemm<64, 4, 0><<<dim3(1, 8, Bc * Hc), 256, S64>>>(
            Sc, ps_hi, ps_lo, Sc, (long)Hc * Sc * Sc, (long)Sc * Sc,
            pvt_hi, pvt_lo, Sc, (long)Dc * Sc, (long)HEADc * Sc,
            nullptr, pao_hi, pao_lo, Dc, (long)Sc * Dc, HEADc,
            Hc, nullptr, 1.f, 0, 0);

        // x = attn_out @ wo + bo + x
        tgemm<128, 1, 0><<<dim3(4, 32, 1), 256, S128>>>(
            Dc, pao_hi, pao_lo, Dc, 0, 0, wot_hi, wot_lo, Dc, 0, 0,
            out, nullptr, nullptr, Dc, 0, 0, 1, bo + l * Dc, 1.f, 0, 0);

        ln_k<<<Tc, 128>>>(out, ln2_w + l * Dc, ln2_b + l * Dc, ph, ph_hi, ph_lo);

        zero_k<<<1, 32>>>();
        gate_k<<<Tc / 4, 128>>>(ph, gate_w + (long)l * Dc * Ec);
        offsets_k<<<1, 1>>>();
        scatter_k<<<2 * Tc / 256, 256>>>();

        // grouped expert GEMMs
        tgemm<128, 2, 1><<<dim3(16, 64, Ec), 256, S128>>>(
            Dc, ph_hi, ph_lo, Dc, 0, 0, w1t_hi, w1t_lo, Dc, 0, 0,
            nullptr, phm_hi, phm_lo, DHc, 0, 0, 1,
            b1 + (long)l * Ec * DHc, 1.f, (long)Dc * DHc, DHc);
        tgemm<128, 3, 2><<<dim3(4, 64, Ec), 256, S128>>>(
            DHc, phm_hi, phm_lo, DHc, 0, 0, w2t_hi, w2t_lo, DHc, 0, 0,
            pyb, nullptr, nullptr, Dc, 0, 0, 1,
            b2 + (long)l * Ec * Dc, 1.f, (long)DHc * Dc, Dc);

        combine_k<<<Tc * Dc / 256, 256>>>(out);
    }
}

// round 5
// speedup vs baseline: 2.9134x; 1.1477x over previous
#include <cuda_runtime.h>
#include <cuda_bf16.h>
#include <math.h>
#include <stdint.h>

#define Tc 4096
#define Dc 512
#define Sc 1024
#define Bc 4
#define Hc 8
#define HEADc 64
#define Ec 8
#define DHc 2048
#define Lc 2

typedef __nv_bfloat16 bf16;

// ---------------- scratch (device globals) ---------------------------------
__device__ float g_h[Tc * Dc];
__device__ bf16  g_h_hi[Tc * Dc], g_h_lo[Tc * Dc];
__device__ bf16  g_q_hi[Tc * Dc], g_q_lo[Tc * Dc];
__device__ bf16  g_k_hi[Tc * Dc], g_k_lo[Tc * Dc];
__device__ float g_v[Tc * Dc];
__device__ bf16  g_vt_hi[Tc * Dc], g_vt_lo[Tc * Dc];     // [B][D][S]
__device__ bf16  g_ao_hi[Tc * Dc], g_ao_lo[Tc * Dc];
__device__ bf16  g_hm_hi[(size_t)2 * Tc * DHc], g_hm_lo[(size_t)2 * Tc * DHc];
__device__ float g_ybuf[(size_t)2 * Tc * Dc];
__device__ bf16  g_wqt_hi[Dc * Dc], g_wqt_lo[Dc * Dc];
__device__ bf16  g_wkt_hi[Dc * Dc], g_wkt_lo[Dc * Dc];
__device__ bf16  g_wvt_hi[Dc * Dc], g_wvt_lo[Dc * Dc];
__device__ bf16  g_wot_hi[Dc * Dc], g_wot_lo[Dc * Dc];
__device__ bf16  g_w1t_hi[(size_t)Ec * Dc * DHc], g_w1t_lo[(size_t)Ec * Dc * DHc];
__device__ bf16  g_w2t_hi[(size_t)Ec * Dc * DHc], g_w2t_lo[(size_t)Ec * Dc * DHc];
__device__ float g_gate[Tc * 2];
__device__ int   g_topi[Tc * 2];
__device__ int   g_cnt[Ec], g_cur[Ec], g_off[Ec];
__device__ int   g_tok[2 * Tc];

// ================= low-level helpers ========================================
__device__ __forceinline__ uint32_t smem_u32(const void* p) {
    uint32_t a;
    asm("{ .reg .u64 t; cvta.to.shared.u64 t, %1; cvt.u32.u64 %0, t; }"
        : "=r"(a) : "l"(p));
    return a;
}
#define SWZ(o) ((o) ^ (((o) >> 3) & 0x70))
#define CP16(dst, src, sz) \
    asm volatile("cp.async.cg.shared.global [%0], [%1], 16, %2;" \
                 :: "r"(dst), "l"(src), "r"(sz) : "memory")
#define CP_COMMIT() asm volatile("cp.async.commit_group;" ::: "memory")

__device__ __forceinline__ void ldsm4(uint32_t* r, uint32_t addr) {
    asm volatile("ldmatrix.sync.aligned.m8n8.x4.shared.b16 {%0,%1,%2,%3}, [%4];"
                 : "=r"(r[0]), "=r"(r[1]), "=r"(r[2]), "=r"(r[3]) : "r"(addr));
}
__device__ __forceinline__ void mma_bf16(float* d, const uint32_t* a,
                                         uint32_t b0, uint32_t b1) {
    asm volatile(
        "mma.sync.aligned.m16n8k16.row.col.f32.bf16.bf16.f32 "
        "{%0,%1,%2,%3}, {%4,%5,%6,%7}, {%8,%9}, {%0,%1,%2,%3};"
        : "+f"(d[0]), "+f"(d[1]), "+f"(d[2]), "+f"(d[3])
        : "r"(a[0]), "r"(a[1]), "r"(a[2]), "r"(a[3]), "r"(b0), "r"(b1));
}
__device__ __forceinline__ void split2(float x0, float x1, uint32_t& hi, uint32_t& lo) {
    bf16 h0 = __float2bfloat16(x0);
    bf16 h1 = __float2bfloat16(x1);
    bf16 l0 = __float2bfloat16(x0 - __bfloat162float(h0));
    bf16 l1 = __float2bfloat16(x1 - __bfloat162float(h1));
    hi = (uint32_t)__bfloat16_as_ushort(h0) | ((uint32_t)__bfloat16_as_ushort(h1) << 16);
    lo = (uint32_t)__bfloat16_as_ushort(l0) | ((uint32_t)__bfloat16_as_ushort(l1) << 16);
}

// ================= pipelined tensor GEMM ====================================
// A: [*,K] K-major bf16 hi/lo.  B: [N,K] K-major bf16 hi/lo.  128xBN tile.
// EPI: 0 fp32*alpha; 1 fp32+bias+C; 2 gelu(+bias)->bf16pair grouped;
//      3 +bias->scatter fp32; 4 bf16 pair plain
// AMODE: 0 direct; 1 gather rows via g_tok>>1; 2 grouped rows off+m
template <int BN, int EPI, int AMODE>
__global__ void __launch_bounds__(256, 1) tgemm(
    int K,
    const bf16* __restrict__ Ahi, const bf16* __restrict__ Alo,
    int lda, long sa1, long sa2,
    const bf16* __restrict__ Bhi, const bf16* __restrict__ Blo,
    int ldb, long sb1, long sb2,
    float* __restrict__ C, bf16* __restrict__ Chi, bf16* __restrict__ Clo,
    int ldc, long sc1, long sc2, int zh,
    const float* __restrict__ bias, float alpha, long wstride, long bstride)
{
    constexpr int NWN = BN / 32, NWM = 8 / NWN, MT = 8 / NWM;
    constexpr uint32_t ASZ = 16384u, BSZ = (uint32_t)BN * 128u;
    constexpr uint32_t STG = 2 * ASZ + 2 * BSZ;
    extern __shared__ char dsm[];
    __shared__ int stok_s[128];
    uint32_t sbb = smem_u32(dsm);
    uint32_t tb = (sbb + 1023) & ~1023u;
    int tid = threadIdx.x, wid = tid >> 5, lid = tid & 31;

    int cnt = 0, off = 0;
    if (AMODE != 0) {
        int e = blockIdx.z;
        cnt = g_cnt[e]; off = g_off[e];
        if ((int)blockIdx.y * 128 >= cnt) return;
        Bhi += (long)e * wstride; Blo += (long)e * wstride;
        bias += (long)e * bstride;
    } else {
        int z = blockIdx.z, zb = z / zh, zhh = z - zb * zh;
        Ahi += zb * sa1 + zhh * sa2; Alo += zb * sa1 + zhh * sa2;
        Bhi += zb * sb1 + zhh * sb2; Blo += zb * sb1 + zhh * sb2;
        if (EPI == 2 || EPI == 4) { Chi += zb * sc1 + zhh * sc2; Clo += zb * sc1 + zhh * sc2; }
        else                       { C   += zb * sc1 + zhh * sc2; }
    }
    int m0 = blockIdx.y * 128, n0 = blockIdx.x * BN;

    if (AMODE == 1 && tid < 128) {
        int i = m0 + tid;
        stok_s[tid] = (i < cnt) ? (g_tok[off + i] >> 1) : -1;
    }
    if (AMODE == 2 && tid < 128) {
        int i = m0 + tid;
        stok_s[tid] = (i < cnt) ? g_tok[off + i] : -1;
    }
    if (AMODE != 0) __syncthreads();

    auto load_stage = [&](int c, int st) {
        uint32_t base = tb + (uint32_t)st * STG;
        int k0 = c << 6;
#pragma unroll
        for (int i = 0; i < 4; i++) {
            int idx = tid + (i << 8);
            int row = idx >> 3, c16 = idx & 7;
            uint32_t d = SWZ((uint32_t)(row * 128 + c16 * 16));
            long so; uint32_t sz = 16;
            if (AMODE == 0) so = (long)(m0 + row) * lda + k0 + c16 * 8;
            else if (AMODE == 1) {
                int tk = stok_s[row];
                if (tk < 0) { sz = 0; tk = 0; }
                so = (long)tk * lda + k0 + c16 * 8;
            } else {
                if (stok_s[row] < 0) { sz = 0; so = 0; }
                else so = (long)(off + m0 + row) * lda + k0 + c16 * 8;
            }
            CP16(base + d, Ahi + so, sz);
            CP16(base + ASZ + d, Alo + so, sz);
        }
#pragma unroll
        for (int i = 0; i < BN / 32; i++) {
            int idx = tid + (i << 8);
            int row = idx >> 3, c16 = idx & 7;
            uint32_t d = SWZ((uint32_t)(row * 128 + c16 * 16));
            long so = (long)(n0 + row) * ldb + k0 + c16 * 8;
            CP16(base + 2 * ASZ + d, Bhi + so, 16);
            CP16(base + 2 * ASZ + BSZ + d, Blo + so, 16);
        }
        CP_COMMIT();
    };

    int wm = (wid / NWN) * (MT * 16), wn = (wid % NWN) * 32;
    int a_row = wm + (lid & 15), a_cb = (lid >> 4) << 4;
    int b_row = wn + ((lid >> 4) << 3) + (lid & 7), b_cb = ((lid >> 3) & 1) << 4;
    float acc[MT][4][4] = {};

    int nch = K >> 6;
    load_stage(0, 0);
    for (int c = 0; c < nch; c++) {
        if (c + 1 < nch) {
            load_stage(c + 1, (c + 1) & 1);
            asm volatile("cp.async.wait_group 1;" ::: "memory");
        } else {
            asm volatile("cp.async.wait_group 0;" ::: "memory");
        }
        __syncthreads();
        uint32_t base = tb + (uint32_t)(c & 1) * STG;
#pragma unroll
        for (int ks = 0; ks < 4; ks++) {
            int kb = ks * 32;
            uint32_t aH[MT][4], aL[MT][4], bH[2][4], bL[2][4];
#pragma unroll
            for (int mt = 0; mt < MT; mt++) {
                uint32_t o = SWZ((uint32_t)((a_row + mt * 16) * 128 + kb + a_cb));
                ldsm4(aH[mt], base + o);
                ldsm4(aL[mt], base + ASZ + o);
            }
#pragma unroll
            for (int g = 0; g < 2; g++) {
                uint32_t o = SWZ((uint32_t)((b_row + g * 16) * 128 + kb + b_cb));
                ldsm4(bH[g], base + 2 * ASZ + o);
                ldsm4(bL[g], base + 2 * ASZ + BSZ + o);
            }
#pragma unroll
            for (int mt = 0; mt < MT; mt++)
#pragma unroll
                for (int nt = 0; nt < 4; nt++) {
                    int g = nt >> 1, pr = (nt & 1) * 2;
                    mma_bf16(acc[mt][nt], aH[mt], bH[g][pr], bH[g][pr + 1]);
                    mma_bf16(acc[mt][nt], aH[mt], bL[g][pr], bL[g][pr + 1]);
                    mma_bf16(acc[mt][nt], aL[mt], bH[g][pr], bH[g][pr + 1]);
                }
        }
        __syncthreads();
    }

    // ---- register epilogue ----
    int lr = lid >> 2, lc = (lid & 3) * 2;
#pragma unroll
    for (int mt = 0; mt < MT; mt++) {
#pragma unroll
        for (int half = 0; half < 2; half++) {
            int lrow = wm + mt * 16 + lr + half * 8;
            int grow = m0 + lrow;
#pragma unroll
            for (int nt = 0; nt < 4; nt++) {
                float v0 = acc[mt][nt][half * 2 + 0];
                float v1 = acc[mt][nt][half * 2 + 1];
                int gc = n0 + wn + nt * 8 + lc;
                if (EPI == 0) {
                    *(float2*)&C[(long)grow * ldc + gc] = make_float2(v0 * alpha, v1 * alpha);
                } else if (EPI == 1) {
                    long idx = (long)grow * ldc + gc;
                    float2 old = *(const float2*)&C[idx];
                    *(float2*)&C[idx] = make_float2(v0 + bias[gc] + old.x,
                                                    v1 + bias[gc + 1] + old.y);
                } else if (EPI == 2) {
                    if (stok_s[lrow] >= 0) {
                        float t0 = v0 + bias[gc], t1 = v1 + bias[gc + 1];
                        float o0 = 0.5f * t0 * (1.f + erff(t0 * 0.70710678118654752f));
                        float o1 = 0.5f * t1 * (1.f + erff(t1 * 0.70710678118654752f));
                        uint32_t hi, lo; split2(o0, o1, hi, lo);
                        long idx = (long)(off + grow) * ldc + gc;
                        *(uint32_t*)&Chi[idx] = hi;
                        *(uint32_t*)&Clo[idx] = lo;
                    }
                } else if (EPI == 3) {
                    int ent = stok_s[lrow];
                    if (ent >= 0) {
                        *(float2*)&C[(long)ent * ldc + gc] =
                            make_float2(v0 + bias[gc], v1 + bias[gc + 1]);
                    }
                } else {  // EPI == 4
                    uint32_t hi, lo; split2(v0, v1, hi, lo);
                    long idx = (long)grow * ldc + gc;
                    *(uint32_t*)&Chi[idx] = hi;
                    *(uint32_t*)&Clo[idx] = lo;
                }
            }
        }
    }
}

// ================= fused flash attention ====================================
// grid: (S/128, B*H). 256 threads = 8 warps; warp w owns q rows w*16..w*16+15.
// Q,K: [B,S,D] bf16 hi/lo (head slice). V^T: [B,D,S] bf16 hi/lo.
// Out: ao hi/lo [B,S,D].
#define FL_QH 0
#define FL_QL 16384
#define FL_KST 32768
#define FL_VST 98304
#define FL_SMEM 163840
__global__ void __launch_bounds__(256, 1) flash_k(
    const bf16* __restrict__ Qhi, const bf16* __restrict__ Qlo,
    const bf16* __restrict__ Khi, const bf16* __restrict__ Klo,
    const bf16* __restrict__ Vhi, const bf16* __restrict__ Vlo,
    bf16* __restrict__ Ohi, bf16* __restrict__ Olo)
{
    extern __shared__ char dsm[];
    uint32_t sb = smem_u32(dsm);
    int tid = threadIdx.x, wid = tid >> 5, lid = tid & 31;
    int bh = blockIdx.y, b = bh >> 3, h = bh & 7;
    int q0 = blockIdx.x * 128;

    long qbase = (long)b * Sc * Dc + (long)q0 * Dc + h * HEADc;   // + row*Dc
    long kb0   = (long)b * Sc * Dc + h * HEADc;                    // + (c*128+row)*Dc
    long vbase = (long)b * Dc * Sc + (long)h * HEADc * Sc;         // + d*Sc + col

    // ---- loaders ----
    auto load_q = [&]() {
#pragma unroll
        for (int i = 0; i < 4; i++) {
            int idx = tid + (i << 8);
            int row = idx >> 3, c16 = idx & 7;
            uint32_t d = SWZ((uint32_t)(row * 128 + c16 * 16));
            long so = qbase + (long)row * Dc + c16 * 8;
            CP16(sb + FL_QH + d, Qhi + so, 16);
            CP16(sb + FL_QL + d, Qlo + so, 16);
        }
    };
    auto load_kv = [&](int c, int st) {
        uint32_t kstg = sb + FL_KST + (uint32_t)st * 32768;
        uint32_t vstg = sb + FL_VST + (uint32_t)st * 32768;
#pragma unroll
        for (int i = 0; i < 4; i++) {
            int idx = tid + (i << 8);
            int row = idx >> 3, c16 = idx & 7;
            uint32_t d = SWZ((uint32_t)(row * 128 + c16 * 16));
            long so = kb0 + (long)(c * 128 + row) * Dc + c16 * 8;
            CP16(kstg + d, Khi + so, 16);
            CP16(kstg + 16384 + d, Klo + so, 16);
        }
#pragma unroll
        for (int i = 0; i < 4; i++) {
            int idx = tid + (i << 8);
            int t = idx >> 9, r = (idx >> 3) & 63, c16 = idx & 7;
            uint32_t d = (uint32_t)t * 8192 + SWZ((uint32_t)(r * 128 + c16 * 16));
            long so = vbase + (long)r * Sc + c * 128 + t * 64 + c16 * 8;
            CP16(vstg + d, Vhi + so, 16);
            CP16(vstg + 16384 + d, Vlo + so, 16);
        }
        CP_COMMIT();
    };

    load_q(); load_kv(0, 0);
    CP_COMMIT();          // group 0 = Q + K0 + V0 ... (load_kv already committed)
    load_kv(1, 1);

    int wm = wid * 16;
    int lr = lid >> 2, lc = (lid & 3) * 2;
    int a_row = wm + (lid & 15), a_cb = (lid >> 4) << 4;
    int b_row8 = ((lid >> 4) << 3) + (lid & 7);
    int b_cb = ((lid >> 3) & 1) << 4;

    uint32_t qh[4][4], ql[4][4];
    float m0r = -1e30f, m1r = -1e30f, l0r = 0.f, l1r = 0.f;
    float acc_o[8][4] = {};

    for (int c = 0; c < 8; c++) {
        if (c < 7) asm volatile("cp.async.wait_group 1;" ::: "memory");
        else       asm volatile("cp.async.wait_group 0;" ::: "memory");
        __syncthreads();

        if (c == 0) {
#pragma unroll
            for (int ks = 0; ks < 4; ks++) {
                uint32_t o = SWZ((uint32_t)(a_row * 128 + ks * 32 + a_cb));
                ldsm4(qh[ks], sb + FL_QH + o);
                ldsm4(ql[ks], sb + FL_QL + o);
            }
        }
        uint32_t kstg = sb + FL_KST + (uint32_t)(c & 1) * 32768;
        uint32_t vstg = sb + FL_VST + (uint32_t)(c & 1) * 32768;

        // ---- S = Q K^T (fp32, 3-way split) ----
        float s_acc[16][4] = {};
#pragma unroll
        for (int ks = 0; ks < 4; ks++) {
            int kb = ks * 32;
            uint32_t kh[8][4], kl[8][4];
#pragma unroll
            for (int g = 0; g < 8; g++) {
                uint32_t o = SWZ((uint32_t)((g * 16 + b_row8) * 128 + kb + b_cb));
                ldsm4(kh[g], kstg + o);
                ldsm4(kl[g], kstg + 16384 + o);
            }
#pragma unroll
            for (int nt = 0; nt < 16; nt++) {
                int g = nt >> 1, pr = (nt & 1) * 2;
                mma_bf16(s_acc[nt], qh[ks], kh[g][pr], kh[g][pr + 1]);
                mma_bf16(s_acc[nt], qh[ks], kl[g][pr], kl[g][pr + 1]);
                mma_bf16(s_acc[nt], ql[ks], kh[g][pr], kh[g][pr + 1]);
            }
        }

        // ---- online softmax (scale 1/8) ----
        float t0 = -1e30f, t1 = -1e30f;
#pragma unroll
        for (int nt = 0; nt < 16; nt++) {
#pragma unroll
            for (int j = 0; j < 4; j++) s_acc[nt][j] *= 0.125f;
            t0 = fmaxf(t0, fmaxf(s_acc[nt][0], s_acc[nt][1]));
            t1 = fmaxf(t1, fmaxf(s_acc[nt][2], s_acc[nt][3]));
        }
#pragma unroll
        for (int o = 1; o <= 2; o <<= 1) {
            t0 = fmaxf(t0, __shfl_xor_sync(0xffffffffu, t0, o));
            t1 = fmaxf(t1, __shfl_xor_sync(0xffffffffu, t1, o));
        }
        float mn0 = fmaxf(m0r, t0), mn1 = fmaxf(m1r, t1);
        float cor0 = expf(m0r - mn0), cor1 = expf(m1r - mn1);
        float rs0 = 0.f, rs1 = 0.f;
#pragma unroll
        for (int nt = 0; nt < 16; nt++) {
            s_acc[nt][0] = expf(s_acc[nt][0] - mn0);
            s_acc[nt][1] = expf(s_acc[nt][1] - mn0);
            s_acc[nt][2] = expf(s_acc[nt][2] - mn1);
            s_acc[nt][3] = expf(s_acc[nt][3] - mn1);
            rs0 += s_acc[nt][0] + s_acc[nt][1];
            rs1 += s_acc[nt][2] + s_acc[nt][3];
        }
#pragma unroll
        for (int o = 1; o <= 2; o <<= 1) {
            rs0 += __shfl_xor_sync(0xffffffffu, rs0, o);
            rs1 += __shfl_xor_sync(0xffffffffu, rs1, o);
        }
        l0r = l0r * cor0 + rs0; l1r = l1r * cor1 + rs1;
        m0r = mn0; m1r = mn1;
#pragma unroll
        for (int nt = 0; nt < 8; nt++) {
            acc_o[nt][0] *= cor0; acc_o[nt][1] *= cor0;
            acc_o[nt][2] *= cor1; acc_o[nt][3] *= cor1;
        }

        // ---- O += P V (3-way split, P from registers) ----
#pragma unroll
        for (int kt = 0; kt < 8; kt++) {
            uint32_t ah[4], al[4];
            split2(s_acc[2 * kt][0],     s_acc[2 * kt][1],     ah[0], al[0]);
            split2(s_acc[2 * kt][2],     s_acc[2 * kt][3],     ah[1], al[1]);
            split2(s_acc[2 * kt + 1][0], s_acc[2 * kt + 1][1], ah[2], al[2]);
            split2(s_acc[2 * kt + 1][2], s_acc[2 * kt + 1][3], ah[3], al[3]);
            uint32_t sub = (uint32_t)(kt >> 2) * 8192;
            uint32_t cb = (uint32_t)((kt & 3) * 32) + b_cb;
            uint32_t vh[4][4], vl[4][4];
#pragma unroll
            for (int g = 0; g < 4; g++) {
                uint32_t o = sub + SWZ((uint32_t)((g * 16 + b_row8) * 128 + cb));
                ldsm4(vh[g], vstg + o);
                ldsm4(vl[g], vstg + 16384 + o);
            }
#pragma unroll
            for (int nt = 0; nt < 8; nt++) {
                int g = nt >> 1, pr = (nt & 1) * 2;
                mma_bf16(acc_o[nt], ah, vh[g][pr], vh[g][pr + 1]);
                mma_bf16(acc_o[nt], ah, vl[g][pr], vl[g][pr + 1]);
                mma_bf16(acc_o[nt], al, vh[g][pr], vh[g][pr + 1]);
            }
        }
        __syncthreads();
        if (c + 2 < 8) load_kv(c + 2, c & 1);
    }

    // ---- epilogue: out = acc_o / l ----
    float inv0 = 1.f / l0r, inv1 = 1.f / l1r;
    long r0g = qbase + (long)(wm + lr) * Dc;
    long r1g = qbase + (long)(wm + lr + 8) * Dc;
#pragma unroll
    for (int nt = 0; nt < 8; nt++) {
        int gc = nt * 8 + lc;
        uint32_t hi, lo;
        split2(acc_o[nt][0] * inv0, acc_o[nt][1] * inv0, hi, lo);
        *(uint32_t*)&Ohi[r0g + gc] = hi;
        *(uint32_t*)&Olo[r0g + gc] = lo;
        split2(acc_o[nt][2] * inv1, acc_o[nt][3] * inv1, hi, lo);
        *(uint32_t*)&Ohi[r1g + gc] = hi;
        *(uint32_t*)&Olo[r1g + gc] = lo;
    }
}

// ================= transpose + split convert ================================
__global__ void tconv(const float* __restrict__ in, bf16* __restrict__ ohi,
                      bf16* __restrict__ olo, int R, int Ccol, long sin, long sout)
{
    __shared__ float t[32][33];
    long ib = (long)blockIdx.z * sin, ob = (long)blockIdx.z * sout;
    int c0 = blockIdx.x * 32, r0 = blockIdx.y * 32;
    int tx = threadIdx.x, ty = threadIdx.y;
#pragma unroll
    for (int j = 0; j < 4; j++)
        t[ty + j * 8][tx] = in[ib + (long)(r0 + ty + j * 8) * Ccol + c0 + tx];
    __syncthreads();
#pragma unroll
    for (int j = 0; j < 4; j++) {
        float v = t[tx][ty + j * 8];
        bf16 h = __float2bfloat16(v);
        long o = ob + (long)(c0 + ty + j * 8) * R + r0 + tx;
        ohi[o] = h;
        olo[o] = __float2bfloat16(v - __bfloat162float(h));
    }
}

// ================= elementwise kernels ======================================
__global__ void copy_k(const float* __restrict__ a, float* __restrict__ o) {
    long i = (long)blockIdx.x * 256 + threadIdx.x;
    o[i] = a[i];
}

__global__ void ln_k(const float* __restrict__ x, const float* __restrict__ w,
                     const float* __restrict__ b, float* __restrict__ out,
                     bf16* __restrict__ ohi, bf16* __restrict__ olo) {
    int row = blockIdx.x;
    const float* xr = x + (long)row * Dc;
    int tid = threadIdx.x;
    float4 v = *(const float4*)&xr[tid * 4];
    float s = v.x + v.y + v.z + v.w;
    float s2 = v.x * v.x + v.y * v.y + v.z * v.z + v.w * v.w;
    __shared__ float sh[4], sh2[4];
#pragma unroll
    for (int o = 16; o > 0; o >>= 1) {
        s  += __shfl_xor_sync(0xffffffffu, s, o);
        s2 += __shfl_xor_sync(0xffffffffu, s2, o);
    }
    if ((tid & 31) == 0) { sh[tid >> 5] = s; sh2[tid >> 5] = s2; }
    __syncthreads();
    float a = 0.f, a2 = 0.f;
#pragma unroll
    for (int i = 0; i < 4; i++) { a += sh[i]; a2 += sh2[i]; }
    float mu  = a * (1.f / Dc);
    float var = a2 * (1.f / Dc) - mu * mu;
    float inv = rsqrtf(var + 1e-6f);
    int d = tid * 4;
    const float4 wv = *(const float4*)&w[d];
    const float4 bv = *(const float4*)&b[d];
    float y0 = (v.x - mu) * inv * wv.x + bv.x;
    float y1 = (v.y - mu) * inv * wv.y + bv.y;
    float y2 = (v.z - mu) * inv * wv.z + bv.z;
    float y3 = (v.w - mu) * inv * wv.w + bv.w;
    long idx = (long)row * Dc + d;
    *(float4*)&out[idx] = make_float4(y0, y1, y2, y3);
    uint32_t h0, l0, h1, l1;
    split2(y0, y1, h0, l0); split2(y2, y3, h1, l1);
    *(uint32_t*)&ohi[idx] = h0; *(uint32_t*)&ohi[idx + 2] = h1;
    *(uint32_t*)&olo[idx] = l0; *(uint32_t*)&olo[idx + 2] = l1;
}

__global__ void zero_k() { if (threadIdx.x < Ec) g_cnt[threadIdx.x] = 0; }

__global__ void gate_k(const float* __restrict__ h, const float* __restrict__ gw) {
    int t = blockIdx.x * 4 + (threadIdx.x >> 5);
    int lid = threadIdx.x & 31;
    const float* hr = h + (long)t * Dc;
    float acc[Ec] = {};
    for (int d = lid; d < Dc; d += 32) {
        float hv = hr[d];
#pragma unroll
        for (int e = 0; e < Ec; e++) acc[e] += hv * gw[d * Ec + e];
    }
#pragma unroll
    for (int e = 0; e < Ec; e++)
#pragma unroll
        for (int o = 16; o > 0; o >>= 1)
            acc[e] += __shfl_xor_sync(0xffffffffu, acc[e], o);
    if (lid == 0) {
        int i0 = 0; float v0 = acc[0];
#pragma unroll
        for (int e = 1; e < Ec; e++) if (acc[e] > v0) { v0 = acc[e]; i0 = e; }
        int i1 = -1; float v1 = -3.4e38f;
#pragma unroll
        for (int e = 0; e < Ec; e++) if (e != i0 && acc[e] > v1) { v1 = acc[e]; i1 = e; }
        float g1 = 1.f / (1.f + expf(v0 - v1));
        g_topi[t * 2] = i0; g_topi[t * 2 + 1] = i1;
        g_gate[t * 2] = 1.f - g1; g_gate[t * 2 + 1] = g1;
        atomicAdd(&g_cnt[i0], 1);
        atomicAdd(&g_cnt[i1], 1);
    }
}

__global__ void offsets_k() {
    if (threadIdx.x == 0) {
        int o = 0;
        for (int e = 0; e < Ec; e++) { g_off[e] = o; g_cur[e] = o; o += g_cnt[e]; }
    }
}

__global__ void scatter_k() {
    int i = blockIdx.x * 256 + threadIdx.x;
    if (i >= 2 * Tc) return;
    int e = g_topi[i];
    int pos = atomicAdd(&g_cur[e], 1);
    g_tok[pos] = i;
}

__global__ void combine_k(float* __restrict__ x) {
    int i = blockIdx.x * 256 + threadIdx.x;
    int t = i >> 9;
    int d = i & 511;
    x[i] += g_gate[t * 2] * g_ybuf[(long)(t * 2) * Dc + d]
          + g_gate[t * 2 + 1] * g_ybuf[(long)(t * 2 + 1) * Dc + d];
}

// ================= host =====================================================
#define S128 (2 * (2 * 16384 + 2 * 128 * 128) + 1024)

extern "C" void kernel_launch(void* const* d_in, const int* in_sizes, int n_in,
                              void* d_out, int out_size)
{
    const float* x      = (const float*)d_in[0];
    const float* ln1_w  = (const float*)d_in[1];
    const float* ln1_b  = (const float*)d_in[2];
    const float* wq     = (const float*)d_in[3];
    const float* wk     = (const float*)d_in[4];
    const float* wv     = (const float*)d_in[5];
    const float* wo     = (const float*)d_in[6];
    const float* bo     = (const float*)d_in[7];
    const float* ln2_w  = (const float*)d_in[8];
    const float* ln2_b  = (const float*)d_in[9];
    const float* gate_w = (const float*)d_in[10];
    const float* w1     = (const float*)d_in[11];
    const float* b1     = (const float*)d_in[12];
    const float* w2     = (const float*)d_in[13];
    const float* b2     = (const float*)d_in[14];
    float* out = (float*)d_out;

    float *ph, *pv, *pyb;
    bf16 *ph_hi, *ph_lo, *pq_hi, *pq_lo, *pk_hi, *pk_lo, *pvt_hi, *pvt_lo;
    bf16 *pao_hi, *pao_lo, *phm_hi, *phm_lo;
    bf16 *wqt_hi, *wqt_lo, *wkt_hi, *wkt_lo, *wvt_hi, *wvt_lo, *wot_hi, *wot_lo;
    bf16 *w1t_hi, *w1t_lo, *w2t_hi, *w2t_lo;
    cudaGetSymbolAddress((void**)&ph, g_h);
    cudaGetSymbolAddress((void**)&pv, g_v);
    cudaGetSymbolAddress((void**)&pyb, g_ybuf);
    cudaGetSymbolAddress((void**)&ph_hi, g_h_hi);  cudaGetSymbolAddress((void**)&ph_lo, g_h_lo);
    cudaGetSymbolAddress((void**)&pq_hi, g_q_hi);  cudaGetSymbolAddress((void**)&pq_lo, g_q_lo);
    cudaGetSymbolAddress((void**)&pk_hi, g_k_hi);  cudaGetSymbolAddress((void**)&pk_lo, g_k_lo);
    cudaGetSymbolAddress((void**)&pvt_hi, g_vt_hi); cudaGetSymbolAddress((void**)&pvt_lo, g_vt_lo);
    cudaGetSymbolAddress((void**)&pao_hi, g_ao_hi); cudaGetSymbolAddress((void**)&pao_lo, g_ao_lo);
    cudaGetSymbolAddress((void**)&phm_hi, g_hm_hi); cudaGetSymbolAddress((void**)&phm_lo, g_hm_lo);
    cudaGetSymbolAddress((void**)&wqt_hi, g_wqt_hi); cudaGetSymbolAddress((void**)&wqt_lo, g_wqt_lo);
    cudaGetSymbolAddress((void**)&wkt_hi, g_wkt_hi); cudaGetSymbolAddress((void**)&wkt_lo, g_wkt_lo);
    cudaGetSymbolAddress((void**)&wvt_hi, g_wvt_hi); cudaGetSymbolAddress((void**)&wvt_lo, g_wvt_lo);
    cudaGetSymbolAddress((void**)&wot_hi, g_wot_hi); cudaGetSymbolAddress((void**)&wot_lo, g_wot_lo);
    cudaGetSymbolAddress((void**)&w1t_hi, g_w1t_hi); cudaGetSymbolAddress((void**)&w1t_lo, g_w1t_lo);
    cudaGetSymbolAddress((void**)&w2t_hi, g_w2t_hi); cudaGetSymbolAddress((void**)&w2t_lo, g_w2t_lo);

    cudaFuncSetAttribute(tgemm<128, 0, 0>, cudaFuncAttributeMaxDynamicSharedMemorySize, S128);
    cudaFuncSetAttribute(tgemm<128, 1, 0>, cudaFuncAttributeMaxDynamicSharedMemorySize, S128);
    cudaFuncSetAttribute(tgemm<128, 4, 0>, cudaFuncAttributeMaxDynamicSharedMemorySize, S128);
    cudaFuncSetAttribute(tgemm<128, 2, 1>, cudaFuncAttributeMaxDynamicSharedMemorySize, S128);
    cudaFuncSetAttribute(tgemm<128, 3, 2>, cudaFuncAttributeMaxDynamicSharedMemorySize, S128);
    cudaFuncSetAttribute(flash_k, cudaFuncAttributeMaxDynamicSharedMemorySize, FL_SMEM);

    copy_k<<<Tc * Dc / 256, 256>>>(x, out);

    dim3 tcb(32, 8);
    for (int l = 0; l < Lc; l++) {
        tconv<<<dim3(16, 16, 1), tcb>>>(wq + (long)l * Dc * Dc, wqt_hi, wqt_lo, Dc, Dc, 0, 0);
        tconv<<<dim3(16, 16, 1), tcb>>>(wk + (long)l * Dc * Dc, wkt_hi, wkt_lo, Dc, Dc, 0, 0);
        tconv<<<dim3(16, 16, 1), tcb>>>(wv + (long)l * Dc * Dc, wvt_hi, wvt_lo, Dc, Dc, 0, 0);
        tconv<<<dim3(16, 16, 1), tcb>>>(wo + (long)l * Dc * Dc, wot_hi, wot_lo, Dc, Dc, 0, 0);
        tconv<<<dim3(DHc / 32, Dc / 32, Ec), tcb>>>(
            w1 + (long)l * Ec * Dc * DHc, w1t_hi, w1t_lo, Dc, DHc,
            (long)Dc * DHc, (long)Dc * DHc);
        tconv<<<dim3(Dc / 32, DHc / 32, Ec), tcb>>>(
            w2 + (long)l * Ec * DHc * Dc, w2t_hi, w2t_lo, DHc, Dc,
            (long)DHc * Dc, (long)DHc * Dc);

        ln_k<<<Tc, 128>>>(out, ln1_w + l * Dc, ln1_b + l * Dc, ph, ph_hi, ph_lo);

        // QKV
        tgemm<128, 4, 0><<<dim3(4, 32, 1), 256, S128>>>(
            Dc, ph_hi, ph_lo, Dc, 0, 0, wqt_hi, wqt_lo, Dc, 0, 0,
            nullptr, pq_hi, pq_lo, Dc, 0, 0, 1, nullptr, 1.f, 0, 0);
        tgemm<128, 4, 0><<<dim3(4, 32, 1), 256, S128>>>(
            Dc, ph_hi, ph_lo, Dc, 0, 0, wkt_hi, wkt_lo, Dc, 0, 0,
            nullptr, pk_hi, pk_lo, Dc, 0, 0, 1, nullptr, 1.f, 0, 0);
        tgemm<128, 0, 0><<<dim3(4, 32, 1), 256, S128>>>(
            Dc, ph_hi, ph_lo, Dc, 0, 0, wvt_hi, wvt_lo, Dc, 0, 0,
            pv, nullptr, nullptr, Dc, 0, 0, 1, nullptr, 1.f, 0, 0);

        // v -> vt (bf16 split, [B][D][S])
        tconv<<<dim3(Dc / 32, Sc / 32, Bc), tcb>>>(
            pv, pvt_hi, pvt_lo, Sc, Dc, (long)Sc * Dc, (long)Dc * Sc);

        // fused attention
        flash_k<<<dim3(Sc / 128, Bc * Hc), 256, FL_SMEM>>>(
            pq_hi, pq_lo, pk_hi, pk_lo, pvt_hi, pvt_lo, pao_hi, pao_lo);

        // x = attn_out @ wo + bo + x
        tgemm<128, 1, 0><<<dim3(4, 32, 1), 256, S128>>>(
            Dc, pao_hi, pao_lo, Dc, 0, 0, wot_hi, wot_lo, Dc, 0, 0,
            out, nullptr, nullptr, Dc, 0, 0, 1, bo + l * Dc, 1.f, 0, 0);

        ln_k<<<Tc, 128>>>(out, ln2_w + l * Dc, ln2_b + l * Dc, ph, ph_hi, ph_lo);

        zero_k<<<1, 32>>>();
        gate_k<<<Tc / 4, 128>>>(ph, gate_w + (long)l * Dc * Ec);
        offsets_k<<<1, 1>>>();
        scatter_k<<<2 * Tc / 256, 256>>>();

        // grouped expert GEMMs
        tgemm<128, 2, 1><<<dim3(16, 64, Ec), 256, S128>>>(
            Dc, ph_hi, ph_lo, Dc, 0, 0, w1t_hi, w1t_lo, Dc, 0, 0,
            nullptr, phm_hi, phm_lo, DHc, 0, 0, 1,
            b1 + (long)l * Ec * DHc, 1.f, (long)Dc * DHc, DHc);
        tgemm<128, 3, 2><<<dim3(4, 64, Ec), 256, S128>>>(
            DHc, phm_hi, phm_lo, DHc, 0, 0, w2t_hi, w2t_lo, DHc, 0, 0,
            pyb, nullptr, nullptr, Dc, 0, 0, 1,
            b2 + (long)l * Ec * Dc, 1.f, (long)DHc * Dc, Dc);

        combine_k<<<Tc * Dc / 256, 256>>>(out);
    }
}

// round 6
// speedup vs baseline: 3.0072x; 1.0322x over previous
#include <cuda_runtime.h>
#include <cuda_bf16.h>
#include <math.h>
#include <stdint.h>

#define Tc 4096
#define Dc 512
#define Sc 1024
#define Bc 4
#define Hc 8
#define HEADc 64
#define Ec 8
#define DHc 2048
#define Lc 2
#define QKVN 1536

typedef __nv_bfloat16 bf16;

// ---------------- scratch (device globals) ---------------------------------
__device__ float g_h[Tc * Dc];
__device__ bf16  g_h_hi[Tc * Dc], g_h_lo[Tc * Dc];
__device__ bf16  g_qkv_hi[(size_t)Tc * QKVN], g_qkv_lo[(size_t)Tc * QKVN];
__device__ bf16  g_ao_hi[Tc * Dc], g_ao_lo[Tc * Dc];
__device__ bf16  g_hm_hi[(size_t)2 * Tc * DHc], g_hm_lo[(size_t)2 * Tc * DHc];
__device__ float g_ybuf[(size_t)2 * Tc * Dc];
__device__ bf16  g_wqkvt_hi[(size_t)Lc * QKVN * Dc], g_wqkvt_lo[(size_t)Lc * QKVN * Dc];
__device__ bf16  g_wot_hi[Lc * Dc * Dc], g_wot_lo[Lc * Dc * Dc];
__device__ bf16  g_w1t_hi[(size_t)Lc * Ec * Dc * DHc], g_w1t_lo[(size_t)Lc * Ec * Dc * DHc];
__device__ bf16  g_w2t_hi[(size_t)Lc * Ec * Dc * DHc], g_w2t_lo[(size_t)Lc * Ec * Dc * DHc];
__device__ float g_gate[Tc * 2];
__device__ int   g_topi[Tc * 2];
__device__ int   g_cnt[Ec], g_cur[Ec], g_off[Ec];
__device__ int   g_tok[2 * Tc];

// ================= low-level helpers ========================================
__device__ __forceinline__ uint32_t smem_u32(const void* p) {
    uint32_t a;
    asm("{ .reg .u64 t; cvta.to.shared.u64 t, %1; cvt.u32.u64 %0, t; }"
        : "=r"(a) : "l"(p));
    return a;
}
#define SWZ(o) ((o) ^ (((o) >> 3) & 0x70))
#define CP16(dst, src, sz) \
    asm volatile("cp.async.cg.shared.global [%0], [%1], 16, %2;" \
                 :: "r"(dst), "l"(src), "r"(sz) : "memory")
#define CP_COMMIT() asm volatile("cp.async.commit_group;" ::: "memory")

__device__ __forceinline__ void ldsm4(uint32_t* r, uint32_t addr) {
    asm volatile("ldmatrix.sync.aligned.m8n8.x4.shared.b16 {%0,%1,%2,%3}, [%4];"
                 : "=r"(r[0]), "=r"(r[1]), "=r"(r[2]), "=r"(r[3]) : "r"(addr));
}
__device__ __forceinline__ void ldsm4t(uint32_t* r, uint32_t addr) {
    asm volatile("ldmatrix.sync.aligned.m8n8.x4.trans.shared.b16 {%0,%1,%2,%3}, [%4];"
                 : "=r"(r[0]), "=r"(r[1]), "=r"(r[2]), "=r"(r[3]) : "r"(addr));
}
__device__ __forceinline__ void mma_bf16(float* d, const uint32_t* a,
                                         uint32_t b0, uint32_t b1) {
    asm volatile(
        "mma.sync.aligned.m16n8k16.row.col.f32.bf16.bf16.f32 "
        "{%0,%1,%2,%3}, {%4,%5,%6,%7}, {%8,%9}, {%0,%1,%2,%3};"
        : "+f"(d[0]), "+f"(d[1]), "+f"(d[2]), "+f"(d[3])
        : "r"(a[0]), "r"(a[1]), "r"(a[2]), "r"(a[3]), "r"(b0), "r"(b1));
}
__device__ __forceinline__ void split2(float x0, float x1, uint32_t& hi, uint32_t& lo) {
    bf16 h0 = __float2bfloat16(x0);
    bf16 h1 = __float2bfloat16(x1);
    bf16 l0 = __float2bfloat16(x0 - __bfloat162float(h0));
    bf16 l1 = __float2bfloat16(x1 - __bfloat162float(h1));
    hi = (uint32_t)__bfloat16_as_ushort(h0) | ((uint32_t)__bfloat16_as_ushort(h1) << 16);
    lo = (uint32_t)__bfloat16_as_ushort(l0) | ((uint32_t)__bfloat16_as_ushort(l1) << 16);
}

// ================= pipelined tensor GEMM ====================================
// EPI: 1 fp32+bias+C(resid); 2 gelu(+bias)->bf16pair grouped; 3 +bias->scatter fp32;
//      4 bf16 pair plain
// AMODE: 0 direct; 1 gather rows via g_tok>>1; 2 grouped rows off+m
template <int BN, int EPI, int AMODE>
__global__ void __launch_bounds__(256, 1) tgemm(
    int K,
    const bf16* __restrict__ Ahi, const bf16* __restrict__ Alo, int lda,
    const bf16* __restrict__ Bhi, const bf16* __restrict__ Blo, int ldb,
    float* __restrict__ C, bf16* __restrict__ Chi, bf16* __restrict__ Clo,
    int ldc, const float* __restrict__ bias, long wstride, long bstride)
{
    constexpr int NWN = BN / 32, NWM = 8 / NWN, MT = 8 / NWM;
    constexpr uint32_t ASZ = 16384u, BSZ = (uint32_t)BN * 128u;
    constexpr uint32_t STG = 2 * ASZ + 2 * BSZ;
    extern __shared__ char dsm[];
    __shared__ int stok_s[128];
    uint32_t sbb = smem_u32(dsm);
    uint32_t tb = (sbb + 1023) & ~1023u;
    int tid = threadIdx.x, wid = tid >> 5, lid = tid & 31;

    int cnt = 0, off = 0;
    if (AMODE != 0) {
        int e = blockIdx.z;
        cnt = g_cnt[e]; off = g_off[e];
        if ((int)blockIdx.y * 128 >= cnt) return;
        Bhi += (long)e * wstride; Blo += (long)e * wstride;
        bias += (long)e * bstride;
    }
    int m0 = blockIdx.y * 128, n0 = blockIdx.x * BN;

    if (AMODE == 1 && tid < 128) {
        int i = m0 + tid;
        stok_s[tid] = (i < cnt) ? (g_tok[off + i] >> 1) : -1;
    }
    if (AMODE == 2 && tid < 128) {
        int i = m0 + tid;
        stok_s[tid] = (i < cnt) ? g_tok[off + i] : -1;
    }
    if (AMODE != 0) __syncthreads();

    auto load_stage = [&](int c, int st) {
        uint32_t base = tb + (uint32_t)st * STG;
        int k0 = c << 6;
#pragma unroll
        for (int i = 0; i < 4; i++) {
            int idx = tid + (i << 8);
            int row = idx >> 3, c16 = idx & 7;
            uint32_t d = SWZ((uint32_t)(row * 128 + c16 * 16));
            long so; uint32_t sz = 16;
            if (AMODE == 0) so = (long)(m0 + row) * lda + k0 + c16 * 8;
            else if (AMODE == 1) {
                int tk = stok_s[row];
                if (tk < 0) { sz = 0; tk = 0; }
                so = (long)tk * lda + k0 + c16 * 8;
            } else {
                if (stok_s[row] < 0) { sz = 0; so = 0; }
                else so = (long)(off + m0 + row) * lda + k0 + c16 * 8;
            }
            CP16(base + d, Ahi + so, sz);
            CP16(base + ASZ + d, Alo + so, sz);
        }
#pragma unroll
        for (int i = 0; i < BN / 32; i++) {
            int idx = tid + (i << 8);
            int row = idx >> 3, c16 = idx & 7;
            uint32_t d = SWZ((uint32_t)(row * 128 + c16 * 16));
            long so = (long)(n0 + row) * ldb + k0 + c16 * 8;
            CP16(base + 2 * ASZ + d, Bhi + so, 16);
            CP16(base + 2 * ASZ + BSZ + d, Blo + so, 16);
        }
        CP_COMMIT();
    };

    int wm = (wid / NWN) * (MT * 16), wn = (wid % NWN) * 32;
    int a_row = wm + (lid & 15), a_cb = (lid >> 4) << 4;
    int b_row = wn + ((lid >> 4) << 3) + (lid & 7), b_cb = ((lid >> 3) & 1) << 4;
    float acc[MT][4][4] = {};

    int nch = K >> 6;
    load_stage(0, 0);
    for (int c = 0; c < nch; c++) {
        if (c + 1 < nch) {
            load_stage(c + 1, (c + 1) & 1);
            asm volatile("cp.async.wait_group 1;" ::: "memory");
        } else {
            asm volatile("cp.async.wait_group 0;" ::: "memory");
        }
        __syncthreads();
        uint32_t base = tb + (uint32_t)(c & 1) * STG;
#pragma unroll
        for (int ks = 0; ks < 4; ks++) {
            int kb = ks * 32;
            uint32_t aH[MT][4], aL[MT][4], bH[2][4], bL[2][4];
#pragma unroll
            for (int mt = 0; mt < MT; mt++) {
                uint32_t o = SWZ((uint32_t)((a_row + mt * 16) * 128 + kb + a_cb));
                ldsm4(aH[mt], base + o);
                ldsm4(aL[mt], base + ASZ + o);
            }
#pragma unroll
            for (int g = 0; g < 2; g++) {
                uint32_t o = SWZ((uint32_t)((b_row + g * 16) * 128 + kb + b_cb));
                ldsm4(bH[g], base + 2 * ASZ + o);
                ldsm4(bL[g], base + 2 * ASZ + BSZ + o);
            }
#pragma unroll
            for (int mt = 0; mt < MT; mt++)
#pragma unroll
                for (int nt = 0; nt < 4; nt++) {
                    int g = nt >> 1, pr = (nt & 1) * 2;
                    mma_bf16(acc[mt][nt], aH[mt], bH[g][pr], bH[g][pr + 1]);
                    mma_bf16(acc[mt][nt], aH[mt], bL[g][pr], bL[g][pr + 1]);
                    mma_bf16(acc[mt][nt], aL[mt], bH[g][pr], bH[g][pr + 1]);
                }
        }
        __syncthreads();
    }

    // ---- register epilogue ----
    int lr = lid >> 2, lc = (lid & 3) * 2;
#pragma unroll
    for (int mt = 0; mt < MT; mt++) {
#pragma unroll
        for (int half = 0; half < 2; half++) {
            int lrow = wm + mt * 16 + lr + half * 8;
            int grow = m0 + lrow;
#pragma unroll
            for (int nt = 0; nt < 4; nt++) {
                float v0 = acc[mt][nt][half * 2 + 0];
                float v1 = acc[mt][nt][half * 2 + 1];
                int gc = n0 + wn + nt * 8 + lc;
                if (EPI == 1) {
                    long idx = (long)grow * ldc + gc;
                    float2 old = *(const float2*)&C[idx];
                    *(float2*)&C[idx] = make_float2(v0 + bias[gc] + old.x,
                                                    v1 + bias[gc + 1] + old.y);
                } else if (EPI == 2) {
                    if (stok_s[lrow] >= 0) {
                        float t0 = v0 + bias[gc], t1 = v1 + bias[gc + 1];
                        float o0 = 0.5f * t0 * (1.f + erff(t0 * 0.70710678118654752f));
                        float o1 = 0.5f * t1 * (1.f + erff(t1 * 0.70710678118654752f));
                        uint32_t hi, lo; split2(o0, o1, hi, lo);
                        long idx = (long)(off + grow) * ldc + gc;
                        *(uint32_t*)&Chi[idx] = hi;
                        *(uint32_t*)&Clo[idx] = lo;
                    }
                } else if (EPI == 3) {
                    int ent = stok_s[lrow];
                    if (ent >= 0) {
                        *(float2*)&C[(long)ent * ldc + gc] =
                            make_float2(v0 + bias[gc], v1 + bias[gc + 1]);
                    }
                } else {  // EPI == 4
                    uint32_t hi, lo; split2(v0, v1, hi, lo);
                    long idx = (long)grow * ldc + gc;
                    *(uint32_t*)&Chi[idx] = hi;
                    *(uint32_t*)&Clo[idx] = lo;
                }
            }
        }
    }
}

// ================= fused flash attention ====================================
// grid: (S/128, B*H). 256 thr. QKV packed [T,1536] hi/lo; V consumed via
// trans-ldmatrix (no pre-transpose). Out: ao hi/lo [T,512].
#define FL_QH 0
#define FL_QL 16384
#define FL_KST 32768
#define FL_VST 98304
#define FL_SMEM 163840
__global__ void __launch_bounds__(256, 1) flash_k(
    const bf16* __restrict__ QKVhi, const bf16* __restrict__ QKVlo,
    bf16* __restrict__ Ohi, bf16* __restrict__ Olo)
{
    extern __shared__ char dsm[];
    uint32_t sb = smem_u32(dsm);
    int tid = threadIdx.x, wid = tid >> 5, lid = tid & 31;
    int bh = blockIdx.y, b = bh >> 3, h = bh & 7;
    int q0 = blockIdx.x * 128;

    long qbase = (long)b * Sc * QKVN + (long)q0 * QKVN + h * HEADc;
    long kb0   = (long)b * Sc * QKVN + 512 + h * HEADc;
    long vb0   = (long)b * Sc * QKVN + 1024 + h * HEADc;
    long obase = (long)b * Sc * Dc + (long)q0 * Dc + h * HEADc;

    auto load_q = [&]() {
#pragma unroll
        for (int i = 0; i < 4; i++) {
            int idx = tid + (i << 8);
            int row = idx >> 3, c16 = idx & 7;
            uint32_t d = SWZ((uint32_t)(row * 128 + c16 * 16));
            long so = qbase + (long)row * QKVN + c16 * 8;
            CP16(sb + FL_QH + d, QKVhi + so, 16);
            CP16(sb + FL_QL + d, QKVlo + so, 16);
        }
    };
    auto load_kv = [&](int c, int st) {
        uint32_t kstg = sb + FL_KST + (uint32_t)st * 32768;
        uint32_t vstg = sb + FL_VST + (uint32_t)st * 32768;
#pragma unroll
        for (int i = 0; i < 4; i++) {
            int idx = tid + (i << 8);
            int row = idx >> 3, c16 = idx & 7;
            uint32_t d = SWZ((uint32_t)(row * 128 + c16 * 16));
            long so = kb0 + (long)(c * 128 + row) * QKVN + c16 * 8;
            CP16(kstg + d, QKVhi + so, 16);
            CP16(kstg + 16384 + d, QKVlo + so, 16);
        }
#pragma unroll
        for (int i = 0; i < 4; i++) {
            int idx = tid + (i << 8);
            int row = idx >> 3, c16 = idx & 7;
            uint32_t d = SWZ((uint32_t)(row * 128 + c16 * 16));
            long so = vb0 + (long)(c * 128 + row) * QKVN + c16 * 8;
            CP16(vstg + d, QKVhi + so, 16);
            CP16(vstg + 16384 + d, QKVlo + so, 16);
        }
        CP_COMMIT();
    };

    load_q(); load_kv(0, 0);
    load_kv(1, 1);

    int wm = wid * 16;
    int lr = lid >> 2, lc = (lid & 3) * 2;
    int a_row = wm + (lid & 15), a_cb = (lid >> 4) << 4;
    int b_row8 = ((lid >> 4) << 3) + (lid & 7);
    int b_cb = ((lid >> 3) & 1) << 4;
    // trans-ldsm lane offsets for V [s,d] tiles
    int v_soff = (lid & 7) + (((lid >> 3) & 1) << 3);
    int v_doff = ((lid >> 4) & 1) << 3;

    uint32_t qh[4][4], ql[4][4];
    float m0r = -1e30f, m1r = -1e30f, l0r = 0.f, l1r = 0.f;
    float acc_o[8][4] = {};

    for (int c = 0; c < 8; c++) {
        if (c < 7) asm volatile("cp.async.wait_group 1;" ::: "memory");
        else       asm volatile("cp.async.wait_group 0;" ::: "memory");
        __syncthreads();

        if (c == 0) {
#pragma unroll
            for (int ks = 0; ks < 4; ks++) {
                uint32_t o = SWZ((uint32_t)(a_row * 128 + ks * 32 + a_cb));
                ldsm4(qh[ks], sb + FL_QH + o);
                ldsm4(ql[ks], sb + FL_QL + o);
            }
        }
        uint32_t kstg = sb + FL_KST + (uint32_t)(c & 1) * 32768;
        uint32_t vstg = sb + FL_VST + (uint32_t)(c & 1) * 32768;

        // ---- S = Q K^T ----
        float s_acc[16][4] = {};
#pragma unroll
        for (int ks = 0; ks < 4; ks++) {
            int kb = ks * 32;
            uint32_t kh[8][4], kl[8][4];
#pragma unroll
            for (int g = 0; g < 8; g++) {
                uint32_t o = SWZ((uint32_t)((g * 16 + b_row8) * 128 + kb + b_cb));
                ldsm4(kh[g], kstg + o);
                ldsm4(kl[g], kstg + 16384 + o);
            }
#pragma unroll
            for (int nt = 0; nt < 16; nt++) {
                int g = nt >> 1, pr = (nt & 1) * 2;
                mma_bf16(s_acc[nt], qh[ks], kh[g][pr], kh[g][pr + 1]);
                mma_bf16(s_acc[nt], qh[ks], kl[g][pr], kl[g][pr + 1]);
                mma_bf16(s_acc[nt], ql[ks], kh[g][pr], kh[g][pr + 1]);
            }
        }

        // ---- online softmax (scale 1/8) ----
        float t0 = -1e30f, t1 = -1e30f;
#pragma unroll
        for (int nt = 0; nt < 16; nt++) {
#pragma unroll
            for (int j = 0; j < 4; j++) s_acc[nt][j] *= 0.125f;
            t0 = fmaxf(t0, fmaxf(s_acc[nt][0], s_acc[nt][1]));
            t1 = fmaxf(t1, fmaxf(s_acc[nt][2], s_acc[nt][3]));
        }
#pragma unroll
        for (int o = 1; o <= 2; o <<= 1) {
            t0 = fmaxf(t0, __shfl_xor_sync(0xffffffffu, t0, o));
            t1 = fmaxf(t1, __shfl_xor_sync(0xffffffffu, t1, o));
        }
        float mn0 = fmaxf(m0r, t0), mn1 = fmaxf(m1r, t1);
        float cor0 = expf(m0r - mn0), cor1 = expf(m1r - mn1);
        float rs0 = 0.f, rs1 = 0.f;
#pragma unroll
        for (int nt = 0; nt < 16; nt++) {
            s_acc[nt][0] = expf(s_acc[nt][0] - mn0);
            s_acc[nt][1] = expf(s_acc[nt][1] - mn0);
            s_acc[nt][2] = expf(s_acc[nt][2] - mn1);
            s_acc[nt][3] = expf(s_acc[nt][3] - mn1);
            rs0 += s_acc[nt][0] + s_acc[nt][1];
            rs1 += s_acc[nt][2] + s_acc[nt][3];
        }
#pragma unroll
        for (int o = 1; o <= 2; o <<= 1) {
            rs0 += __shfl_xor_sync(0xffffffffu, rs0, o);
            rs1 += __shfl_xor_sync(0xffffffffu, rs1, o);
        }
        l0r = l0r * cor0 + rs0; l1r = l1r * cor1 + rs1;
        m0r = mn0; m1r = mn1;
#pragma unroll
        for (int nt = 0; nt < 8; nt++) {
            acc_o[nt][0] *= cor0; acc_o[nt][1] *= cor0;
            acc_o[nt][2] *= cor1; acc_o[nt][3] *= cor1;
        }

        // ---- O += P V (V via trans-ldmatrix from [s,d] tiles) ----
#pragma unroll
        for (int kt = 0; kt < 8; kt++) {
            uint32_t ah[4], al[4];
            split2(s_acc[2 * kt][0],     s_acc[2 * kt][1],     ah[0], al[0]);
            split2(s_acc[2 * kt][2],     s_acc[2 * kt][3],     ah[1], al[1]);
            split2(s_acc[2 * kt + 1][0], s_acc[2 * kt + 1][1], ah[2], al[2]);
            split2(s_acc[2 * kt + 1][2], s_acc[2 * kt + 1][3], ah[3], al[3]);
            uint32_t vh[4][4], vl[4][4];
#pragma unroll
            for (int g = 0; g < 4; g++) {
                uint32_t o = SWZ((uint32_t)((kt * 16 + v_soff) * 128 +
                                            (g * 16 + v_doff) * 2));
                ldsm4t(vh[g], vstg + o);
                ldsm4t(vl[g], vstg + 16384 + o);
            }
#pragma unroll
            for (int nt = 0; nt < 8; nt++) {
                int g = nt >> 1, pr = (nt & 1) * 2;
                mma_bf16(acc_o[nt], ah, vh[g][pr], vh[g][pr + 1]);
                mma_bf16(acc_o[nt], ah, vl[g][pr], vl[g][pr + 1]);
                mma_bf16(acc_o[nt], al, vh[g][pr], vh[g][pr + 1]);
            }
        }
        __syncthreads();
        if (c + 2 < 8) load_kv(c + 2, c & 1);
    }

    // ---- epilogue ----
    float inv0 = 1.f / l0r, inv1 = 1.f / l1r;
    long r0g = obase + (long)(wm + lr) * Dc;
    long r1g = obase + (long)(wm + lr + 8) * Dc;
#pragma unroll
    for (int nt = 0; nt < 8; nt++) {
        int gc = nt * 8 + lc;
        uint32_t hi, lo;
        split2(acc_o[nt][0] * inv0, acc_o[nt][1] * inv0, hi, lo);
        *(uint32_t*)&Ohi[r0g + gc] = hi;
        *(uint32_t*)&Olo[r0g + gc] = lo;
        split2(acc_o[nt][2] * inv1, acc_o[nt][3] * inv1, hi, lo);
        *(uint32_t*)&Ohi[r1g + gc] = hi;
        *(uint32_t*)&Olo[r1g + gc] = lo;
    }
}

// ================= transpose + split convert ================================
__global__ void tconv(const float* __restrict__ in, bf16* __restrict__ ohi,
                      bf16* __restrict__ olo, int R, int Ccol, long sin, long sout)
{
    __shared__ float t[32][33];
    long ib = (long)blockIdx.z * sin, ob = (long)blockIdx.z * sout;
    int c0 = blockIdx.x * 32, r0 = blockIdx.y * 32;
    int tx = threadIdx.x, ty = threadIdx.y;
#pragma unroll
    for (int j = 0; j < 4; j++)
        t[ty + j * 8][tx] = in[ib + (long)(r0 + ty + j * 8) * Ccol + c0 + tx];
    __syncthreads();
#pragma unroll
    for (int j = 0; j < 4; j++) {
        float v = t[tx][ty + j * 8];
        bf16 h = __float2bfloat16(v);
        long o = ob + (long)(c0 + ty + j * 8) * R + r0 + tx;
        ohi[o] = h;
        olo[o] = __float2bfloat16(v - __bfloat162float(h));
    }
}

// ================= elementwise kernels ======================================
__global__ void copy_k(const float* __restrict__ a, float* __restrict__ o) {
    long i = (long)blockIdx.x * 256 + threadIdx.x;
    o[i] = a[i];
}

__global__ void ln_k(const float* __restrict__ x, const float* __restrict__ w,
                     const float* __restrict__ b, float* __restrict__ out,
                     bf16* __restrict__ ohi, bf16* __restrict__ olo, int zeroCnt) {
    int row = blockIdx.x;
    int tid = threadIdx.x;
    if (zeroCnt && row == 0 && tid < Ec) g_cnt[tid] = 0;
    const float* xr = x + (long)row * Dc;
    float4 v = *(const float4*)&xr[tid * 4];
    float s = v.x + v.y + v.z + v.w;
    float s2 = v.x * v.x + v.y * v.y + v.z * v.z + v.w * v.w;
    __shared__ float sh[4], sh2[4];
#pragma unroll
    for (int o = 16; o > 0; o >>= 1) {
        s  += __shfl_xor_sync(0xffffffffu, s, o);
        s2 += __shfl_xor_sync(0xffffffffu, s2, o);
    }
    if ((tid & 31) == 0) { sh[tid >> 5] = s; sh2[tid >> 5] = s2; }
    __syncthreads();
    float a = 0.f, a2 = 0.f;
#pragma unroll
    for (int i = 0; i < 4; i++) { a += sh[i]; a2 += sh2[i]; }
    float mu  = a * (1.f / Dc);
    float var = a2 * (1.f / Dc) - mu * mu;
    float inv = rsqrtf(var + 1e-6f);
    int d = tid * 4;
    const float4 wv = *(const float4*)&w[d];
    const float4 bv = *(const float4*)&b[d];
    float y0 = (v.x - mu) * inv * wv.x + bv.x;
    float y1 = (v.y - mu) * inv * wv.y + bv.y;
    float y2 = (v.z - mu) * inv * wv.z + bv.z;
    float y3 = (v.w - mu) * inv * wv.w + bv.w;
    long idx = (long)row * Dc + d;
    *(float4*)&out[idx] = make_float4(y0, y1, y2, y3);
    uint32_t h0, l0, h1, l1;
    split2(y0, y1, h0, l0); split2(y2, y3, h1, l1);
    *(uint32_t*)&ohi[idx] = h0; *(uint32_t*)&ohi[idx + 2] = h1;
    *(uint32_t*)&olo[idx] = l0; *(uint32_t*)&olo[idx + 2] = l1;
}

__global__ void gate_k(const float* __restrict__ h, const float* __restrict__ gw) {
    int t = blockIdx.x * 4 + (threadIdx.x >> 5);
    int lid = threadIdx.x & 31;
    const float* hr = h + (long)t * Dc;
    float acc[Ec] = {};
    for (int d = lid; d < Dc; d += 32) {
        float hv = hr[d];
#pragma unroll
        for (int e = 0; e < Ec; e++) acc[e] += hv * gw[d * Ec + e];
    }
#pragma unroll
    for (int e = 0; e < Ec; e++)
#pragma unroll
        for (int o = 16; o > 0; o >>= 1)
            acc[e] += __shfl_xor_sync(0xffffffffu, acc[e], o);
    if (lid == 0) {
        int i0 = 0; float v0 = acc[0];
#pragma unroll
        for (int e = 1; e < Ec; e++) if (acc[e] > v0) { v0 = acc[e]; i0 = e; }
        int i1 = -1; float v1 = -3.4e38f;
#pragma unroll
        for (int e = 0; e < Ec; e++) if (e != i0 && acc[e] > v1) { v1 = acc[e]; i1 = e; }
        float g1 = 1.f / (1.f + expf(v0 - v1));
        g_topi[t * 2] = i0; g_topi[t * 2 + 1] = i1;
        g_gate[t * 2] = 1.f - g1; g_gate[t * 2 + 1] = g1;
        atomicAdd(&g_cnt[i0], 1);
        atomicAdd(&g_cnt[i1], 1);
    }
}

__global__ void offsets_k() {
    if (threadIdx.x == 0) {
        int o = 0;
        for (int e = 0; e < Ec; e++) { g_off[e] = o; g_cur[e] = o; o += g_cnt[e]; }
    }
}

__global__ void scatter_k() {
    int i = blockIdx.x * 256 + threadIdx.x;
    if (i >= 2 * Tc) return;
    int e = g_topi[i];
    int pos = atomicAdd(&g_cur[e], 1);
    g_tok[pos] = i;
}

__global__ void combine_k(float* __restrict__ x) {
    int i = blockIdx.x * 256 + threadIdx.x;
    int t = i >> 9;
    int d = i & 511;
    x[i] += g_gate[t * 2] * g_ybuf[(long)(t * 2) * Dc + d]
          + g_gate[t * 2 + 1] * g_ybuf[(long)(t * 2 + 1) * Dc + d];
}

// ================= host =====================================================
#define S128 (2 * (2 * 16384 + 2 * 128 * 128) + 1024)

extern "C" void kernel_launch(void* const* d_in, const int* in_sizes, int n_in,
                              void* d_out, int out_size)
{
    const float* x      = (const float*)d_in[0];
    const float* ln1_w  = (const float*)d_in[1];
    const float* ln1_b  = (const float*)d_in[2];
    const float* wq     = (const float*)d_in[3];
    const float* wk     = (const float*)d_in[4];
    const float* wv     = (const float*)d_in[5];
    const float* wo     = (const float*)d_in[6];
    const float* bo     = (const float*)d_in[7];
    const float* ln2_w  = (const float*)d_in[8];
    const float* ln2_b  = (const float*)d_in[9];
    const float* gate_w = (const float*)d_in[10];
    const float* w1     = (const float*)d_in[11];
    const float* b1     = (const float*)d_in[12];
    const float* w2     = (const float*)d_in[13];
    const float* b2     = (const float*)d_in[14];
    float* out = (float*)d_out;

    float *ph, *pyb;
    bf16 *ph_hi, *ph_lo, *pqkv_hi, *pqkv_lo, *pao_hi, *pao_lo, *phm_hi, *phm_lo;
    bf16 *wqkvt_hi, *wqkvt_lo, *wot_hi, *wot_lo, *w1t_hi, *w1t_lo, *w2t_hi, *w2t_lo;
    cudaGetSymbolAddress((void**)&ph, g_h);
    cudaGetSymbolAddress((void**)&pyb, g_ybuf);
    cudaGetSymbolAddress((void**)&ph_hi, g_h_hi);   cudaGetSymbolAddress((void**)&ph_lo, g_h_lo);
    cudaGetSymbolAddress((void**)&pqkv_hi, g_qkv_hi); cudaGetSymbolAddress((void**)&pqkv_lo, g_qkv_lo);
    cudaGetSymbolAddress((void**)&pao_hi, g_ao_hi); cudaGetSymbolAddress((void**)&pao_lo, g_ao_lo);
    cudaGetSymbolAddress((void**)&phm_hi, g_hm_hi); cudaGetSymbolAddress((void**)&phm_lo, g_hm_lo);
    cudaGetSymbolAddress((void**)&wqkvt_hi, g_wqkvt_hi); cudaGetSymbolAddress((void**)&wqkvt_lo, g_wqkvt_lo);
    cudaGetSymbolAddress((void**)&wot_hi, g_wot_hi); cudaGetSymbolAddress((void**)&wot_lo, g_wot_lo);
    cudaGetSymbolAddress((void**)&w1t_hi, g_w1t_hi); cudaGetSymbolAddress((void**)&w1t_lo, g_w1t_lo);
    cudaGetSymbolAddress((void**)&w2t_hi, g_w2t_hi); cudaGetSymbolAddress((void**)&w2t_lo, g_w2t_lo);

    cudaFuncSetAttribute(tgemm<128, 1, 0>, cudaFuncAttributeMaxDynamicSharedMemorySize, S128);
    cudaFuncSetAttribute(tgemm<128, 4, 0>, cudaFuncAttributeMaxDynamicSharedMemorySize, S128);
    cudaFuncSetAttribute(tgemm<128, 2, 1>, cudaFuncAttributeMaxDynamicSharedMemorySize, S128);
    cudaFuncSetAttribute(tgemm<128, 3, 2>, cudaFuncAttributeMaxDynamicSharedMemorySize, S128);
    cudaFuncSetAttribute(flash_k, cudaFuncAttributeMaxDynamicSharedMemorySize, FL_SMEM);

    // side stream for weight conversion (host handles leak across the ~2
    // kernel_launch invocations; no device memory involved)
    cudaStream_t s1;
    cudaStreamCreateWithFlags(&s1, cudaStreamNonBlocking);
    cudaEvent_t eFork, eQKV[Lc], eWO[Lc], eMOE[Lc];
    cudaEventCreateWithFlags(&eFork, cudaEventDisableTiming);
    for (int l = 0; l < Lc; l++) {
        cudaEventCreateWithFlags(&eQKV[l], cudaEventDisableTiming);
        cudaEventCreateWithFlags(&eWO[l], cudaEventDisableTiming);
        cudaEventCreateWithFlags(&eMOE[l], cudaEventDisableTiming);
    }

    dim3 tcb(32, 8);
    cudaEventRecord(eFork, 0);
    cudaStreamWaitEvent(s1, eFork, 0);
    for (int l = 0; l < Lc; l++) {
        bf16* qt_hi = wqkvt_hi + (long)l * QKVN * Dc;
        bf16* qt_lo = wqkvt_lo + (long)l * QKVN * Dc;
        tconv<<<dim3(16, 16, 1), tcb, 0, s1>>>(wq + (long)l * Dc * Dc, qt_hi, qt_lo, Dc, Dc, 0, 0);
        tconv<<<dim3(16, 16, 1), tcb, 0, s1>>>(wk + (long)l * Dc * Dc, qt_hi + 512 * Dc, qt_lo + 512 * Dc, Dc, Dc, 0, 0);
        tconv<<<dim3(16, 16, 1), tcb, 0, s1>>>(wv + (long)l * Dc * Dc, qt_hi + 1024 * Dc, qt_lo + 1024 * Dc, Dc, Dc, 0, 0);
        cudaEventRecord(eQKV[l], s1);
        tconv<<<dim3(16, 16, 1), tcb, 0, s1>>>(wo + (long)l * Dc * Dc,
            wot_hi + (long)l * Dc * Dc, wot_lo + (long)l * Dc * Dc, Dc, Dc, 0, 0);
        cudaEventRecord(eWO[l], s1);
        tconv<<<dim3(DHc / 32, Dc / 32, Ec), tcb, 0, s1>>>(
            w1 + (long)l * Ec * Dc * DHc,
            w1t_hi + (long)l * Ec * Dc * DHc, w1t_lo + (long)l * Ec * Dc * DHc,
            Dc, DHc, (long)Dc * DHc, (long)Dc * DHc);
        tconv<<<dim3(Dc / 32, DHc / 32, Ec), tcb, 0, s1>>>(
            w2 + (long)l * Ec * DHc * Dc,
            w2t_hi + (long)l * Ec * DHc * Dc, w2t_lo + (long)l * Ec * DHc * Dc,
            DHc, Dc, (long)DHc * Dc, (long)DHc * Dc);
        cudaEventRecord(eMOE[l], s1);
    }

    copy_k<<<Tc * Dc / 256, 256>>>(x, out);

    for (int l = 0; l < Lc; l++) {
        bf16* qt_hi = wqkvt_hi + (long)l * QKVN * Dc;
        bf16* qt_lo = wqkvt_lo + (long)l * QKVN * Dc;

        ln_k<<<Tc, 128>>>(out, ln1_w + l * Dc, ln1_b + l * Dc, ph, ph_hi, ph_lo, 0);

        // fused QKV
        cudaStreamWaitEvent(0, eQKV[l], 0);
        tgemm<128, 4, 0><<<dim3(QKVN / 128, 32, 1), 256, S128>>>(
            Dc, ph_hi, ph_lo, Dc, qt_hi, qt_lo, Dc,
            nullptr, pqkv_hi, pqkv_lo, QKVN, nullptr, 0, 0);

        // fused attention
        flash_k<<<dim3(Sc / 128, Bc * Hc), 256, FL_SMEM>>>(
            pqkv_hi, pqkv_lo, pao_hi, pao_lo);

        // x = attn_out @ wo + bo + x
        cudaStreamWaitEvent(0, eWO[l], 0);
        tgemm<128, 1, 0><<<dim3(4, 32, 1), 256, S128>>>(
            Dc, pao_hi, pao_lo, Dc,
            wot_hi + (long)l * Dc * Dc, wot_lo + (long)l * Dc * Dc, Dc,
            out, nullptr, nullptr, Dc, bo + l * Dc, 0, 0);

        ln_k<<<Tc, 128>>>(out, ln2_w + l * Dc, ln2_b + l * Dc, ph, ph_hi, ph_lo, 1);

        gate_k<<<Tc / 4, 128>>>(ph, gate_w + (long)l * Dc * Ec);
        offsets_k<<<1, 1>>>();
        scatter_k<<<2 * Tc / 256, 256>>>();

        // grouped expert GEMMs
        cudaStreamWaitEvent(0, eMOE[l], 0);
        tgemm<128, 2, 1><<<dim3(16, 64, Ec), 256, S128>>>(
            Dc, ph_hi, ph_lo, Dc,
            w1t_hi + (long)l * Ec * Dc * DHc, w1t_lo + (long)l * Ec * Dc * DHc, Dc,
            nullptr, phm_hi, phm_lo, DHc,
            b1 + (long)l * Ec * DHc, (long)Dc * DHc, DHc);
        tgemm<128, 3, 2><<<dim3(4, 64, Ec), 256, S128>>>(
            DHc, phm_hi, phm_lo, DHc,
            w2t_hi + (long)l * Ec * DHc * Dc, w2t_lo + (long)l * Ec * DHc * Dc, DHc,
            pyb, nullptr, nullptr, Dc,
            b2 + (long)l * Ec * Dc, (long)DHc * Dc, Dc);

        combine_k<<<Tc * Dc / 256, 256>>>(out);
    }
}

// round 7
// speedup vs baseline: 3.1296x; 1.0407x over previous
#include <cuda_runtime.h>
#include <cuda_bf16.h>
#include <math.h>
#include <stdint.h>

#define Tc 4096
#define Dc 512
#define Sc 1024
#define Bc 4
#define Hc 8
#define HEADc 64
#define Ec 8
#define DHc 2048
#define Lc 2
#define QKVN 1536

typedef __nv_bfloat16 bf16;

// ---------------- scratch (device globals) ---------------------------------
__device__ float g_h[Tc * Dc];
__device__ bf16  g_h_hi[Tc * Dc], g_h_lo[Tc * Dc];
__device__ bf16  g_qkv_hi[(size_t)Tc * QKVN], g_qkv_lo[(size_t)Tc * QKVN];
__device__ bf16  g_ao_hi[Tc * Dc], g_ao_lo[Tc * Dc];
__device__ bf16  g_hm_hi[(size_t)2 * Tc * DHc], g_hm_lo[(size_t)2 * Tc * DHc];
__device__ float g_ybuf[(size_t)2 * Tc * Dc];
__device__ bf16  g_wqkvt_hi[(size_t)Lc * QKVN * Dc], g_wqkvt_lo[(size_t)Lc * QKVN * Dc];
__device__ bf16  g_wot_hi[Lc * Dc * Dc], g_wot_lo[Lc * Dc * Dc];
__device__ bf16  g_w1t_hi[(size_t)Lc * Ec * Dc * DHc], g_w1t_lo[(size_t)Lc * Ec * Dc * DHc];
__device__ bf16  g_w2t_hi[(size_t)Lc * Ec * Dc * DHc], g_w2t_lo[(size_t)Lc * Ec * Dc * DHc];
__device__ float g_gate[Tc * 2];
__device__ int   g_topi[Tc * 2];
__device__ int   g_cnt[Ec], g_cur[Ec], g_off[Ec];
__device__ int   g_tok[2 * Tc];

// ================= low-level helpers ========================================
__device__ __forceinline__ uint32_t smem_u32(const void* p) {
    uint32_t a;
    asm("{ .reg .u64 t; cvta.to.shared.u64 t, %1; cvt.u32.u64 %0, t; }"
        : "=r"(a) : "l"(p));
    return a;
}
#define SWZ(o)   ((o) ^ (((o) >> 3) & 0x70))
#define SWZ64(o) ((o) ^ (((o) >> 3) & 0x30))
#define CP16(dst, src, sz) \
    asm volatile("cp.async.cg.shared.global [%0], [%1], 16, %2;" \
                 :: "r"(dst), "l"(src), "r"(sz) : "memory")
#define CP_COMMIT() asm volatile("cp.async.commit_group;" ::: "memory")

__device__ __forceinline__ void ldsm4(uint32_t* r, uint32_t addr) {
    asm volatile("ldmatrix.sync.aligned.m8n8.x4.shared.b16 {%0,%1,%2,%3}, [%4];"
                 : "=r"(r[0]), "=r"(r[1]), "=r"(r[2]), "=r"(r[3]) : "r"(addr));
}
__device__ __forceinline__ void ldsm4t(uint32_t* r, uint32_t addr) {
    asm volatile("ldmatrix.sync.aligned.m8n8.x4.trans.shared.b16 {%0,%1,%2,%3}, [%4];"
                 : "=r"(r[0]), "=r"(r[1]), "=r"(r[2]), "=r"(r[3]) : "r"(addr));
}
__device__ __forceinline__ void mma_bf16(float* d, const uint32_t* a,
                                         uint32_t b0, uint32_t b1) {
    asm volatile(
        "mma.sync.aligned.m16n8k16.row.col.f32.bf16.bf16.f32 "
        "{%0,%1,%2,%3}, {%4,%5,%6,%7}, {%8,%9}, {%0,%1,%2,%3};"
        : "+f"(d[0]), "+f"(d[1]), "+f"(d[2]), "+f"(d[3])
        : "r"(a[0]), "r"(a[1]), "r"(a[2]), "r"(a[3]), "r"(b0), "r"(b1));
}
__device__ __forceinline__ void split2(float x0, float x1, uint32_t& hi, uint32_t& lo) {
    bf16 h0 = __float2bfloat16(x0);
    bf16 h1 = __float2bfloat16(x1);
    bf16 l0 = __float2bfloat16(x0 - __bfloat162float(h0));
    bf16 l1 = __float2bfloat16(x1 - __bfloat162float(h1));
    hi = (uint32_t)__bfloat16_as_ushort(h0) | ((uint32_t)__bfloat16_as_ushort(h1) << 16);
    lo = (uint32_t)__bfloat16_as_ushort(l0) | ((uint32_t)__bfloat16_as_ushort(l1) << 16);
}

// ================= pipelined tensor GEMM (2 CTAs/SM) ========================
// K-chunk = 32 elems (64B rows, SW64 swizzle). Stage 32KB, 2 stages = 64KB.
// EPI: 1 fp32+bias+C(resid); 2 gelu(+bias)->bf16pair grouped; 3 +bias->scatter fp32;
//      4 bf16 pair plain
// AMODE: 0 direct; 1 gather rows via g_tok>>1; 2 grouped rows off+m
#define TG_STG 32768u
#define TG_OAL 8192u
#define TG_OBH 16384u
#define TG_OBL 24576u
#define S128 (2 * 32768 + 1024)
template <int EPI, int AMODE>
__global__ void __launch_bounds__(256, 2) tgemm(
    int K,
    const bf16* __restrict__ Ahi, const bf16* __restrict__ Alo, int lda,
    const bf16* __restrict__ Bhi, const bf16* __restrict__ Blo, int ldb,
    float* __restrict__ C, bf16* __restrict__ Chi, bf16* __restrict__ Clo,
    int ldc, const float* __restrict__ bias, long wstride, long bstride)
{
    extern __shared__ char dsm[];
    __shared__ int stok_s[128];
    uint32_t sbb = smem_u32(dsm);
    uint32_t tb = (sbb + 1023) & ~1023u;
    int tid = threadIdx.x, wid = tid >> 5, lid = tid & 31;

    int cnt = 0, off = 0;
    if (AMODE != 0) {
        int e = blockIdx.z;
        cnt = g_cnt[e]; off = g_off[e];
        if ((int)blockIdx.y * 128 >= cnt) return;
        Bhi += (long)e * wstride; Blo += (long)e * wstride;
        bias += (long)e * bstride;
    }
    int m0 = blockIdx.y * 128, n0 = blockIdx.x * 128;

    if (AMODE == 1 && tid < 128) {
        int i = m0 + tid;
        stok_s[tid] = (i < cnt) ? (g_tok[off + i] >> 1) : -1;
    }
    if (AMODE == 2 && tid < 128) {
        int i = m0 + tid;
        stok_s[tid] = (i < cnt) ? g_tok[off + i] : -1;
    }
    if (AMODE != 0) __syncthreads();

    // per-stage loader: 128 rows x 32 k (64B rows), A hi/lo + B hi/lo
    auto load_stage = [&](int c, int st) {
        uint32_t base = tb + (uint32_t)st * TG_STG;
        int k0 = c << 5;
#pragma unroll
        for (int i = 0; i < 2; i++) {
            int idx = tid + (i << 8);
            int row = idx >> 2, c16 = idx & 3;
            uint32_t d = SWZ64((uint32_t)(row * 64 + c16 * 16));
            long so; uint32_t sz = 16;
            if (AMODE == 0) so = (long)(m0 + row) * lda + k0 + c16 * 8;
            else if (AMODE == 1) {
                int tk = stok_s[row];
                if (tk < 0) { sz = 0; tk = 0; }
                so = (long)tk * lda + k0 + c16 * 8;
            } else {
                if (stok_s[row] < 0) { sz = 0; so = 0; }
                else so = (long)(off + m0 + row) * lda + k0 + c16 * 8;
            }
            CP16(base + d, Ahi + so, sz);
            CP16(base + TG_OAL + d, Alo + so, sz);
        }
#pragma unroll
        for (int i = 0; i < 2; i++) {
            int idx = tid + (i << 8);
            int row = idx >> 2, c16 = idx & 3;
            uint32_t d = SWZ64((uint32_t)(row * 64 + c16 * 16));
            long so = (long)(n0 + row) * ldb + k0 + c16 * 8;
            CP16(base + TG_OBH + d, Bhi + so, 16);
            CP16(base + TG_OBL + d, Blo + so, 16);
        }
        CP_COMMIT();
    };

    int wm = (wid >> 2) * 64, wn = (wid & 3) * 32;
    int a_row = wm + (lid & 15), a_cb = (lid >> 4) << 4;
    int b_row = wn + ((lid >> 4) << 3) + (lid & 7), b_cb = ((lid >> 3) & 1) << 4;
    float acc[4][4][4] = {};

    int nch = K >> 5;
    load_stage(0, 0);
    for (int c = 0; c < nch; c++) {
        if (c + 1 < nch) {
            load_stage(c + 1, (c + 1) & 1);
            asm volatile("cp.async.wait_group 1;" ::: "memory");
        } else {
            asm volatile("cp.async.wait_group 0;" ::: "memory");
        }
        __syncthreads();
        uint32_t base = tb + (uint32_t)(c & 1) * TG_STG;
#pragma unroll
        for (int ks = 0; ks < 2; ks++) {
            int kb = ks * 32;
            uint32_t bH[2][4], bL[2][4];
#pragma unroll
            for (int g = 0; g < 2; g++) {
                uint32_t o = SWZ64((uint32_t)((b_row + g * 16) * 64 + kb + b_cb));
                ldsm4(bH[g], base + TG_OBH + o);
                ldsm4(bL[g], base + TG_OBL + o);
            }
#pragma unroll
            for (int mt = 0; mt < 4; mt++) {
                uint32_t aH[4], aL[4];
                uint32_t o = SWZ64((uint32_t)((a_row + mt * 16) * 64 + kb + a_cb));
                ldsm4(aH, base + o);
                ldsm4(aL, base + TG_OAL + o);
#pragma unroll
                for (int nt = 0; nt < 4; nt++) {
                    int g = nt >> 1, pr = (nt & 1) * 2;
                    mma_bf16(acc[mt][nt], aH, bH[g][pr], bH[g][pr + 1]);
                    mma_bf16(acc[mt][nt], aH, bL[g][pr], bL[g][pr + 1]);
                    mma_bf16(acc[mt][nt], aL, bH[g][pr], bH[g][pr + 1]);
                }
            }
        }
        __syncthreads();
    }

    // ---- register epilogue ----
    int lr = lid >> 2, lc = (lid & 3) * 2;
#pragma unroll
    for (int mt = 0; mt < 4; mt++) {
#pragma unroll
        for (int half = 0; half < 2; half++) {
            int lrow = wm + mt * 16 + lr + half * 8;
            int grow = m0 + lrow;
#pragma unroll
            for (int nt = 0; nt < 4; nt++) {
                float v0 = acc[mt][nt][half * 2 + 0];
                float v1 = acc[mt][nt][half * 2 + 1];
                int gc = n0 + wn + nt * 8 + lc;
                if (EPI == 1) {
                    long idx = (long)grow * ldc + gc;
                    float2 old = *(const float2*)&C[idx];
                    *(float2*)&C[idx] = make_float2(v0 + bias[gc] + old.x,
                                                    v1 + bias[gc + 1] + old.y);
                } else if (EPI == 2) {
                    if (stok_s[lrow] >= 0) {
                        float t0 = v0 + bias[gc], t1 = v1 + bias[gc + 1];
                        float o0 = 0.5f * t0 * (1.f + erff(t0 * 0.70710678118654752f));
                        float o1 = 0.5f * t1 * (1.f + erff(t1 * 0.70710678118654752f));
                        uint32_t hi, lo; split2(o0, o1, hi, lo);
                        long idx = (long)(off + grow) * ldc + gc;
                        *(uint32_t*)&Chi[idx] = hi;
                        *(uint32_t*)&Clo[idx] = lo;
                    }
                } else if (EPI == 3) {
                    int ent = stok_s[lrow];
                    if (ent >= 0) {
                        *(float2*)&C[(long)ent * ldc + gc] =
                            make_float2(v0 + bias[gc], v1 + bias[gc + 1]);
                    }
                } else {  // EPI == 4
                    uint32_t hi, lo; split2(v0, v1, hi, lo);
                    long idx = (long)grow * ldc + gc;
                    *(uint32_t*)&Chi[idx] = hi;
                    *(uint32_t*)&Clo[idx] = lo;
                }
            }
        }
    }
}

// ================= fused flash attention ====================================
#define FL_QH 0
#define FL_QL 16384
#define FL_KST 32768
#define FL_VST 98304
#define FL_SMEM 163840
__global__ void __launch_bounds__(256, 1) flash_k(
    const bf16* __restrict__ QKVhi, const bf16* __restrict__ QKVlo,
    bf16* __restrict__ Ohi, bf16* __restrict__ Olo)
{
    extern __shared__ char dsm[];
    uint32_t sb = smem_u32(dsm);
    int tid = threadIdx.x, wid = tid >> 5, lid = tid & 31;
    int bh = blockIdx.y, b = bh >> 3, h = bh & 7;
    int q0 = blockIdx.x * 128;

    long qbase = (long)b * Sc * QKVN + (long)q0 * QKVN + h * HEADc;
    long kb0   = (long)b * Sc * QKVN + 512 + h * HEADc;
    long vb0   = (long)b * Sc * QKVN + 1024 + h * HEADc;
    long obase = (long)b * Sc * Dc + (long)q0 * Dc + h * HEADc;

    auto load_q = [&]() {
#pragma unroll
        for (int i = 0; i < 4; i++) {
            int idx = tid + (i << 8);
            int row = idx >> 3, c16 = idx & 7;
            uint32_t d = SWZ((uint32_t)(row * 128 + c16 * 16));
            long so = qbase + (long)row * QKVN + c16 * 8;
            CP16(sb + FL_QH + d, QKVhi + so, 16);
            CP16(sb + FL_QL + d, QKVlo + so, 16);
        }
    };
    auto load_kv = [&](int c, int st) {
        uint32_t kstg = sb + FL_KST + (uint32_t)st * 32768;
        uint32_t vstg = sb + FL_VST + (uint32_t)st * 32768;
#pragma unroll
        for (int i = 0; i < 4; i++) {
            int idx = tid + (i << 8);
            int row = idx >> 3, c16 = idx & 7;
            uint32_t d = SWZ((uint32_t)(row * 128 + c16 * 16));
            long so = kb0 + (long)(c * 128 + row) * QKVN + c16 * 8;
            CP16(kstg + d, QKVhi + so, 16);
            CP16(kstg + 16384 + d, QKVlo + so, 16);
        }
#pragma unroll
        for (int i = 0; i < 4; i++) {
            int idx = tid + (i << 8);
            int row = idx >> 3, c16 = idx & 7;
            uint32_t d = SWZ((uint32_t)(row * 128 + c16 * 16));
            long so = vb0 + (long)(c * 128 + row) * QKVN + c16 * 8;
            CP16(vstg + d, QKVhi + so, 16);
            CP16(vstg + 16384 + d, QKVlo + so, 16);
        }
        CP_COMMIT();
    };

    load_q(); load_kv(0, 0);
    load_kv(1, 1);

    int wm = wid * 16;
    int lr = lid >> 2, lc = (lid & 3) * 2;
    int a_row = wm + (lid & 15), a_cb = (lid >> 4) << 4;
    int b_row8 = ((lid >> 4) << 3) + (lid & 7);
    int b_cb = ((lid >> 3) & 1) << 4;
    int v_soff = (lid & 7) + (((lid >> 3) & 1) << 3);
    int v_doff = ((lid >> 4) & 1) << 3;

    uint32_t qh[4][4], ql[4][4];
    float m0r = -1e30f, m1r = -1e30f, l0r = 0.f, l1r = 0.f;
    float acc_o[8][4] = {};

    for (int c = 0; c < 8; c++) {
        if (c < 7) asm volatile("cp.async.wait_group 1;" ::: "memory");
        else       asm volatile("cp.async.wait_group 0;" ::: "memory");
        __syncthreads();

        if (c == 0) {
#pragma unroll
            for (int ks = 0; ks < 4; ks++) {
                uint32_t o = SWZ((uint32_t)(a_row * 128 + ks * 32 + a_cb));
                ldsm4(qh[ks], sb + FL_QH + o);
                ldsm4(ql[ks], sb + FL_QL + o);
            }
        }
        uint32_t kstg = sb + FL_KST + (uint32_t)(c & 1) * 32768;
        uint32_t vstg = sb + FL_VST + (uint32_t)(c & 1) * 32768;

        float s_acc[16][4] = {};
#pragma unroll
        for (int ks = 0; ks < 4; ks++) {
            int kb = ks * 32;
            uint32_t kh[8][4], kl[8][4];
#pragma unroll
            for (int g = 0; g < 8; g++) {
                uint32_t o = SWZ((uint32_t)((g * 16 + b_row8) * 128 + kb + b_cb));
                ldsm4(kh[g], kstg + o);
                ldsm4(kl[g], kstg + 16384 + o);
            }
#pragma unroll
            for (int nt = 0; nt < 16; nt++) {
                int g = nt >> 1, pr = (nt & 1) * 2;
                mma_bf16(s_acc[nt], qh[ks], kh[g][pr], kh[g][pr + 1]);
                mma_bf16(s_acc[nt], qh[ks], kl[g][pr], kl[g][pr + 1]);
                mma_bf16(s_acc[nt], ql[ks], kh[g][pr], kh[g][pr + 1]);
            }
        }

        float t0 = -1e30f, t1 = -1e30f;
#pragma unroll
        for (int nt = 0; nt < 16; nt++) {
#pragma unroll
            for (int j = 0; j < 4; j++) s_acc[nt][j] *= 0.125f;
            t0 = fmaxf(t0, fmaxf(s_acc[nt][0], s_acc[nt][1]));
            t1 = fmaxf(t1, fmaxf(s_acc[nt][2], s_acc[nt][3]));
        }
#pragma unroll
        for (int o = 1; o <= 2; o <<= 1) {
            t0 = fmaxf(t0, __shfl_xor_sync(0xffffffffu, t0, o));
            t1 = fmaxf(t1, __shfl_xor_sync(0xffffffffu, t1, o));
        }
        float mn0 = fmaxf(m0r, t0), mn1 = fmaxf(m1r, t1);
        float cor0 = expf(m0r - mn0), cor1 = expf(m1r - mn1);
        float rs0 = 0.f, rs1 = 0.f;
#pragma unroll
        for (int nt = 0; nt < 16; nt++) {
            s_acc[nt][0] = expf(s_acc[nt][0] - mn0);
            s_acc[nt][1] = expf(s_acc[nt][1] - mn0);
            s_acc[nt][2] = expf(s_acc[nt][2] - mn1);
            s_acc[nt][3] = expf(s_acc[nt][3] - mn1);
            rs0 += s_acc[nt][0] + s_acc[nt][1];
            rs1 += s_acc[nt][2] + s_acc[nt][3];
        }
#pragma unroll
        for (int o = 1; o <= 2; o <<= 1) {
            rs0 += __shfl_xor_sync(0xffffffffu, rs0, o);
            rs1 += __shfl_xor_sync(0xffffffffu, rs1, o);
        }
        l0r = l0r * cor0 + rs0; l1r = l1r * cor1 + rs1;
        m0r = mn0; m1r = mn1;
#pragma unroll
        for (int nt = 0; nt < 8; nt++) {
            acc_o[nt][0] *= cor0; acc_o[nt][1] *= cor0;
            acc_o[nt][2] *= cor1; acc_o[nt][3] *= cor1;
        }

#pragma unroll
        for (int kt = 0; kt < 8; kt++) {
            uint32_t ah[4], al[4];
            split2(s_acc[2 * kt][0],     s_acc[2 * kt][1],     ah[0], al[0]);
            split2(s_acc[2 * kt][2],     s_acc[2 * kt][3],     ah[1], al[1]);
            split2(s_acc[2 * kt + 1][0], s_acc[2 * kt + 1][1], ah[2], al[2]);
            split2(s_acc[2 * kt + 1][2], s_acc[2 * kt + 1][3], ah[3], al[3]);
            uint32_t vh[4][4], vl[4][4];
#pragma unroll
            for (int g = 0; g < 4; g++) {
                uint32_t o = SWZ((uint32_t)((kt * 16 + v_soff) * 128 +
                                            (g * 16 + v_doff) * 2));
                ldsm4t(vh[g], vstg + o);
                ldsm4t(vl[g], vstg + 16384 + o);
            }
#pragma unroll
            for (int nt = 0; nt < 8; nt++) {
                int g = nt >> 1, pr = (nt & 1) * 2;
                mma_bf16(acc_o[nt], ah, vh[g][pr], vh[g][pr + 1]);
                mma_bf16(acc_o[nt], ah, vl[g][pr], vl[g][pr + 1]);
                mma_bf16(acc_o[nt], al, vh[g][pr], vh[g][pr + 1]);
            }
        }
        __syncthreads();
        if (c + 2 < 8) load_kv(c + 2, c & 1);
    }

    float inv0 = 1.f / l0r, inv1 = 1.f / l1r;
    long r0g = obase + (long)(wm + lr) * Dc;
    long r1g = obase + (long)(wm + lr + 8) * Dc;
#pragma unroll
    for (int nt = 0; nt < 8; nt++) {
        int gc = nt * 8 + lc;
        uint32_t hi, lo;
        split2(acc_o[nt][0] * inv0, acc_o[nt][1] * inv0, hi, lo);
        *(uint32_t*)&Ohi[r0g + gc] = hi;
        *(uint32_t*)&Olo[r0g + gc] = lo;
        split2(acc_o[nt][2] * inv1, acc_o[nt][3] * inv1, hi, lo);
        *(uint32_t*)&Ohi[r1g + gc] = hi;
        *(uint32_t*)&Olo[r1g + gc] = lo;
    }
}

// ================= transpose + split convert ================================
__global__ void tconv(const float* __restrict__ in, bf16* __restrict__ ohi,
                      bf16* __restrict__ olo, int R, int Ccol, long sin, long sout)
{
    __shared__ float t[32][33];
    long ib = (long)blockIdx.z * sin, ob = (long)blockIdx.z * sout;
    int c0 = blockIdx.x * 32, r0 = blockIdx.y * 32;
    int tx = threadIdx.x, ty = threadIdx.y;
#pragma unroll
    for (int j = 0; j < 4; j++)
        t[ty + j * 8][tx] = in[ib + (long)(r0 + ty + j * 8) * Ccol + c0 + tx];
    __syncthreads();
#pragma unroll
    for (int j = 0; j < 4; j++) {
        float v = t[tx][ty + j * 8];
        bf16 h = __float2bfloat16(v);
        long o = ob + (long)(c0 + ty + j * 8) * R + r0 + tx;
        ohi[o] = h;
        olo[o] = __float2bfloat16(v - __bfloat162float(h));
    }
}

// ================= elementwise kernels ======================================
__global__ void copy_k(const float* __restrict__ a, float* __restrict__ o) {
    long i = (long)blockIdx.x * 256 + threadIdx.x;
    o[i] = a[i];
}

__global__ void ln_k(const float* __restrict__ x, const float* __restrict__ w,
                     const float* __restrict__ b, float* __restrict__ out,
                     bf16* __restrict__ ohi, bf16* __restrict__ olo, int zeroCnt) {
    int row = blockIdx.x;
    int tid = threadIdx.x;
    if (zeroCnt && row == 0 && tid < Ec) g_cnt[tid] = 0;
    const float* xr = x + (long)row * Dc;
    float4 v = *(const float4*)&xr[tid * 4];
    float s = v.x + v.y + v.z + v.w;
    float s2 = v.x * v.x + v.y * v.y + v.z * v.z + v.w * v.w;
    __shared__ float sh[4], sh2[4];
#pragma unroll
    for (int o = 16; o > 0; o >>= 1) {
        s  += __shfl_xor_sync(0xffffffffu, s, o);
        s2 += __shfl_xor_sync(0xffffffffu, s2, o);
    }
    if ((tid & 31) == 0) { sh[tid >> 5] = s; sh2[tid >> 5] = s2; }
    __syncthreads();
    float a = 0.f, a2 = 0.f;
#pragma unroll
    for (int i = 0; i < 4; i++) { a += sh[i]; a2 += sh2[i]; }
    float mu  = a * (1.f / Dc);
    float var = a2 * (1.f / Dc) - mu * mu;
    float inv = rsqrtf(var + 1e-6f);
    int d = tid * 4;
    const float4 wv = *(const float4*)&w[d];
    const float4 bv = *(const float4*)&b[d];
    float y0 = (v.x - mu) * inv * wv.x + bv.x;
    float y1 = (v.y - mu) * inv * wv.y + bv.y;
    float y2 = (v.z - mu) * inv * wv.z + bv.z;
    float y3 = (v.w - mu) * inv * wv.w + bv.w;
    long idx = (long)row * Dc + d;
    *(float4*)&out[idx] = make_float4(y0, y1, y2, y3);
    uint32_t h0, l0, h1, l1;
    split2(y0, y1, h0, l0); split2(y2, y3, h1, l1);
    *(uint32_t*)&ohi[idx] = h0; *(uint32_t*)&ohi[idx + 2] = h1;
    *(uint32_t*)&olo[idx] = l0; *(uint32_t*)&olo[idx + 2] = l1;
}

__global__ void gate_k(const float* __restrict__ h, const float* __restrict__ gw) {
    int t = blockIdx.x * 4 + (threadIdx.x >> 5);
    int lid = threadIdx.x & 31;
    const float* hr = h + (long)t * Dc;
    float acc[Ec] = {};
    for (int d = lid; d < Dc; d += 32) {
        float hv = hr[d];
#pragma unroll
        for (int e = 0; e < Ec; e++) acc[e] += hv * gw[d * Ec + e];
    }
#pragma unroll
    for (int e = 0; e < Ec; e++)
#pragma unroll
        for (int o = 16; o > 0; o >>= 1)
            acc[e] += __shfl_xor_sync(0xffffffffu, acc[e], o);
    if (lid == 0) {
        int i0 = 0; float v0 = acc[0];
#pragma unroll
        for (int e = 1; e < Ec; e++) if (acc[e] > v0) { v0 = acc[e]; i0 = e; }
        int i1 = -1; float v1 = -3.4e38f;
#pragma unroll
        for (int e = 0; e < Ec; e++) if (e != i0 && acc[e] > v1) { v1 = acc[e]; i1 = e; }
        float g1 = 1.f / (1.f + expf(v0 - v1));
        g_topi[t * 2] = i0; g_topi[t * 2 + 1] = i1;
        g_gate[t * 2] = 1.f - g1; g_gate[t * 2 + 1] = g1;
        atomicAdd(&g_cnt[i0], 1);
        atomicAdd(&g_cnt[i1], 1);
    }
}

__global__ void offsets_k() {
    if (threadIdx.x == 0) {
        int o = 0;
        for (int e = 0; e < Ec; e++) { g_off[e] = o; g_cur[e] = o; o += g_cnt[e]; }
    }
}

__global__ void scatter_k() {
    int i = blockIdx.x * 256 + threadIdx.x;
    if (i >= 2 * Tc) return;
    int e = g_topi[i];
    int pos = atomicAdd(&g_cur[e], 1);
    g_tok[pos] = i;
}

__global__ void combine_k(float* __restrict__ x) {
    int i = blockIdx.x * 256 + threadIdx.x;
    int t = i >> 9;
    int d = i & 511;
    x[i] += g_gate[t * 2] * g_ybuf[(long)(t * 2) * Dc + d]
          + g_gate[t * 2 + 1] * g_ybuf[(long)(t * 2 + 1) * Dc + d];
}

// ================= host =====================================================
extern "C" void kernel_launch(void* const* d_in, const int* in_sizes, int n_in,
                              void* d_out, int out_size)
{
    const float* x      = (const float*)d_in[0];
    const float* ln1_w  = (const float*)d_in[1];
    const float* ln1_b  = (const float*)d_in[2];
    const float* wq     = (const float*)d_in[3];
    const float* wk     = (const float*)d_in[4];
    const float* wv     = (const float*)d_in[5];
    const float* wo     = (const float*)d_in[6];
    const float* bo     = (const float*)d_in[7];
    const float* ln2_w  = (const float*)d_in[8];
    const float* ln2_b  = (const float*)d_in[9];
    const float* gate_w = (const float*)d_in[10];
    const float* w1     = (const float*)d_in[11];
    const float* b1     = (const float*)d_in[12];
    const float* w2     = (const float*)d_in[13];
    const float* b2     = (const float*)d_in[14];
    float* out = (float*)d_out;

    float *ph, *pyb;
    bf16 *ph_hi, *ph_lo, *pqkv_hi, *pqkv_lo, *pao_hi, *pao_lo, *phm_hi, *phm_lo;
    bf16 *wqkvt_hi, *wqkvt_lo, *wot_hi, *wot_lo, *w1t_hi, *w1t_lo, *w2t_hi, *w2t_lo;
    cudaGetSymbolAddress((void**)&ph, g_h);
    cudaGetSymbolAddress((void**)&pyb, g_ybuf);
    cudaGetSymbolAddress((void**)&ph_hi, g_h_hi);   cudaGetSymbolAddress((void**)&ph_lo, g_h_lo);
    cudaGetSymbolAddress((void**)&pqkv_hi, g_qkv_hi); cudaGetSymbolAddress((void**)&pqkv_lo, g_qkv_lo);
    cudaGetSymbolAddress((void**)&pao_hi, g_ao_hi); cudaGetSymbolAddress((void**)&pao_lo, g_ao_lo);
    cudaGetSymbolAddress((void**)&phm_hi, g_hm_hi); cudaGetSymbolAddress((void**)&phm_lo, g_hm_lo);
    cudaGetSymbolAddress((void**)&wqkvt_hi, g_wqkvt_hi); cudaGetSymbolAddress((void**)&wqkvt_lo, g_wqkvt_lo);
    cudaGetSymbolAddress((void**)&wot_hi, g_wot_hi); cudaGetSymbolAddress((void**)&wot_lo, g_wot_lo);
    cudaGetSymbolAddress((void**)&w1t_hi, g_w1t_hi); cudaGetSymbolAddress((void**)&w1t_lo, g_w1t_lo);
    cudaGetSymbolAddress((void**)&w2t_hi, g_w2t_hi); cudaGetSymbolAddress((void**)&w2t_lo, g_w2t_lo);

    cudaFuncSetAttribute(tgemm<1, 0>, cudaFuncAttributeMaxDynamicSharedMemorySize, S128);
    cudaFuncSetAttribute(tgemm<4, 0>, cudaFuncAttributeMaxDynamicSharedMemorySize, S128);
    cudaFuncSetAttribute(tgemm<2, 1>, cudaFuncAttributeMaxDynamicSharedMemorySize, S128);
    cudaFuncSetAttribute(tgemm<3, 2>, cudaFuncAttributeMaxDynamicSharedMemorySize, S128);
    cudaFuncSetAttribute(flash_k, cudaFuncAttributeMaxDynamicSharedMemorySize, FL_SMEM);

    cudaStream_t s1;
    cudaStreamCreateWithFlags(&s1, cudaStreamNonBlocking);
    cudaEvent_t eFork, eQKV[Lc], eWO[Lc], eMOE[Lc];
    cudaEventCreateWithFlags(&eFork, cudaEventDisableTiming);
    for (int l = 0; l < Lc; l++) {
        cudaEventCreateWithFlags(&eQKV[l], cudaEventDisableTiming);
        cudaEventCreateWithFlags(&eWO[l], cudaEventDisableTiming);
        cudaEventCreateWithFlags(&eMOE[l], cudaEventDisableTiming);
    }

    dim3 tcb(32, 8);
    cudaEventRecord(eFork, 0);
    cudaStreamWaitEvent(s1, eFork, 0);
    for (int l = 0; l < Lc; l++) {
        bf16* qt_hi = wqkvt_hi + (long)l * QKVN * Dc;
        bf16* qt_lo = wqkvt_lo + (long)l * QKVN * Dc;
        tconv<<<dim3(16, 16, 1), tcb, 0, s1>>>(wq + (long)l * Dc * Dc, qt_hi, qt_lo, Dc, Dc, 0, 0);
        tconv<<<dim3(16, 16, 1), tcb, 0, s1>>>(wk + (long)l * Dc * Dc, qt_hi + 512 * Dc, qt_lo + 512 * Dc, Dc, Dc, 0, 0);
        tconv<<<dim3(16, 16, 1), tcb, 0, s1>>>(wv + (long)l * Dc * Dc, qt_hi + 1024 * Dc, qt_lo + 1024 * Dc, Dc, Dc, 0, 0);
        cudaEventRecord(eQKV[l], s1);
        tconv<<<dim3(16, 16, 1), tcb, 0, s1>>>(wo + (long)l * Dc * Dc,
            wot_hi + (long)l * Dc * Dc, wot_lo + (long)l * Dc * Dc, Dc, Dc, 0, 0);
        cudaEventRecord(eWO[l], s1);
        tconv<<<dim3(DHc / 32, Dc / 32, Ec), tcb, 0, s1>>>(
            w1 + (long)l * Ec * Dc * DHc,
            w1t_hi + (long)l * Ec * Dc * DHc, w1t_lo + (long)l * Ec * Dc * DHc,
            Dc, DHc, (long)Dc * DHc, (long)Dc * DHc);
        tconv<<<dim3(Dc / 32, DHc / 32, Ec), tcb, 0, s1>>>(
            w2 + (long)l * Ec * DHc * Dc,
            w2t_hi + (long)l * Ec * DHc * Dc, w2t_lo + (long)l * Ec * DHc * Dc,
            DHc, Dc, (long)DHc * Dc, (long)DHc * Dc);
        cudaEventRecord(eMOE[l], s1);
    }

    copy_k<<<Tc * Dc / 256, 256>>>(x, out);

    for (int l = 0; l < Lc; l++) {
        bf16* qt_hi = wqkvt_hi + (long)l * QKVN * Dc;
        bf16* qt_lo = wqkvt_lo + (long)l * QKVN * Dc;

        ln_k<<<Tc, 128>>>(out, ln1_w + l * Dc, ln1_b + l * Dc, ph, ph_hi, ph_lo, 0);

        cudaStreamWaitEvent(0, eQKV[l], 0);
        tgemm<4, 0><<<dim3(QKVN / 128, 32, 1), 256, S128>>>(
            Dc, ph_hi, ph_lo, Dc, qt_hi, qt_lo, Dc,
            nullptr, pqkv_hi, pqkv_lo, QKVN, nullptr, 0, 0);

        flash_k<<<dim3(Sc / 128, Bc * Hc), 256, FL_SMEM>>>(
            pqkv_hi, pqkv_lo, pao_hi, pao_lo);

        cudaStreamWaitEvent(0, eWO[l], 0);
        tgemm<1, 0><<<dim3(4, 32, 1), 256, S128>>>(
            Dc, pao_hi, pao_lo, Dc,
            wot_hi + (long)l * Dc * Dc, wot_lo + (long)l * Dc * Dc, Dc,
            out, nullptr, nullptr, Dc, bo + l * Dc, 0, 0);

        ln_k<<<Tc, 128>>>(out, ln2_w + l * Dc, ln2_b + l * Dc, ph, ph_hi, ph_lo, 1);

        gate_k<<<Tc / 4, 128>>>(ph, gate_w + (long)l * Dc * Ec);
        offsets_k<<<1, 1>>>();
        scatter_k<<<2 * Tc / 256, 256>>>();

        cudaStreamWaitEvent(0, eMOE[l], 0);
        tgemm<2, 1><<<dim3(16, 64, Ec), 256, S128>>>(
            Dc, ph_hi, ph_lo, Dc,
            w1t_hi + (long)l * Ec * Dc * DHc, w1t_lo + (long)l * Ec * Dc * DHc, Dc,
            nullptr, phm_hi, phm_lo, DHc,
            b1 + (long)l * Ec * DHc, (long)Dc * DHc, DHc);
        tgemm<3, 2><<<dim3(4, 64, Ec), 256, S128>>>(
            DHc, phm_hi, phm_lo, DHc,
            w2t_hi + (long)l * Ec * DHc * Dc, w2t_lo + (long)l * Ec * DHc * Dc, DHc,
            pyb, nullptr, nullptr, Dc,
            b2 + (long)l * Ec * Dc, (long)DHc * Dc, Dc);

        combine_k<<<Tc * Dc / 256, 256>>>(out);
    }
}

// round 8
// speedup vs baseline: 5.8812x; 1.8792x over previous
#include <cuda_runtime.h>
#include <cuda_fp16.h>
#include <math.h>
#include <stdint.h>

#define Tc 4096
#define Dc 512
#define Sc 1024
#define Bc 4
#define Hc 8
#define HEADc 64
#define Ec 8
#define DHc 2048
#define Lc 2
#define QKVN 1536

typedef __half half_t;

// ---------------- scratch (device globals) ---------------------------------
__device__ float  g_h[Tc * Dc];
__device__ half_t g_h16[Tc * Dc];
__device__ half_t g_qkv16[(size_t)Tc * QKVN];
__device__ half_t g_ao16[Tc * Dc];
__device__ half_t g_hm16[(size_t)2 * Tc * DHc];
__device__ float  g_ybuf[(size_t)2 * Tc * Dc];
__device__ half_t g_wqkvt16[(size_t)Lc * QKVN * Dc];
__device__ half_t g_wot16[Lc * Dc * Dc];
__device__ half_t g_w1t16[(size_t)Lc * Ec * Dc * DHc];
__device__ half_t g_w2t16[(size_t)Lc * Ec * Dc * DHc];
__device__ float  g_gate[Tc * 2];
__device__ int    g_topi[Tc * 2];
__device__ int    g_cnt[Ec], g_cur[Ec], g_off[Ec];
__device__ int    g_tok[2 * Tc];

// ================= low-level helpers ========================================
__device__ __forceinline__ uint32_t smem_u32(const void* p) {
    uint32_t a;
    asm("{ .reg .u64 t; cvta.to.shared.u64 t, %1; cvt.u32.u64 %0, t; }"
        : "=r"(a) : "l"(p));
    return a;
}
#define SWZ(o) ((o) ^ (((o) >> 3) & 0x70))
#define CP16(dst, src, sz) \
    asm volatile("cp.async.cg.shared.global [%0], [%1], 16, %2;" \
                 :: "r"(dst), "l"(src), "r"(sz) : "memory")
#define CP_COMMIT() asm volatile("cp.async.commit_group;" ::: "memory")

__device__ __forceinline__ void ldsm4(uint32_t* r, uint32_t addr) {
    asm volatile("ldmatrix.sync.aligned.m8n8.x4.shared.b16 {%0,%1,%2,%3}, [%4];"
                 : "=r"(r[0]), "=r"(r[1]), "=r"(r[2]), "=r"(r[3]) : "r"(addr));
}
__device__ __forceinline__ void ldsm4t(uint32_t* r, uint32_t addr) {
    asm volatile("ldmatrix.sync.aligned.m8n8.x4.trans.shared.b16 {%0,%1,%2,%3}, [%4];"
                 : "=r"(r[0]), "=r"(r[1]), "=r"(r[2]), "=r"(r[3]) : "r"(addr));
}
__device__ __forceinline__ void mma_f16(float* d, const uint32_t* a,
                                        uint32_t b0, uint32_t b1) {
    asm volatile(
        "mma.sync.aligned.m16n8k16.row.col.f32.f16.f16.f32 "
        "{%0,%1,%2,%3}, {%4,%5,%6,%7}, {%8,%9}, {%0,%1,%2,%3};"
        : "+f"(d[0]), "+f"(d[1]), "+f"(d[2]), "+f"(d[3])
        : "r"(a[0]), "r"(a[1]), "r"(a[2]), "r"(a[3]), "r"(b0), "r"(b1));
}
__device__ __forceinline__ uint32_t pack2h(float x0, float x1) {
    __half2 h = __floats2half2_rn(x0, x1);
    return *(uint32_t*)&h;
}

// ================= pipelined fp16 tensor GEMM (2 CTAs/SM) ===================
// A: [*,K] K-major fp16.  B: [N,K] K-major fp16.  128x128 tile, K-chunk 64.
// Stage = 32KB (A 16KB + B 16KB), 2 stages.
// EPI: 1 fp32+bias+C(resid); 2 gelu(+bias)->fp16 grouped; 3 +bias->scatter fp32;
//      4 fp16 plain
// AMODE: 0 direct; 1 gather rows via g_tok>>1; 2 grouped rows off+m
#define TG_STG 32768u
#define TG_OB  16384u
#define TG_SMEM (2 * 32768 + 1024)
template <int EPI, int AMODE>
__global__ void __launch_bounds__(256, 2) tgemm(
    int K,
    const half_t* __restrict__ A, int lda,
    const half_t* __restrict__ B, int ldb,
    float* __restrict__ C, half_t* __restrict__ C16, int ldc,
    const float* __restrict__ bias, long wstride, long bstride)
{
    extern __shared__ char dsm[];
    __shared__ int stok_s[128];
    uint32_t sbb = smem_u32(dsm);
    uint32_t tb = (sbb + 1023) & ~1023u;
    int tid = threadIdx.x, wid = tid >> 5, lid = tid & 31;

    int cnt = 0, off = 0;
    if (AMODE != 0) {
        int e = blockIdx.z;
        cnt = g_cnt[e]; off = g_off[e];
        if ((int)blockIdx.y * 128 >= cnt) return;
        B += (long)e * wstride;
        bias += (long)e * bstride;
    }
    int m0 = blockIdx.y * 128, n0 = blockIdx.x * 128;

    if (AMODE == 1 && tid < 128) {
        int i = m0 + tid;
        stok_s[tid] = (i < cnt) ? (g_tok[off + i] >> 1) : -1;
    }
    if (AMODE == 2 && tid < 128) {
        int i = m0 + tid;
        stok_s[tid] = (i < cnt) ? g_tok[off + i] : -1;
    }
    if (AMODE != 0) __syncthreads();

    // stage loader: 128 rows x 64 fp16 (128B rows, SW128) for A and B
    auto load_stage = [&](int c, int st) {
        uint32_t base = tb + (uint32_t)st * TG_STG;
        int k0 = c << 6;
#pragma unroll
        for (int i = 0; i < 4; i++) {
            int idx = tid + (i << 8);
            int row = idx >> 3, c16 = idx & 7;
            uint32_t d = SWZ((uint32_t)(row * 128 + c16 * 16));
            long so; uint32_t sz = 16;
            if (AMODE == 0) so = (long)(m0 + row) * lda + k0 + c16 * 8;
            else if (AMODE == 1) {
                int tk = stok_s[row];
                if (tk < 0) { sz = 0; tk = 0; }
                so = (long)tk * lda + k0 + c16 * 8;
            } else {
                if (stok_s[row] < 0) { sz = 0; so = 0; }
                else so = (long)(off + m0 + row) * lda + k0 + c16 * 8;
            }
            CP16(base + d, A + so, sz);
        }
#pragma unroll
        for (int i = 0; i < 4; i++) {
            int idx = tid + (i << 8);
            int row = idx >> 3, c16 = idx & 7;
            uint32_t d = SWZ((uint32_t)(row * 128 + c16 * 16));
            long so = (long)(n0 + row) * ldb + k0 + c16 * 8;
            CP16(base + TG_OB + d, B + so, 16);
        }
        CP_COMMIT();
    };

    int wm = (wid >> 2) * 64, wn = (wid & 3) * 32;
    int a_row = wm + (lid & 15), a_cb = (lid >> 4) << 4;
    int b_row = wn + ((lid >> 4) << 3) + (lid & 7), b_cb = ((lid >> 3) & 1) << 4;
    float acc[4][4][4] = {};

    int nch = K >> 6;
    load_stage(0, 0);
    for (int c = 0; c < nch; c++) {
        if (c + 1 < nch) {
            load_stage(c + 1, (c + 1) & 1);
            asm volatile("cp.async.wait_group 1;" ::: "memory");
        } else {
            asm volatile("cp.async.wait_group 0;" ::: "memory");
        }
        __syncthreads();
        uint32_t base = tb + (uint32_t)(c & 1) * TG_STG;
#pragma unroll
        for (int ks = 0; ks < 4; ks++) {
            int kb = ks * 32;
            uint32_t bF[2][4];
#pragma unroll
            for (int g = 0; g < 2; g++) {
                uint32_t o = SWZ((uint32_t)((b_row + g * 16) * 128 + kb + b_cb));
                ldsm4(bF[g], base + TG_OB + o);
            }
#pragma unroll
            for (int mt = 0; mt < 4; mt++) {
                uint32_t aF[4];
                uint32_t o = SWZ((uint32_t)((a_row + mt * 16) * 128 + kb + a_cb));
                ldsm4(aF, base + o);
#pragma unroll
                for (int nt = 0; nt < 4; nt++) {
                    int g = nt >> 1, pr = (nt & 1) * 2;
                    mma_f16(acc[mt][nt], aF, bF[g][pr], bF[g][pr + 1]);
                }
            }
        }
        __syncthreads();
    }

    // ---- register epilogue ----
    int lr = lid >> 2, lc = (lid & 3) * 2;
#pragma unroll
    for (int mt = 0; mt < 4; mt++) {
#pragma unroll
        for (int half = 0; half < 2; half++) {
            int lrow = wm + mt * 16 + lr + half * 8;
            int grow = m0 + lrow;
#pragma unroll
            for (int nt = 0; nt < 4; nt++) {
                float v0 = acc[mt][nt][half * 2 + 0];
                float v1 = acc[mt][nt][half * 2 + 1];
                int gc = n0 + wn + nt * 8 + lc;
                if (EPI == 1) {
                    long idx = (long)grow * ldc + gc;
                    float2 old = *(const float2*)&C[idx];
                    *(float2*)&C[idx] = make_float2(v0 + bias[gc] + old.x,
                                                    v1 + bias[gc + 1] + old.y);
                } else if (EPI == 2) {
                    if (stok_s[lrow] >= 0) {
                        float t0 = v0 + bias[gc], t1 = v1 + bias[gc + 1];
                        float o0 = 0.5f * t0 * (1.f + erff(t0 * 0.70710678118654752f));
                        float o1 = 0.5f * t1 * (1.f + erff(t1 * 0.70710678118654752f));
                        long idx = (long)(off + grow) * ldc + gc;
                        *(uint32_t*)&C16[idx] = pack2h(o0, o1);
                    }
                } else if (EPI == 3) {
                    int ent = stok_s[lrow];
                    if (ent >= 0) {
                        *(float2*)&C[(long)ent * ldc + gc] =
                            make_float2(v0 + bias[gc], v1 + bias[gc + 1]);
                    }
                } else {  // EPI == 4
                    long idx = (long)grow * ldc + gc;
                    *(uint32_t*)&C16[idx] = pack2h(v0, v1);
                }
            }
        }
    }
}

// ================= fused flash attention (fp16) =============================
// grid: (S/128, B*H). 256 thr. QKV packed [T,1536] fp16.
#define FL_Q   0
#define FL_KST 16384
#define FL_VST 49152
#define FL_SMEM 81920
__global__ void __launch_bounds__(256, 1) flash_k(
    const half_t* __restrict__ QKV, half_t* __restrict__ O)
{
    extern __shared__ char dsm[];
    uint32_t sb = smem_u32(dsm);
    int tid = threadIdx.x, wid = tid >> 5, lid = tid & 31;
    int bh = blockIdx.y, b = bh >> 3, h = bh & 7;
    int q0 = blockIdx.x * 128;

    long qbase = (long)b * Sc * QKVN + (long)q0 * QKVN + h * HEADc;
    long kb0   = (long)b * Sc * QKVN + 512 + h * HEADc;
    long vb0   = (long)b * Sc * QKVN + 1024 + h * HEADc;
    long obase = (long)b * Sc * Dc + (long)q0 * Dc + h * HEADc;

    auto load_q = [&]() {
#pragma unroll
        for (int i = 0; i < 4; i++) {
            int idx = tid + (i << 8);
            int row = idx >> 3, c16 = idx & 7;
            uint32_t d = SWZ((uint32_t)(row * 128 + c16 * 16));
            CP16(sb + FL_Q + d, QKV + qbase + (long)row * QKVN + c16 * 8, 16);
        }
    };
    auto load_kv = [&](int c, int st) {
        uint32_t kstg = sb + FL_KST + (uint32_t)st * 16384;
        uint32_t vstg = sb + FL_VST + (uint32_t)st * 16384;
#pragma unroll
        for (int i = 0; i < 4; i++) {
            int idx = tid + (i << 8);
            int row = idx >> 3, c16 = idx & 7;
            uint32_t d = SWZ((uint32_t)(row * 128 + c16 * 16));
            CP16(kstg + d, QKV + kb0 + (long)(c * 128 + row) * QKVN + c16 * 8, 16);
        }
#pragma unroll
        for (int i = 0; i < 4; i++) {
            int idx = tid + (i << 8);
            int row = idx >> 3, c16 = idx & 7;
            uint32_t d = SWZ((uint32_t)(row * 128 + c16 * 16));
            CP16(vstg + d, QKV + vb0 + (long)(c * 128 + row) * QKVN + c16 * 8, 16);
        }
        CP_COMMIT();
    };

    load_q(); load_kv(0, 0);
    load_kv(1, 1);

    int wm = wid * 16;
    int lr = lid >> 2, lc = (lid & 3) * 2;
    int a_row = wm + (lid & 15), a_cb = (lid >> 4) << 4;
    int b_row8 = ((lid >> 4) << 3) + (lid & 7);
    int b_cb = ((lid >> 3) & 1) << 4;
    int v_soff = (lid & 7) + (((lid >> 3) & 1) << 3);
    int v_doff = ((lid >> 4) & 1) << 3;

    uint32_t qF[4][4];
    float m0r = -1e30f, m1r = -1e30f, l0r = 0.f, l1r = 0.f;
    float acc_o[8][4] = {};

    for (int c = 0; c < 8; c++) {
        if (c < 7) asm volatile("cp.async.wait_group 1;" ::: "memory");
        else       asm volatile("cp.async.wait_group 0;" ::: "memory");
        __syncthreads();

        if (c == 0) {
#pragma unroll
            for (int ks = 0; ks < 4; ks++) {
                uint32_t o = SWZ((uint32_t)(a_row * 128 + ks * 32 + a_cb));
                ldsm4(qF[ks], sb + FL_Q + o);
            }
        }
        uint32_t kstg = sb + FL_KST + (uint32_t)(c & 1) * 16384;
        uint32_t vstg = sb + FL_VST + (uint32_t)(c & 1) * 16384;

        // ---- S = Q K^T ----
        float s_acc[16][4] = {};
#pragma unroll
        for (int ks = 0; ks < 4; ks++) {
            int kb = ks * 32;
            uint32_t kF[8][4];
#pragma unroll
            for (int g = 0; g < 8; g++) {
                uint32_t o = SWZ((uint32_t)((g * 16 + b_row8) * 128 + kb + b_cb));
                ldsm4(kF[g], kstg + o);
            }
#pragma unroll
            for (int nt = 0; nt < 16; nt++) {
                int g = nt >> 1, pr = (nt & 1) * 2;
                mma_f16(s_acc[nt], qF[ks], kF[g][pr], kF[g][pr + 1]);
            }
        }

        // ---- online softmax (scale 1/8) ----
        float t0 = -1e30f, t1 = -1e30f;
#pragma unroll
        for (int nt = 0; nt < 16; nt++) {
#pragma unroll
            for (int j = 0; j < 4; j++) s_acc[nt][j] *= 0.125f;
            t0 = fmaxf(t0, fmaxf(s_acc[nt][0], s_acc[nt][1]));
            t1 = fmaxf(t1, fmaxf(s_acc[nt][2], s_acc[nt][3]));
        }
#pragma unroll
        for (int o = 1; o <= 2; o <<= 1) {
            t0 = fmaxf(t0, __shfl_xor_sync(0xffffffffu, t0, o));
            t1 = fmaxf(t1, __shfl_xor_sync(0xffffffffu, t1, o));
        }
        float mn0 = fmaxf(m0r, t0), mn1 = fmaxf(m1r, t1);
        float cor0 = expf(m0r - mn0), cor1 = expf(m1r - mn1);
        float rs0 = 0.f, rs1 = 0.f;
#pragma unroll
        for (int nt = 0; nt < 16; nt++) {
            s_acc[nt][0] = expf(s_acc[nt][0] - mn0);
            s_acc[nt][1] = expf(s_acc[nt][1] - mn0);
            s_acc[nt][2] = expf(s_acc[nt][2] - mn1);
            s_acc[nt][3] = expf(s_acc[nt][3] - mn1);
            rs0 += s_acc[nt][0] + s_acc[nt][1];
            rs1 += s_acc[nt][2] + s_acc[nt][3];
        }
#pragma unroll
        for (int o = 1; o <= 2; o <<= 1) {
            rs0 += __shfl_xor_sync(0xffffffffu, rs0, o);
            rs1 += __shfl_xor_sync(0xffffffffu, rs1, o);
        }
        l0r = l0r * cor0 + rs0; l1r = l1r * cor1 + rs1;
        m0r = mn0; m1r = mn1;
#pragma unroll
        for (int nt = 0; nt < 8; nt++) {
            acc_o[nt][0] *= cor0; acc_o[nt][1] *= cor0;
            acc_o[nt][2] *= cor1; acc_o[nt][3] *= cor1;
        }

        // ---- O += P V (V via trans-ldmatrix from [s,d] tiles) ----
#pragma unroll
        for (int kt = 0; kt < 8; kt++) {
            uint32_t aP[4];
            aP[0] = pack2h(s_acc[2 * kt][0],     s_acc[2 * kt][1]);
            aP[1] = pack2h(s_acc[2 * kt][2],     s_acc[2 * kt][3]);
            aP[2] = pack2h(s_acc[2 * kt + 1][0], s_acc[2 * kt + 1][1]);
            aP[3] = pack2h(s_acc[2 * kt + 1][2], s_acc[2 * kt + 1][3]);
            uint32_t vF[4][4];
#pragma unroll
            for (int g = 0; g < 4; g++) {
                uint32_t o = SWZ((uint32_t)((kt * 16 + v_soff) * 128 +
                                            (g * 16 + v_doff) * 2));
                ldsm4t(vF[g], vstg + o);
            }
#pragma unroll
            for (int nt = 0; nt < 8; nt++) {
                int g = nt >> 1, pr = (nt & 1) * 2;
                mma_f16(acc_o[nt], aP, vF[g][pr], vF[g][pr + 1]);
            }
        }
        __syncthreads();
        if (c + 2 < 8) load_kv(c + 2, c & 1);
    }

    // ---- epilogue ----
    float inv0 = 1.f / l0r, inv1 = 1.f / l1r;
    long r0g = obase + (long)(wm + lr) * Dc;
    long r1g = obase + (long)(wm + lr + 8) * Dc;
#pragma unroll
    for (int nt = 0; nt < 8; nt++) {
        int gc = nt * 8 + lc;
        *(uint32_t*)&O[r0g + gc] = pack2h(acc_o[nt][0] * inv0, acc_o[nt][1] * inv0);
        *(uint32_t*)&O[r1g + gc] = pack2h(acc_o[nt][2] * inv1, acc_o[nt][3] * inv1);
    }
}

// ================= transpose + fp16 convert ================================
__global__ void tconv(const float* __restrict__ in, half_t* __restrict__ o16,
                      int R, int Ccol, long sin, long sout)
{
    __shared__ float t[32][33];
    long ib = (long)blockIdx.z * sin, ob = (long)blockIdx.z * sout;
    int c0 = blockIdx.x * 32, r0 = blockIdx.y * 32;
    int tx = threadIdx.x, ty = threadIdx.y;
#pragma unroll
    for (int j = 0; j < 4; j++)
        t[ty + j * 8][tx] = in[ib + (long)(r0 + ty + j * 8) * Ccol + c0 + tx];
    __syncthreads();
#pragma unroll
    for (int j = 0; j < 4; j++) {
        float v = t[tx][ty + j * 8];
        o16[ob + (long)(c0 + ty + j * 8) * R + r0 + tx] = __float2half_rn(v);
    }
}

// ================= elementwise kernels ======================================
__global__ void copy_k(const float* __restrict__ a, float* __restrict__ o) {
    long i = (long)blockIdx.x * 256 + threadIdx.x;
    o[i] = a[i];
}

__global__ void ln_k(const float* __restrict__ x, const float* __restrict__ w,
                     const float* __restrict__ b, float* __restrict__ out,
                     half_t* __restrict__ o16, int zeroCnt) {
    int row = blockIdx.x;
    int tid = threadIdx.x;
    if (zeroCnt && row == 0 && tid < Ec) g_cnt[tid] = 0;
    const float* xr = x + (long)row * Dc;
    float4 v = *(const float4*)&xr[tid * 4];
    float s = v.x + v.y + v.z + v.w;
    float s2 = v.x * v.x + v.y * v.y + v.z * v.z + v.w * v.w;
    __shared__ float sh[4], sh2[4];
#pragma unroll
    for (int o = 16; o > 0; o >>= 1) {
        s  += __shfl_xor_sync(0xffffffffu, s, o);
        s2 += __shfl_xor_sync(0xffffffffu, s2, o);
    }
    if ((tid & 31) == 0) { sh[tid >> 5] = s; sh2[tid >> 5] = s2; }
    __syncthreads();
    float a = 0.f, a2 = 0.f;
#pragma unroll
    for (int i = 0; i < 4; i++) { a += sh[i]; a2 += sh2[i]; }
    float mu  = a * (1.f / Dc);
    float var = a2 * (1.f / Dc) - mu * mu;
    float inv = rsqrtf(var + 1e-6f);
    int d = tid * 4;
    const float4 wv = *(const float4*)&w[d];
    const float4 bv = *(const float4*)&b[d];
    float y0 = (v.x - mu) * inv * wv.x + bv.x;
    float y1 = (v.y - mu) * inv * wv.y + bv.y;
    float y2 = (v.z - mu) * inv * wv.z + bv.z;
    float y3 = (v.w - mu) * inv * wv.w + bv.w;
    long idx = (long)row * Dc + d;
    *(float4*)&out[idx] = make_float4(y0, y1, y2, y3);
    *(uint32_t*)&o16[idx] = pack2h(y0, y1);
    *(uint32_t*)&o16[idx + 2] = pack2h(y2, y3);
}

__global__ void gate_k(const float* __restrict__ h, const float* __restrict__ gw) {
    int t = blockIdx.x * 4 + (threadIdx.x >> 5);
    int lid = threadIdx.x & 31;
    const float* hr = h + (long)t * Dc;
    float acc[Ec] = {};
    for (int d = lid; d < Dc; d += 32) {
        float hv = hr[d];
#pragma unroll
        for (int e = 0; e < Ec; e++) acc[e] += hv * gw[d * Ec + e];
    }
#pragma unroll
    for (int e = 0; e < Ec; e++)
#pragma unroll
        for (int o = 16; o > 0; o >>= 1)
            acc[e] += __shfl_xor_sync(0xffffffffu, acc[e], o);
    if (lid == 0) {
        int i0 = 0; float v0 = acc[0];
#pragma unroll
        for (int e = 1; e < Ec; e++) if (acc[e] > v0) { v0 = acc[e]; i0 = e; }
        int i1 = -1; float v1 = -3.4e38f;
#pragma unroll
        for (int e = 0; e < Ec; e++) if (e != i0 && acc[e] > v1) { v1 = acc[e]; i1 = e; }
        float g1 = 1.f / (1.f + expf(v0 - v1));
        g_topi[t * 2] = i0; g_topi[t * 2 + 1] = i1;
        g_gate[t * 2] = 1.f - g1; g_gate[t * 2 + 1] = g1;
        atomicAdd(&g_cnt[i0], 1);
        atomicAdd(&g_cnt[i1], 1);
    }
}

__global__ void offsets_k() {
    if (threadIdx.x == 0) {
        int o = 0;
        for (int e = 0; e < Ec; e++) { g_off[e] = o; g_cur[e] = o; o += g_cnt[e]; }
    }
}

__global__ void scatter_k() {
    int i = blockIdx.x * 256 + threadIdx.x;
    if (i >= 2 * Tc) return;
    int e = g_topi[i];
    int pos = atomicAdd(&g_cur[e], 1);
    g_tok[pos] = i;
}

__global__ void combine_k(float* __restrict__ x) {
    int i = blockIdx.x * 256 + threadIdx.x;
    int t = i >> 9;
    int d = i & 511;
    x[i] += g_gate[t * 2] * g_ybuf[(long)(t * 2) * Dc + d]
          + g_gate[t * 2 + 1] * g_ybuf[(long)(t * 2 + 1) * Dc + d];
}

// ================= host =====================================================
extern "C" void kernel_launch(void* const* d_in, const int* in_sizes, int n_in,
                              void* d_out, int out_size)
{
    const float* x      = (const float*)d_in[0];
    const float* ln1_w  = (const float*)d_in[1];
    const float* ln1_b  = (const float*)d_in[2];
    const float* wq     = (const float*)d_in[3];
    const float* wk     = (const float*)d_in[4];
    const float* wv     = (const float*)d_in[5];
    const float* wo     = (const float*)d_in[6];
    const float* bo     = (const float*)d_in[7];
    const float* ln2_w  = (const float*)d_in[8];
    const float* ln2_b  = (const float*)d_in[9];
    const float* gate_w = (const float*)d_in[10];
    const float* w1     = (const float*)d_in[11];
    const float* b1     = (const float*)d_in[12];
    const float* w2     = (const float*)d_in[13];
    const float* b2     = (const float*)d_in[14];
    float* out = (float*)d_out;

    float *ph, *pyb;
    half_t *ph16, *pqkv16, *pao16, *phm16;
    half_t *wqkvt16, *wot16, *w1t16, *w2t16;
    cudaGetSymbolAddress((void**)&ph, g_h);
    cudaGetSymbolAddress((void**)&pyb, g_ybuf);
    cudaGetSymbolAddress((void**)&ph16, g_h16);
    cudaGetSymbolAddress((void**)&pqkv16, g_qkv16);
    cudaGetSymbolAddress((void**)&pao16, g_ao16);
    cudaGetSymbolAddress((void**)&phm16, g_hm16);
    cudaGetSymbolAddress((void**)&wqkvt16, g_wqkvt16);
    cudaGetSymbolAddress((void**)&wot16, g_wot16);
    cudaGetSymbolAddress((void**)&w1t16, g_w1t16);
    cudaGetSymbolAddress((void**)&w2t16, g_w2t16);

    cudaFuncSetAttribute(tgemm<1, 0>, cudaFuncAttributeMaxDynamicSharedMemorySize, TG_SMEM);
    cudaFuncSetAttribute(tgemm<4, 0>, cudaFuncAttributeMaxDynamicSharedMemorySize, TG_SMEM);
    cudaFuncSetAttribute(tgemm<2, 1>, cudaFuncAttributeMaxDynamicSharedMemorySize, TG_SMEM);
    cudaFuncSetAttribute(tgemm<3, 2>, cudaFuncAttributeMaxDynamicSharedMemorySize, TG_SMEM);
    cudaFuncSetAttribute(flash_k, cudaFuncAttributeMaxDynamicSharedMemorySize, FL_SMEM);

    cudaStream_t s1;
    cudaStreamCreateWithFlags(&s1, cudaStreamNonBlocking);
    cudaEvent_t eFork, eQKV[Lc], eWO[Lc], eMOE[Lc];
    cudaEventCreateWithFlags(&eFork, cudaEventDisableTiming);
    for (int l = 0; l < Lc; l++) {
        cudaEventCreateWithFlags(&eQKV[l], cudaEventDisableTiming);
        cudaEventCreateWithFlags(&eWO[l], cudaEventDisableTiming);
        cudaEventCreateWithFlags(&eMOE[l], cudaEventDisableTiming);
    }

    dim3 tcb(32, 8);
    cudaEventRecord(eFork, 0);
    cudaStreamWaitEvent(s1, eFork, 0);
    for (int l = 0; l < Lc; l++) {
        half_t* qt = wqkvt16 + (long)l * QKVN * Dc;
        tconv<<<dim3(16, 16, 1), tcb, 0, s1>>>(wq + (long)l * Dc * Dc, qt, Dc, Dc, 0, 0);
        tconv<<<dim3(16, 16, 1), tcb, 0, s1>>>(wk + (long)l * Dc * Dc, qt + 512 * Dc, Dc, Dc, 0, 0);
        tconv<<<dim3(16, 16, 1), tcb, 0, s1>>>(wv + (long)l * Dc * Dc, qt + 1024 * Dc, Dc, Dc, 0, 0);
        cudaEventRecord(eQKV[l], s1);
        tconv<<<dim3(16, 16, 1), tcb, 0, s1>>>(wo + (long)l * Dc * Dc,
            wot16 + (long)l * Dc * Dc, Dc, Dc, 0, 0);
        cudaEventRecord(eWO[l], s1);
        tconv<<<dim3(DHc / 32, Dc / 32, Ec), tcb, 0, s1>>>(
            w1 + (long)l * Ec * Dc * DHc, w1t16 + (long)l * Ec * Dc * DHc,
            Dc, DHc, (long)Dc * DHc, (long)Dc * DHc);
        tconv<<<dim3(Dc / 32, DHc / 32, Ec), tcb, 0, s1>>>(
            w2 + (long)l * Ec * DHc * Dc, w2t16 + (long)l * Ec * DHc * Dc,
            DHc, Dc, (long)DHc * Dc, (long)DHc * Dc);
        cudaEventRecord(eMOE[l], s1);
    }

    copy_k<<<Tc * Dc / 256, 256>>>(x, out);

    for (int l = 0; l < Lc; l++) {
        half_t* qt = wqkvt16 + (long)l * QKVN * Dc;

        ln_k<<<Tc, 128>>>(out, ln1_w + l * Dc, ln1_b + l * Dc, ph, ph16, 0);

        cudaStreamWaitEvent(0, eQKV[l], 0);
        tgemm<4, 0><<<dim3(QKVN / 128, 32, 1), 256, TG_SMEM>>>(
            Dc, ph16, Dc, qt, Dc,
            nullptr, pqkv16, QKVN, nullptr, 0, 0);

        flash_k<<<dim3(Sc / 128, Bc * Hc), 256, FL_SMEM>>>(pqkv16, pao16);

        cudaStreamWaitEvent(0, eWO[l], 0);
        tgemm<1, 0><<<dim3(4, 32, 1), 256, TG_SMEM>>>(
            Dc, pao16, Dc, wot16 + (long)l * Dc * Dc, Dc,
            out, nullptr, Dc, bo + l * Dc, 0, 0);

        ln_k<<<Tc, 128>>>(out, ln2_w + l * Dc, ln2_b + l * Dc, ph, ph16, 1);

        gate_k<<<Tc / 4, 128>>>(ph, gate_w + (long)l * Dc * Ec);
        offsets_k<<<1, 1>>>();
        scatter_k<<<2 * Tc / 256, 256>>>();

        cudaStreamWaitEvent(0, eMOE[l], 0);
        tgemm<2, 1><<<dim3(16, 64, Ec), 256, TG_SMEM>>>(
            Dc, ph16, Dc, w1t16 + (long)l * Ec * Dc * DHc, Dc,
            nullptr, phm16, DHc,
            b1 + (long)l * Ec * DHc, (long)Dc * DHc, DHc);
        tgemm<3, 2><<<dim3(4, 64, Ec), 256, TG_SMEM>>>(
            DHc, phm16, DHc, w2t16 + (long)l * Ec * DHc * Dc, DHc,
            pyb, nullptr, Dc,
            b2 + (long)l * Ec * Dc, (long)DHc * Dc, Dc);

        combine_k<<<Tc * Dc / 256, 256>>>(out);
    }
}

// round 9
// speedup vs baseline: 6.0863x; 1.0349x over previous
#include <cuda_runtime.h>
#include <cuda_fp16.h>
#include <math.h>
#include <stdint.h>

#define Tc 4096
#define Dc 512
#define Sc 1024
#define Bc 4
#define Hc 8
#define HEADc 64
#define Ec 8
#define DHc 2048
#define Lc 2
#define QKVN 1536
#define MAXBLK 72

typedef __half half_t;

// ---------------- scratch (device globals) ---------------------------------
__device__ float  g_h[Tc * Dc];
__device__ half_t g_h16[Tc * Dc];
__device__ half_t g_qkv16[(size_t)Tc * QKVN];
__device__ half_t g_ao16[Tc * Dc];
__device__ half_t g_hm16[(size_t)2 * Tc * DHc];
__device__ half_t g_wqkvt16[(size_t)Lc * QKVN * Dc];
__device__ half_t g_wot16[Lc * Dc * Dc];
__device__ half_t g_w1t16[(size_t)Lc * Ec * Dc * DHc];
__device__ half_t g_w2t16[(size_t)Lc * Ec * Dc * DHc];
__device__ float  g_gate[Tc * 2];
__device__ int    g_topi[Tc * 2];
__device__ int    g_cnt[Ec], g_cur[Ec], g_off[Ec];
__device__ int    g_tok[2 * Tc];
__device__ int    g_blk_e[MAXBLK], g_blk_m[MAXBLK], g_nblk;

// ================= low-level helpers ========================================
__device__ __forceinline__ uint32_t smem_u32(const void* p) {
    uint32_t a;
    asm("{ .reg .u64 t; cvta.to.shared.u64 t, %1; cvt.u32.u64 %0, t; }"
        : "=r"(a) : "l"(p));
    return a;
}
#define SWZ(o) ((o) ^ (((o) >> 3) & 0x70))
#define CP16(dst, src, sz) \
    asm volatile("cp.async.cg.shared.global [%0], [%1], 16, %2;" \
                 :: "r"(dst), "l"(src), "r"(sz) : "memory")
#define CP_COMMIT() asm volatile("cp.async.commit_group;" ::: "memory")

__device__ __forceinline__ void ldsm4(uint32_t* r, uint32_t addr) {
    asm volatile("ldmatrix.sync.aligned.m8n8.x4.shared.b16 {%0,%1,%2,%3}, [%4];"
                 : "=r"(r[0]), "=r"(r[1]), "=r"(r[2]), "=r"(r[3]) : "r"(addr));
}
__device__ __forceinline__ void ldsm4t(uint32_t* r, uint32_t addr) {
    asm volatile("ldmatrix.sync.aligned.m8n8.x4.trans.shared.b16 {%0,%1,%2,%3}, [%4];"
                 : "=r"(r[0]), "=r"(r[1]), "=r"(r[2]), "=r"(r[3]) : "r"(addr));
}
__device__ __forceinline__ void mma_f16(float* d, const uint32_t* a,
                                        uint32_t b0, uint32_t b1) {
    asm volatile(
        "mma.sync.aligned.m16n8k16.row.col.f32.f16.f16.f32 "
        "{%0,%1,%2,%3}, {%4,%5,%6,%7}, {%8,%9}, {%0,%1,%2,%3};"
        : "+f"(d[0]), "+f"(d[1]), "+f"(d[2]), "+f"(d[3])
        : "r"(a[0]), "r"(a[1]), "r"(a[2]), "r"(a[3]), "r"(b0), "r"(b1));
}
__device__ __forceinline__ uint32_t pack2h(float x0, float x1) {
    __half2 h = __floats2half2_rn(x0, x1);
    return *(uint32_t*)&h;
}

// ================= pipelined fp16 tensor GEMM (3-stage, 2 CTAs/SM) ==========
// A: [*,K] K-major fp16.  B: [N,K] K-major fp16.  128x128 tile, K-chunk 64.
// Stage = 32KB (A 16KB + B 16KB), 3 stages.
// EPI: 1 fp32+bias+C(resid); 2 gelu(+bias)->fp16 grouped;
//      3 gate-weighted atomicAdd into fp32 out; 4 fp16 plain
// AMODE: 0 direct; 1 grouped + gather rows via g_tok>>1; 2 grouped rows off+m
#define TG_STG 32768u
#define TG_OB  16384u
#define TG_SMEM (3 * 32768 + 1024)
template <int EPI, int AMODE>
__global__ void __launch_bounds__(256, 2) tgemm(
    int K,
    const half_t* __restrict__ A, int lda,
    const half_t* __restrict__ B, int ldb,
    float* __restrict__ C, half_t* __restrict__ C16, int ldc,
    const float* __restrict__ bias, long wstride, long bstride)
{
    extern __shared__ char dsm[];
    __shared__ int stok_s[128];
    uint32_t sbb = smem_u32(dsm);
    uint32_t tb = (sbb + 1023) & ~1023u;
    int tid = threadIdx.x, wid = tid >> 5, lid = tid & 31;

    int cnt = 0, off = 0, m0, n0;
    if (AMODE != 0) {
        int by = blockIdx.y;
        if (by >= g_nblk) return;
        int e = g_blk_e[by];
        cnt = g_cnt[e]; off = g_off[e];
        m0 = g_blk_m[by] * 128;
        B += (long)e * wstride;
        bias += (long)e * bstride;
    } else {
        m0 = blockIdx.y * 128;
    }
    n0 = blockIdx.x * 128;

    if (AMODE == 1 && tid < 128) {
        int i = m0 + tid;
        stok_s[tid] = (i < cnt) ? (g_tok[off + i] >> 1) : -1;
    }
    if (AMODE == 2 && tid < 128) {
        int i = m0 + tid;
        stok_s[tid] = (i < cnt) ? g_tok[off + i] : -1;
    }
    if (AMODE != 0) __syncthreads();

    // stage loader: 128 rows x 64 fp16 (128B rows, SW128) for A and B
    auto load_stage = [&](int c, int st) {
        uint32_t base = tb + (uint32_t)st * TG_STG;
        int k0 = c << 6;
#pragma unroll
        for (int i = 0; i < 4; i++) {
            int idx = tid + (i << 8);
            int row = idx >> 3, c16 = idx & 7;
            uint32_t d = SWZ((uint32_t)(row * 128 + c16 * 16));
            long so; uint32_t sz = 16;
            if (AMODE == 0) so = (long)(m0 + row) * lda + k0 + c16 * 8;
            else if (AMODE == 1) {
                int tk = stok_s[row];
                if (tk < 0) { sz = 0; tk = 0; }
                so = (long)tk * lda + k0 + c16 * 8;
            } else {
                if (stok_s[row] < 0) { sz = 0; so = 0; }
                else so = (long)(off + m0 + row) * lda + k0 + c16 * 8;
            }
            CP16(base + d, A + so, sz);
        }
#pragma unroll
        for (int i = 0; i < 4; i++) {
            int idx = tid + (i << 8);
            int row = idx >> 3, c16 = idx & 7;
            uint32_t d = SWZ((uint32_t)(row * 128 + c16 * 16));
            long so = (long)(n0 + row) * ldb + k0 + c16 * 8;
            CP16(base + TG_OB + d, B + so, 16);
        }
        CP_COMMIT();
    };

    int wm = (wid >> 2) * 64, wn = (wid & 3) * 32;
    int a_row = wm + (lid & 15), a_cb = (lid >> 4) << 4;
    int b_row = wn + ((lid >> 4) << 3) + (lid & 7), b_cb = ((lid >> 3) & 1) << 4;
    float acc[4][4][4] = {};

    int nch = K >> 6;
    load_stage(0, 0);
    if (nch > 1) load_stage(1, 1);
    int st = 0;
    for (int c = 0; c < nch; c++) {
        if (c + 2 < nch) {
            load_stage(c + 2, (st + 2) % 3);
            asm volatile("cp.async.wait_group 2;" ::: "memory");
        } else if (c + 1 < nch) {
            asm volatile("cp.async.wait_group 1;" ::: "memory");
        } else {
            asm volatile("cp.async.wait_group 0;" ::: "memory");
        }
        __syncthreads();
        uint32_t base = tb + (uint32_t)st * TG_STG;
#pragma unroll
        for (int ks = 0; ks < 4; ks++) {
            int kb = ks * 32;
            uint32_t bF[2][4];
#pragma unroll
            for (int g = 0; g < 2; g++) {
                uint32_t o = SWZ((uint32_t)((b_row + g * 16) * 128 + kb + b_cb));
                ldsm4(bF[g], base + TG_OB + o);
            }
#pragma unroll
            for (int mt = 0; mt < 4; mt++) {
                uint32_t aF[4];
                uint32_t o = SWZ((uint32_t)((a_row + mt * 16) * 128 + kb + a_cb));
                ldsm4(aF, base + o);
#pragma unroll
                for (int nt = 0; nt < 4; nt++) {
                    int g = nt >> 1, pr = (nt & 1) * 2;
                    mma_f16(acc[mt][nt], aF, bF[g][pr], bF[g][pr + 1]);
                }
            }
        }
        __syncthreads();
        st = (st + 1) % 3;
    }

    // ---- register epilogue ----
    int lr = lid >> 2, lc = (lid & 3) * 2;
#pragma unroll
    for (int mt = 0; mt < 4; mt++) {
#pragma unroll
        for (int half = 0; half < 2; half++) {
            int lrow = wm + mt * 16 + lr + half * 8;
            int grow = m0 + lrow;
#pragma unroll
            for (int nt = 0; nt < 4; nt++) {
                float v0 = acc[mt][nt][half * 2 + 0];
                float v1 = acc[mt][nt][half * 2 + 1];
                int gc = n0 + wn + nt * 8 + lc;
                if (EPI == 1) {
                    long idx = (long)grow * ldc + gc;
                    float2 old = *(const float2*)&C[idx];
                    *(float2*)&C[idx] = make_float2(v0 + bias[gc] + old.x,
                                                    v1 + bias[gc + 1] + old.y);
                } else if (EPI == 2) {
                    if (stok_s[lrow] >= 0) {
                        float t0 = v0 + bias[gc], t1 = v1 + bias[gc + 1];
                        float o0 = 0.5f * t0 * (1.f + erff(t0 * 0.70710678118654752f));
                        float o1 = 0.5f * t1 * (1.f + erff(t1 * 0.70710678118654752f));
                        long idx = (long)(off + grow) * ldc + gc;
                        *(uint32_t*)&C16[idx] = pack2h(o0, o1);
                    }
                } else if (EPI == 3) {
                    int ent = stok_s[lrow];
                    if (ent >= 0) {
                        float w = g_gate[ent];
                        long idx = (long)(ent >> 1) * ldc + gc;
                        atomicAdd(&C[idx],     w * (v0 + bias[gc]));
                        atomicAdd(&C[idx + 1], w * (v1 + bias[gc + 1]));
                    }
                } else {  // EPI == 4
                    long idx = (long)grow * ldc + gc;
                    *(uint32_t*)&C16[idx] = pack2h(v0, v1);
                }
            }
        }
    }
}

// ================= fused flash attention (fp16) =============================
#define FL_Q   0
#define FL_KST 16384
#define FL_VST 49152
#define FL_SMEM 81920
__global__ void __launch_bounds__(256, 1) flash_k(
    const half_t* __restrict__ QKV, half_t* __restrict__ O)
{
    extern __shared__ char dsm[];
    uint32_t sb = smem_u32(dsm);
    int tid = threadIdx.x, wid = tid >> 5, lid = tid & 31;
    int bh = blockIdx.y, b = bh >> 3, h = bh & 7;
    int q0 = blockIdx.x * 128;

    long qbase = (long)b * Sc * QKVN + (long)q0 * QKVN + h * HEADc;
    long kb0   = (long)b * Sc * QKVN + 512 + h * HEADc;
    long vb0   = (long)b * Sc * QKVN + 1024 + h * HEADc;
    long obase = (long)b * Sc * Dc + (long)q0 * Dc + h * HEADc;

    auto load_q = [&]() {
#pragma unroll
        for (int i = 0; i < 4; i++) {
            int idx = tid + (i << 8);
            int row = idx >> 3, c16 = idx & 7;
            uint32_t d = SWZ((uint32_t)(row * 128 + c16 * 16));
            CP16(sb + FL_Q + d, QKV + qbase + (long)row * QKVN + c16 * 8, 16);
        }
    };
    auto load_kv = [&](int c, int st) {
        uint32_t kstg = sb + FL_KST + (uint32_t)st * 16384;
        uint32_t vstg = sb + FL_VST + (uint32_t)st * 16384;
#pragma unroll
        for (int i = 0; i < 4; i++) {
            int idx = tid + (i << 8);
            int row = idx >> 3, c16 = idx & 7;
            uint32_t d = SWZ((uint32_t)(row * 128 + c16 * 16));
            CP16(kstg + d, QKV + kb0 + (long)(c * 128 + row) * QKVN + c16 * 8, 16);
        }
#pragma unroll
        for (int i = 0; i < 4; i++) {
            int idx = tid + (i << 8);
            int row = idx >> 3, c16 = idx & 7;
            uint32_t d = SWZ((uint32_t)(row * 128 + c16 * 16));
            CP16(vstg + d, QKV + vb0 + (long)(c * 128 + row) * QKVN + c16 * 8, 16);
        }
        CP_COMMIT();
    };

    load_q(); load_kv(0, 0);
    load_kv(1, 1);

    int wm = wid * 16;
    int lr = lid >> 2, lc = (lid & 3) * 2;
    int a_row = wm + (lid & 15), a_cb = (lid >> 4) << 4;
    int b_row8 = ((lid >> 4) << 3) + (lid & 7);
    int b_cb = ((lid >> 3) & 1) << 4;
    int v_soff = (lid & 7) + (((lid >> 3) & 1) << 3);
    int v_doff = ((lid >> 4) & 1) << 3;

    uint32_t qF[4][4];
    float m0r = -1e30f, m1r = -1e30f, l0r = 0.f, l1r = 0.f;
    float acc_o[8][4] = {};

    for (int c = 0; c < 8; c++) {
        if (c < 7) asm volatile("cp.async.wait_group 1;" ::: "memory");
        else       asm volatile("cp.async.wait_group 0;" ::: "memory");
        __syncthreads();

        if (c == 0) {
#pragma unroll
            for (int ks = 0; ks < 4; ks++) {
                uint32_t o = SWZ((uint32_t)(a_row * 128 + ks * 32 + a_cb));
                ldsm4(qF[ks], sb + FL_Q + o);
            }
        }
        uint32_t kstg = sb + FL_KST + (uint32_t)(c & 1) * 16384;
        uint32_t vstg = sb + FL_VST + (uint32_t)(c & 1) * 16384;

        float s_acc[16][4] = {};
#pragma unroll
        for (int ks = 0; ks < 4; ks++) {
            int kb = ks * 32;
            uint32_t kF[8][4];
#pragma unroll
            for (int g = 0; g < 8; g++) {
                uint32_t o = SWZ((uint32_t)((g * 16 + b_row8) * 128 + kb + b_cb));
                ldsm4(kF[g], kstg + o);
            }
#pragma unroll
            for (int nt = 0; nt < 16; nt++) {
                int g = nt >> 1, pr = (nt & 1) * 2;
                mma_f16(s_acc[nt], qF[ks], kF[g][pr], kF[g][pr + 1]);
            }
        }

        float t0 = -1e30f, t1 = -1e30f;
#pragma unroll
        for (int nt = 0; nt < 16; nt++) {
#pragma unroll
            for (int j = 0; j < 4; j++) s_acc[nt][j] *= 0.125f;
            t0 = fmaxf(t0, fmaxf(s_acc[nt][0], s_acc[nt][1]));
            t1 = fmaxf(t1, fmaxf(s_acc[nt][2], s_acc[nt][3]));
        }
#pragma unroll
        for (int o = 1; o <= 2; o <<= 1) {
            t0 = fmaxf(t0, __shfl_xor_sync(0xffffffffu, t0, o));
            t1 = fmaxf(t1, __shfl_xor_sync(0xffffffffu, t1, o));
        }
        float mn0 = fmaxf(m0r, t0), mn1 = fmaxf(m1r, t1);
        float cor0 = expf(m0r - mn0), cor1 = expf(m1r - mn1);
        float rs0 = 0.f, rs1 = 0.f;
#pragma unroll
        for (int nt = 0; nt < 16; nt++) {
            s_acc[nt][0] = expf(s_acc[nt][0] - mn0);
            s_acc[nt][1] = expf(s_acc[nt][1] - mn0);
            s_acc[nt][2] = expf(s_acc[nt][2] - mn1);
            s_acc[nt][3] = expf(s_acc[nt][3] - mn1);
            rs0 += s_acc[nt][0] + s_acc[nt][1];
            rs1 += s_acc[nt][2] + s_acc[nt][3];
        }
#pragma unroll
        for (int o = 1; o <= 2; o <<= 1) {
            rs0 += __shfl_xor_sync(0xffffffffu, rs0, o);
            rs1 += __shfl_xor_sync(0xffffffffu, rs1, o);
        }
        l0r = l0r * cor0 + rs0; l1r = l1r * cor1 + rs1;
        m0r = mn0; m1r = mn1;
#pragma unroll
        for (int nt = 0; nt < 8; nt++) {
            acc_o[nt][0] *= cor0; acc_o[nt][1] *= cor0;
            acc_o[nt][2] *= cor1; acc_o[nt][3] *= cor1;
        }

#pragma unroll
        for (int kt = 0; kt < 8; kt++) {
            uint32_t aP[4];
            aP[0] = pack2h(s_acc[2 * kt][0],     s_acc[2 * kt][1]);
            aP[1] = pack2h(s_acc[2 * kt][2],     s_acc[2 * kt][3]);
            aP[2] = pack2h(s_acc[2 * kt + 1][0], s_acc[2 * kt + 1][1]);
            aP[3] = pack2h(s_acc[2 * kt + 1][2], s_acc[2 * kt + 1][3]);
            uint32_t vF[4][4];
#pragma unroll
            for (int g = 0; g < 4; g++) {
                uint32_t o = SWZ((uint32_t)((kt * 16 + v_soff) * 128 +
                                            (g * 16 + v_doff) * 2));
                ldsm4t(vF[g], vstg + o);
            }
#pragma unroll
            for (int nt = 0; nt < 8; nt++) {
                int g = nt >> 1, pr = (nt & 1) * 2;
                mma_f16(acc_o[nt], aP, vF[g][pr], vF[g][pr + 1]);
            }
        }
        __syncthreads();
        if (c + 2 < 8) load_kv(c + 2, c & 1);
    }

    float inv0 = 1.f / l0r, inv1 = 1.f / l1r;
    long r0g = obase + (long)(wm + lr) * Dc;
    long r1g = obase + (long)(wm + lr + 8) * Dc;
#pragma unroll
    for (int nt = 0; nt < 8; nt++) {
        int gc = nt * 8 + lc;
        *(uint32_t*)&O[r0g + gc] = pack2h(acc_o[nt][0] * inv0, acc_o[nt][1] * inv0);
        *(uint32_t*)&O[r1g + gc] = pack2h(acc_o[nt][2] * inv1, acc_o[nt][3] * inv1);
    }
}

// ================= transpose + fp16 convert ================================
__global__ void tconv(const float* __restrict__ in, half_t* __restrict__ o16,
                      int R, int Ccol, long sin, long sout)
{
    __shared__ float t[32][33];
    long ib = (long)blockIdx.z * sin, ob = (long)blockIdx.z * sout;
    int c0 = blockIdx.x * 32, r0 = blockIdx.y * 32;
    int tx = threadIdx.x, ty = threadIdx.y;
#pragma unroll
    for (int j = 0; j < 4; j++)
        t[ty + j * 8][tx] = in[ib + (long)(r0 + ty + j * 8) * Ccol + c0 + tx];
    __syncthreads();
#pragma unroll
    for (int j = 0; j < 4; j++) {
        float v = t[tx][ty + j * 8];
        o16[ob + (long)(c0 + ty + j * 8) * R + r0 + tx] = __float2half_rn(v);
    }
}

// ================= elementwise kernels ======================================
__global__ void copy_k(const float* __restrict__ a, float* __restrict__ o) {
    long i = (long)blockIdx.x * 256 + threadIdx.x;
    o[i] = a[i];
}

// isLn2: also zero g_cnt and store fp32 h (for gate); LN1 stores fp16 only
__global__ void ln_k(const float* __restrict__ x, const float* __restrict__ w,
                     const float* __restrict__ b, float* __restrict__ out,
                     half_t* __restrict__ o16, int isLn2) {
    int row = blockIdx.x;
    int tid = threadIdx.x;
    if (isLn2 && row == 0 && tid < Ec) g_cnt[tid] = 0;
    const float* xr = x + (long)row * Dc;
    float4 v = *(const float4*)&xr[tid * 4];
    float s = v.x + v.y + v.z + v.w;
    float s2 = v.x * v.x + v.y * v.y + v.z * v.z + v.w * v.w;
    __shared__ float sh[4], sh2[4];
#pragma unroll
    for (int o = 16; o > 0; o >>= 1) {
        s  += __shfl_xor_sync(0xffffffffu, s, o);
        s2 += __shfl_xor_sync(0xffffffffu, s2, o);
    }
    if ((tid & 31) == 0) { sh[tid >> 5] = s; sh2[tid >> 5] = s2; }
    __syncthreads();
    float a = 0.f, a2 = 0.f;
#pragma unroll
    for (int i = 0; i < 4; i++) { a += sh[i]; a2 += sh2[i]; }
    float mu  = a * (1.f / Dc);
    float var = a2 * (1.f / Dc) - mu * mu;
    float inv = rsqrtf(var + 1e-6f);
    int d = tid * 4;
    const float4 wv = *(const float4*)&w[d];
    const float4 bv = *(const float4*)&b[d];
    float y0 = (v.x - mu) * inv * wv.x + bv.x;
    float y1 = (v.y - mu) * inv * wv.y + bv.y;
    float y2 = (v.z - mu) * inv * wv.z + bv.z;
    float y3 = (v.w - mu) * inv * wv.w + bv.w;
    long idx = (long)row * Dc + d;
    if (isLn2) *(float4*)&out[idx] = make_float4(y0, y1, y2, y3);
    *(uint32_t*)&o16[idx] = pack2h(y0, y1);
    *(uint32_t*)&o16[idx + 2] = pack2h(y2, y3);
}

__global__ void gate_k(const float* __restrict__ h, const float* __restrict__ gw) {
    int t = blockIdx.x * 4 + (threadIdx.x >> 5);
    int lid = threadIdx.x & 31;
    const float* hr = h + (long)t * Dc;
    float acc[Ec] = {};
    for (int d = lid; d < Dc; d += 32) {
        float hv = hr[d];
#pragma unroll
        for (int e = 0; e < Ec; e++) acc[e] += hv * gw[d * Ec + e];
    }
#pragma unroll
    for (int e = 0; e < Ec; e++)
#pragma unroll
        for (int o = 16; o > 0; o >>= 1)
            acc[e] += __shfl_xor_sync(0xffffffffu, acc[e], o);
    if (lid == 0) {
        int i0 = 0; float v0 = acc[0];
#pragma unroll
        for (int e = 1; e < Ec; e++) if (acc[e] > v0) { v0 = acc[e]; i0 = e; }
        int i1 = -1; float v1 = -3.4e38f;
#pragma unroll
        for (int e = 0; e < Ec; e++) if (e != i0 && acc[e] > v1) { v1 = acc[e]; i1 = e; }
        float g1 = 1.f / (1.f + expf(v0 - v1));
        g_topi[t * 2] = i0; g_topi[t * 2 + 1] = i1;
        g_gate[t * 2] = 1.f - g1; g_gate[t * 2 + 1] = g1;
        atomicAdd(&g_cnt[i0], 1);
        atomicAdd(&g_cnt[i1], 1);
    }
}

// offsets + block table
__global__ void offsets_k() {
    if (threadIdx.x == 0) {
        int o = 0, nb = 0;
        for (int e = 0; e < Ec; e++) {
            g_off[e] = o; g_cur[e] = o;
            int c = g_cnt[e];
            int nbe = (c + 127) >> 7;
            for (int j = 0; j < nbe; j++) { g_blk_e[nb] = e; g_blk_m[nb] = j; nb++; }
            o += c;
        }
        g_nblk = nb;
    }
}

__global__ void scatter_k() {
    int i = blockIdx.x * 256 + threadIdx.x;
    if (i >= 2 * Tc) return;
    int e = g_topi[i];
    int pos = atomicAdd(&g_cur[e], 1);
    g_tok[pos] = i;
}

// ================= host =====================================================
extern "C" void kernel_launch(void* const* d_in, const int* in_sizes, int n_in,
                              void* d_out, int out_size)
{
    const float* x      = (const float*)d_in[0];
    const float* ln1_w  = (const float*)d_in[1];
    const float* ln1_b  = (const float*)d_in[2];
    const float* wq     = (const float*)d_in[3];
    const float* wk     = (const float*)d_in[4];
    const float* wv     = (const float*)d_in[5];
    const float* wo     = (const float*)d_in[6];
    const float* bo     = (const float*)d_in[7];
    const float* ln2_w  = (const float*)d_in[8];
    const float* ln2_b  = (const float*)d_in[9];
    const float* gate_w = (const float*)d_in[10];
    const float* w1     = (const float*)d_in[11];
    const float* b1     = (const float*)d_in[12];
    const float* w2     = (const float*)d_in[13];
    const float* b2     = (const float*)d_in[14];
    float* out = (float*)d_out;

    float *ph;
    half_t *ph16, *pqkv16, *pao16, *phm16;
    half_t *wqkvt16, *wot16, *w1t16, *w2t16;
    cudaGetSymbolAddress((void**)&ph, g_h);
    cudaGetSymbolAddress((void**)&ph16, g_h16);
    cudaGetSymbolAddress((void**)&pqkv16, g_qkv16);
    cudaGetSymbolAddress((void**)&pao16, g_ao16);
    cudaGetSymbolAddress((void**)&phm16, g_hm16);
    cudaGetSymbolAddress((void**)&wqkvt16, g_wqkvt16);
    cudaGetSymbolAddress((void**)&wot16, g_wot16);
    cudaGetSymbolAddress((void**)&w1t16, g_w1t16);
    cudaGetSymbolAddress((void**)&w2t16, g_w2t16);

    cudaFuncSetAttribute(tgemm<1, 0>, cudaFuncAttributeMaxDynamicSharedMemorySize, TG_SMEM);
    cudaFuncSetAttribute(tgemm<4, 0>, cudaFuncAttributeMaxDynamicSharedMemorySize, TG_SMEM);
    cudaFuncSetAttribute(tgemm<2, 1>, cudaFuncAttributeMaxDynamicSharedMemorySize, TG_SMEM);
    cudaFuncSetAttribute(tgemm<3, 2>, cudaFuncAttributeMaxDynamicSharedMemorySize, TG_SMEM);
    cudaFuncSetAttribute(flash_k, cudaFuncAttributeMaxDynamicSharedMemorySize, FL_SMEM);

    cudaStream_t s1;
    cudaStreamCreateWithFlags(&s1, cudaStreamNonBlocking);
    cudaEvent_t eFork, eQKV[Lc], eWO[Lc], eMOE[Lc];
    cudaEventCreateWithFlags(&eFork, cudaEventDisableTiming);
    for (int l = 0; l < Lc; l++) {
        cudaEventCreateWithFlags(&eQKV[l], cudaEventDisableTiming);
        cudaEventCreateWithFlags(&eWO[l], cudaEventDisableTiming);
        cudaEventCreateWithFlags(&eMOE[l], cudaEventDisableTiming);
    }

    dim3 tcb(32, 8);
    cudaEventRecord(eFork, 0);
    cudaStreamWaitEvent(s1, eFork, 0);
    for (int l = 0; l < Lc; l++) {
        half_t* qt = wqkvt16 + (long)l * QKVN * Dc;
        tconv<<<dim3(16, 16, 1), tcb, 0, s1>>>(wq + (long)l * Dc * Dc, qt, Dc, Dc, 0, 0);
        tconv<<<dim3(16, 16, 1), tcb, 0, s1>>>(wk + (long)l * Dc * Dc, qt + 512 * Dc, Dc, Dc, 0, 0);
        tconv<<<dim3(16, 16, 1), tcb, 0, s1>>>(wv + (long)l * Dc * Dc, qt + 1024 * Dc, Dc, Dc, 0, 0);
        cudaEventRecord(eQKV[l], s1);
        tconv<<<dim3(16, 16, 1), tcb, 0, s1>>>(wo + (long)l * Dc * Dc,
            wot16 + (long)l * Dc * Dc, Dc, Dc, 0, 0);
        cudaEventRecord(eWO[l], s1);
        tconv<<<dim3(DHc / 32, Dc / 32, Ec), tcb, 0, s1>>>(
            w1 + (long)l * Ec * Dc * DHc, w1t16 + (long)l * Ec * Dc * DHc,
            Dc, DHc, (long)Dc * DHc, (long)Dc * DHc);
        tconv<<<dim3(Dc / 32, DHc / 32, Ec), tcb, 0, s1>>>(
            w2 + (long)l * Ec * DHc * Dc, w2t16 + (long)l * Ec * DHc * Dc,
            DHc, Dc, (long)DHc * Dc, (long)DHc * Dc);
        cudaEventRecord(eMOE[l], s1);
    }

    copy_k<<<Tc * Dc / 256, 256>>>(x, out);

    for (int l = 0; l < Lc; l++) {
        half_t* qt = wqkvt16 + (long)l * QKVN * Dc;

        ln_k<<<Tc, 128>>>(out, ln1_w + l * Dc, ln1_b + l * Dc, ph, ph16, 0);

        cudaStreamWaitEvent(0, eQKV[l], 0);
        tgemm<4, 0><<<dim3(QKVN / 128, 32, 1), 256, TG_SMEM>>>(
            Dc, ph16, Dc, qt, Dc,
            nullptr, pqkv16, QKVN, nullptr, 0, 0);

        flash_k<<<dim3(Sc / 128, Bc * Hc), 256, FL_SMEM>>>(pqkv16, pao16);

        cudaStreamWaitEvent(0, eWO[l], 0);
        tgemm<1, 0><<<dim3(4, 32, 1), 256, TG_SMEM>>>(
            Dc, pao16, Dc, wot16 + (long)l * Dc * Dc, Dc,
            out, nullptr, Dc, bo + l * Dc, 0, 0);

        ln_k<<<Tc, 128>>>(out, ln2_w + l * Dc, ln2_b + l * Dc, ph, ph16, 1);

        gate_k<<<Tc / 4, 128>>>(ph, gate_w + (long)l * Dc * Ec);
        offsets_k<<<1, 1>>>();
        scatter_k<<<2 * Tc / 256, 256>>>();

        cudaStreamWaitEvent(0, eMOE[l], 0);
        // MoE GEMM1: hmid = gelu(h[tok] @ W1[e] + b1[e])  (compact block table)
        tgemm<2, 1><<<dim3(16, MAXBLK, 1), 256, TG_SMEM>>>(
            Dc, ph16, Dc, w1t16 + (long)l * Ec * Dc * DHc, Dc,
            nullptr, phm16, DHc,
            b1 + (long)l * Ec * DHc, (long)Dc * DHc, DHc);
        // MoE GEMM2 + fused gate-weighted combine into out
        tgemm<3, 2><<<dim3(4, MAXBLK, 1), 256, TG_SMEM>>>(
            DHc, phm16, DHc, w2t16 + (long)l * Ec * DHc * Dc, DHc,
            out, nullptr, Dc,
            b2 + (long)l * Ec * Dc, (long)DHc * Dc, Dc);
    }
}